// round 1
// baseline (speedup 1.0000x reference)
#include <cuda_runtime.h>
#include <cuda_bf16.h>
#include <math.h>

// Problem constants
#define EMB   1024
#define HID   1024
#define SEQ   128
#define BATCH 64
#define VOCAB 10000
#define BH    (BATCH * HID)      // 65536
#define ROWS  (SEQ * BATCH)      // 8192

typedef unsigned long long ull;

// ---------------- scratch (device globals; no allocation allowed) ----------
__device__ float g_xproj0[ROWS * HID];          // x @ wx0^T + bh0 for all t
__device__ float g_h0[(SEQ + 1) * BH];          // h0 history, slot t+1 = after step t
__device__ float g_h1[(SEQ + 1) * BH];          // h1 history

// ---------------- f32x2 packed-FMA helpers (Blackwell) ---------------------
__device__ __forceinline__ ull pk2(float x, float y) {
    ull r;
    asm("mov.b64 %0, {%1, %2};" : "=l"(r) : "f"(x), "f"(y));
    return r;
}
__device__ __forceinline__ void fma2(ull& c, ull a, ull b) {
    asm("fma.rn.f32x2 %0, %1, %2, %0;" : "+l"(c) : "l"(a), "l"(b));
}
__device__ __forceinline__ float2 up2(ull v) {
    float2 r;
    asm("mov.b64 {%0, %1}, %2;" : "=f"(r.x), "=f"(r.y) : "l"(v));
    return r;
}

// ---------------- init: load initial hidden state ---------------------------
__global__ void init_kernel(const float* __restrict__ hidden) {
    int i = blockIdx.x * blockDim.x + threadIdx.x;
    if (i < BH) {
        g_h0[i] = hidden[i];          // layer 0 initial state
        g_h1[i] = hidden[BH + i];     // layer 1 initial state
    }
}

// ---------------- xproj: g_xproj0 = gather(emb, inputs) @ wx0^T + bh0 -------
// Tiles: 64(M) x 64(N), K=1024, Kt=16, 256 threads, 4x4 microtile with f32x2.
__global__ __launch_bounds__(256) void xproj_kernel(
    const int* __restrict__ inp, const float* __restrict__ emb,
    const float* __restrict__ wx0, const float* __restrict__ bh0)
{
    __shared__ int   idx_s[64];
    __shared__ float As[16][68];
    __shared__ float Bs[16][68];

    int tid   = threadIdx.x;
    int rbase = blockIdx.y * 64;
    int nbase = blockIdx.x * 64;

    if (tid < 64) idx_s[tid] = inp[rbase + tid];
    __syncthreads();

    int rl = tid >> 2;            // 0..63
    int kq = (tid & 3) * 4;       // 0,4,8,12
    const float* arow = emb + (size_t)idx_s[rl] * EMB + kq;
    const float* brow = wx0 + (size_t)(nbase + rl) * EMB + kq;

    int ty = tid >> 4, tx = tid & 15;
    ull acc[4][2] = {};

    for (int kt = 0; kt < EMB; kt += 16) {
        float4 av = *(const float4*)(arow + kt);
        float4 bv = *(const float4*)(brow + kt);
        As[kq + 0][rl] = av.x; As[kq + 1][rl] = av.y;
        As[kq + 2][rl] = av.z; As[kq + 3][rl] = av.w;
        Bs[kq + 0][rl] = bv.x; Bs[kq + 1][rl] = bv.y;
        Bs[kq + 2][rl] = bv.z; Bs[kq + 3][rl] = bv.w;
        __syncthreads();

        #pragma unroll
        for (int kk = 0; kk < 16; kk++) {
            float4 a4 = *(const float4*)&As[kk][ty * 4];
            float4 b4 = *(const float4*)&Bs[kk][tx * 4];
            ull b01 = pk2(b4.x, b4.y), b23 = pk2(b4.z, b4.w);
            ull a;
            a = pk2(a4.x, a4.x); fma2(acc[0][0], a, b01); fma2(acc[0][1], a, b23);
            a = pk2(a4.y, a4.y); fma2(acc[1][0], a, b01); fma2(acc[1][1], a, b23);
            a = pk2(a4.z, a4.z); fma2(acc[2][0], a, b01); fma2(acc[2][1], a, b23);
            a = pk2(a4.w, a4.w); fma2(acc[3][0], a, b01); fma2(acc[3][1], a, b23);
        }
        __syncthreads();
    }

    int n0 = nbase + tx * 4;
    float4 bb = *(const float4*)(bh0 + n0);
    #pragma unroll
    for (int i = 0; i < 4; i++) {
        int r = rbase + ty * 4 + i;
        float2 p0 = up2(acc[i][0]), p1 = up2(acc[i][1]);
        float4 o = make_float4(p0.x + bb.x, p0.y + bb.y, p1.x + bb.z, p1.y + bb.w);
        *(float4*)&g_xproj0[(size_t)r * HID + n0] = o;
    }
}

// ---------------- step: one pipelined recurrence launch ---------------------
// blocks 0..63  : layer0, step t=k     : h0[k+1] = tanh(xproj0[k] + h0[k] @ wh0^T)
// blocks 64..127: layer1, step t=k-1   : h1[k]   = tanh(h0[k] @ wx1^T + h1[k-1] @ wh1^T + bh1)
// Each block: M=64, Ntile=16, Kt=32; thread -> (m = tid&63, 4 consecutive n).
__global__ __launch_bounds__(256) void step_kernel(
    int k, const float* __restrict__ wh0, const float* __restrict__ wx1,
    const float* __restrict__ wh1, const float* __restrict__ bh1)
{
    int layer = blockIdx.x >> 6;
    if (layer == 0 && k >= SEQ) return;
    if (layer == 1 && k == 0)   return;

    __shared__ float As[32][68];
    __shared__ float Bs[32][20];

    int tid = threadIdx.x;
    int nbase = (blockIdx.x & 63) * 16;
    int m  = tid & 63;
    int nq = tid >> 6;            // 0..3
    ull acc0 = 0, acc1 = 0;

    const float* Aptrs[2];
    const float* Bptrs[2];
    int nphase;
    if (layer == 0) {
        Aptrs[0] = g_h0 + (size_t)k * BH;       Bptrs[0] = wh0;  nphase = 1;
    } else {
        Aptrs[0] = g_h0 + (size_t)k * BH;       Bptrs[0] = wx1;
        Aptrs[1] = g_h1 + (size_t)(k - 1) * BH; Bptrs[1] = wh1;  nphase = 2;
    }

    int rl  = tid >> 2;           // 0..63 (A loader row)
    int kq4 = (tid & 3) * 4;      // 0,4,8,12

    for (int ph = 0; ph < nphase; ph++) {
        const float* A  = Aptrs[ph];
        const float* Bp = Bptrs[ph];
        for (int kt = 0; kt < HID; kt += 32) {
            #pragma unroll
            for (int p = 0; p < 2; p++) {
                float4 v = *(const float4*)(A + (size_t)rl * HID + kt + kq4 + p * 16);
                As[kq4 + p * 16 + 0][rl] = v.x;
                As[kq4 + p * 16 + 1][rl] = v.y;
                As[kq4 + p * 16 + 2][rl] = v.z;
                As[kq4 + p * 16 + 3][rl] = v.w;
            }
            if (tid < 128) {
                int nl = tid >> 3;            // 0..15
                int kq = (tid & 7) * 4;       // 0..28
                float4 v = *(const float4*)(Bp + (size_t)(nbase + nl) * HID + kt + kq);
                Bs[kq + 0][nl] = v.x; Bs[kq + 1][nl] = v.y;
                Bs[kq + 2][nl] = v.z; Bs[kq + 3][nl] = v.w;
            }
            __syncthreads();

            #pragma unroll
            for (int kk = 0; kk < 32; kk++) {
                float  a  = As[kk][m];
                float4 b4 = *(const float4*)&Bs[kk][nq * 4];
                ull a2 = pk2(a, a);
                fma2(acc0, a2, pk2(b4.x, b4.y));
                fma2(acc1, a2, pk2(b4.z, b4.w));
            }
            __syncthreads();
        }
    }

    int n = nbase + nq * 4;
    float2 p0 = up2(acc0), p1 = up2(acc1);
    if (layer == 0) {
        float4 x4 = *(const float4*)(g_xproj0 + ((size_t)k * BATCH + m) * HID + n);
        float4 r = make_float4(tanhf(p0.x + x4.x), tanhf(p0.y + x4.y),
                               tanhf(p1.x + x4.z), tanhf(p1.y + x4.w));
        *(float4*)&g_h0[(size_t)(k + 1) * BH + (size_t)m * HID + n] = r;
    } else {
        float4 bb = *(const float4*)(bh1 + n);
        float4 r = make_float4(tanhf(p0.x + bb.x), tanhf(p0.y + bb.y),
                               tanhf(p1.x + bb.z), tanhf(p1.y + bb.w));
        *(float4*)&g_h1[(size_t)k * BH + (size_t)m * HID + n] = r;  // slot t+1 = k
    }
}

// ---------------- logits: out = top(8192x1024) @ v_w^T + v_b ----------------
// 128x128 tile, 256 threads, 8x8 microtile with f32x2, Kt=16.
__global__ __launch_bounds__(256, 2) void logits_kernel(
    const float* __restrict__ vw, const float* __restrict__ vb,
    float* __restrict__ out)
{
    __shared__ float As[16][132];
    __shared__ float Bs[16][132];

    int tid = threadIdx.x;
    int mbase = blockIdx.y * 128;
    int nbase = blockIdx.x * 128;
    int tx = tid & 15, ty = tid >> 4;

    const float* Ag = g_h1 + BH;  // top output rows: slot t+1, row r = t*B+b

    int rl  = tid >> 1;           // 0..127
    int kq8 = (tid & 1) * 8;      // 0 or 8
    int arow = mbase + rl;
    int brow = nbase + rl;
    if (brow >= VOCAB) brow = VOCAB - 1;

    const float* aro = Ag + (size_t)arow * HID + kq8;
    const float* bro = vw + (size_t)brow * HID + kq8;

    ull acc[8][4] = {};

    for (int kt = 0; kt < HID; kt += 16) {
        float4 a0 = *(const float4*)(aro + kt);
        float4 a1 = *(const float4*)(aro + kt + 4);
        float4 b0 = *(const float4*)(bro + kt);
        float4 b1 = *(const float4*)(bro + kt + 4);
        As[kq8 + 0][rl] = a0.x; As[kq8 + 1][rl] = a0.y;
        As[kq8 + 2][rl] = a0.z; As[kq8 + 3][rl] = a0.w;
        As[kq8 + 4][rl] = a1.x; As[kq8 + 5][rl] = a1.y;
        As[kq8 + 6][rl] = a1.z; As[kq8 + 7][rl] = a1.w;
        Bs[kq8 + 0][rl] = b0.x; Bs[kq8 + 1][rl] = b0.y;
        Bs[kq8 + 2][rl] = b0.z; Bs[kq8 + 3][rl] = b0.w;
        Bs[kq8 + 4][rl] = b1.x; Bs[kq8 + 5][rl] = b1.y;
        Bs[kq8 + 6][rl] = b1.z; Bs[kq8 + 7][rl] = b1.w;
        __syncthreads();

        #pragma unroll
        for (int kk = 0; kk < 16; kk++) {
            float4 aA = *(const float4*)&As[kk][ty * 8];
            float4 aB = *(const float4*)&As[kk][ty * 8 + 4];
            float4 bA = *(const float4*)&Bs[kk][tx * 8];
            float4 bB = *(const float4*)&Bs[kk][tx * 8 + 4];
            ull bp0 = pk2(bA.x, bA.y), bp1 = pk2(bA.z, bA.w);
            ull bp2 = pk2(bB.x, bB.y), bp3 = pk2(bB.z, bB.w);
            float am[8] = {aA.x, aA.y, aA.z, aA.w, aB.x, aB.y, aB.z, aB.w};
            #pragma unroll
            for (int i = 0; i < 8; i++) {
                ull a2 = pk2(am[i], am[i]);
                fma2(acc[i][0], a2, bp0);
                fma2(acc[i][1], a2, bp1);
                fma2(acc[i][2], a2, bp2);
                fma2(acc[i][3], a2, bp3);
            }
        }
        __syncthreads();
    }

    #pragma unroll
    for (int i = 0; i < 8; i++) {
        int r = mbase + ty * 8 + i;
        float* orow = out + (size_t)r * VOCAB;
        #pragma unroll
        for (int j = 0; j < 4; j++) {
            int n0 = nbase + tx * 8 + 2 * j;
            float2 p = up2(acc[i][j]);
            if (n0 < VOCAB)     orow[n0]     = p.x + vb[n0];
            if (n0 + 1 < VOCAB) orow[n0 + 1] = p.y + vb[n0 + 1];
        }
    }
}

// ---------------- finalize: hidden_final appended after logits --------------
__global__ void finalize_kernel(float* __restrict__ out) {
    int i = blockIdx.x * blockDim.x + threadIdx.x;
    if (i < BH) {
        size_t base = (size_t)ROWS * VOCAB;
        out[base + i]      = g_h0[(size_t)SEQ * BH + i];
        out[base + BH + i] = g_h1[(size_t)SEQ * BH + i];
    }
}

// ---------------- launcher ---------------------------------------------------
extern "C" void kernel_launch(void* const* d_in, const int* in_sizes, int n_in,
                              void* d_out, int out_size)
{
    const int*   inputs    = (const int*)  d_in[0];
    const float* hidden    = (const float*)d_in[1];
    const float* embedding = (const float*)d_in[2];
    const float* wx0       = (const float*)d_in[3];
    const float* wh0       = (const float*)d_in[4];
    const float* bh0       = (const float*)d_in[5];
    const float* wx1       = (const float*)d_in[6];
    const float* wh1       = (const float*)d_in[7];
    const float* bh1       = (const float*)d_in[8];
    const float* v_w       = (const float*)d_in[9];
    const float* v_b       = (const float*)d_in[10];
    float* out = (float*)d_out;

    init_kernel<<<(BH + 255) / 256, 256>>>(hidden);
    xproj_kernel<<<dim3(HID / 64, ROWS / 64), 256>>>(inputs, embedding, wx0, bh0);

    // Pipelined recurrence: launch k does layer0@t=k and layer1@t=k-1.
    for (int k = 0; k <= SEQ; k++) {
        step_kernel<<<128, 256>>>(k, wh0, wx1, wh1, bh1);
    }

    logits_kernel<<<dim3((VOCAB + 127) / 128, ROWS / 128), 256>>>(v_w, v_b, out);

    long long need = (long long)ROWS * VOCAB + 2LL * BH;
    if ((long long)out_size >= need) {
        finalize_kernel<<<(BH + 255) / 256, 256>>>(out);
    }
}

// round 2
// speedup vs baseline: 1.0977x; 1.0977x over previous
#include <cuda_runtime.h>
#include <math.h>

// Problem constants
#define EMB   1024
#define HID   1024
#define SEQ   128
#define BATCH 64
#define VOCAB 10000
#define BH    (BATCH * HID)      // 65536
#define ROWS  (SEQ * BATCH)      // 8192

// Persistent recurrence config
#define NB_L0 32                 // layer-0 blocks, 32 cols each
#define NB_L1 64                 // layer-1 blocks, 16 cols each (x2 matrices)
#define NBLK  (NB_L0 + NB_L1)    // 96 blocks, 1 per SM (smem-bound)
#define KC    32                 // K-chunk
#define W0_STRIDE 36             // padded row stride (16B-aligned quads)
#define W1_STRIDE 20
#define RECUR_SMEM 196608        // max(1024*36, 2048*20)*4 + 2*32*64*8

typedef unsigned long long ull;

// ---------------- scratch (device globals; no allocation allowed) ----------
__device__ float g_xproj0[ROWS * HID];          // x @ wx0^T + bh0 for all t
__device__ float g_h0[(SEQ + 1) * BH];          // h0 history, slot s = after step s-1
__device__ float g_h1[(SEQ + 1) * BH];          // h1 history
__device__ unsigned g_bar;                      // grid barrier counter

// ---------------- f32x2 packed-FMA helpers (Blackwell) ---------------------
__device__ __forceinline__ ull pk2(float x, float y) {
    ull r;
    asm("mov.b64 %0, {%1, %2};" : "=l"(r) : "f"(x), "f"(y));
    return r;
}
__device__ __forceinline__ void fma2(ull& c, ull a, ull b) {
    asm("fma.rn.f32x2 %0, %1, %2, %0;" : "+l"(c) : "l"(a), "l"(b));
}
__device__ __forceinline__ float2 up2(ull v) {
    float2 r;
    asm("mov.b64 {%0, %1}, %2;" : "=f"(r.x), "=f"(r.y) : "l"(v));
    return r;
}

// ---------------- init: load initial hidden state + reset barrier ----------
__global__ void init_kernel(const float* __restrict__ hidden) {
    int i = blockIdx.x * blockDim.x + threadIdx.x;
    if (i == 0) g_bar = 0;
    if (i < BH) {
        g_h0[i] = hidden[i];
        g_h1[i] = hidden[BH + i];
    }
}

// ---------------- xproj: g_xproj0 = gather(emb, inputs) @ wx0^T + bh0 -------
__global__ __launch_bounds__(256) void xproj_kernel(
    const int* __restrict__ inp, const float* __restrict__ emb,
    const float* __restrict__ wx0, const float* __restrict__ bh0)
{
    __shared__ int   idx_s[64];
    __shared__ float As[16][68];
    __shared__ float Bs[16][68];

    int tid   = threadIdx.x;
    int rbase = blockIdx.y * 64;
    int nbase = blockIdx.x * 64;

    if (tid < 64) idx_s[tid] = inp[rbase + tid];
    __syncthreads();

    int rl = tid >> 2;
    int kq = (tid & 3) * 4;
    const float* arow = emb + (size_t)idx_s[rl] * EMB + kq;
    const float* brow = wx0 + (size_t)(nbase + rl) * EMB + kq;

    int ty = tid >> 4, tx = tid & 15;
    ull acc[4][2] = {};

    for (int kt = 0; kt < EMB; kt += 16) {
        float4 av = *(const float4*)(arow + kt);
        float4 bv = *(const float4*)(brow + kt);
        As[kq + 0][rl] = av.x; As[kq + 1][rl] = av.y;
        As[kq + 2][rl] = av.z; As[kq + 3][rl] = av.w;
        Bs[kq + 0][rl] = bv.x; Bs[kq + 1][rl] = bv.y;
        Bs[kq + 2][rl] = bv.z; Bs[kq + 3][rl] = bv.w;
        __syncthreads();

        #pragma unroll
        for (int kk = 0; kk < 16; kk++) {
            float4 a4 = *(const float4*)&As[kk][ty * 4];
            float4 b4 = *(const float4*)&Bs[kk][tx * 4];
            ull b01 = pk2(b4.x, b4.y), b23 = pk2(b4.z, b4.w);
            ull a;
            a = pk2(a4.x, a4.x); fma2(acc[0][0], a, b01); fma2(acc[0][1], a, b23);
            a = pk2(a4.y, a4.y); fma2(acc[1][0], a, b01); fma2(acc[1][1], a, b23);
            a = pk2(a4.z, a4.z); fma2(acc[2][0], a, b01); fma2(acc[2][1], a, b23);
            a = pk2(a4.w, a4.w); fma2(acc[3][0], a, b01); fma2(acc[3][1], a, b23);
        }
        __syncthreads();
    }

    int n0 = nbase + tx * 4;
    float4 bb = *(const float4*)(bh0 + n0);
    #pragma unroll
    for (int i = 0; i < 4; i++) {
        int r = rbase + ty * 4 + i;
        float2 p0 = up2(acc[i][0]), p1 = up2(acc[i][1]);
        float4 o = make_float4(p0.x + bb.x, p0.y + bb.y, p1.x + bb.z, p1.y + bb.w);
        *(float4*)&g_xproj0[(size_t)r * HID + n0] = o;
    }
}

// ---------------- persistent recurrence -------------------------------------
// Blocks 0..31  (layer 0): own cols [b*32, b*32+32) of wh0, smem-resident.
//   step k: h0[k+1] = tanh(xproj0[k] + h0[k] @ wh0^T)   for k in [0,128)
// Blocks 32..95 (layer 1): own cols [j*16, j*16+16) of wx1 AND wh1.
//   step k: h1[k] = tanh(h0[k] @ wx1^T + h1[k-1] @ wh1^T + bh1)   for k in [1,128]
// Grid barrier between iterations. A chunks double-buffered (reg prefetch),
// stored duplicated as (a,a) float2 so the inner loop needs no packing movs.

__device__ __forceinline__ void sts_dup(float2* dst, int kqa, int r,
                                        float4 a, float4 b) {
    dst[(kqa + 0) * 64 + r] = make_float2(a.x, a.x);
    dst[(kqa + 1) * 64 + r] = make_float2(a.y, a.y);
    dst[(kqa + 2) * 64 + r] = make_float2(a.z, a.z);
    dst[(kqa + 3) * 64 + r] = make_float2(a.w, a.w);
    dst[(kqa + 4) * 64 + r] = make_float2(b.x, b.x);
    dst[(kqa + 5) * 64 + r] = make_float2(b.y, b.y);
    dst[(kqa + 6) * 64 + r] = make_float2(b.z, b.z);
    dst[(kqa + 7) * 64 + r] = make_float2(b.w, b.w);
}

__global__ __launch_bounds__(256, 1) void recur_kernel(
    const float* __restrict__ wh0, const float* __restrict__ wx1,
    const float* __restrict__ wh1, const float* __restrict__ bh1)
{
    extern __shared__ float smem[];
    const int tid = threadIdx.x;
    const int bid = blockIdx.x;
    const bool is_l1 = (bid >= NB_L0);

    float*  Wt  = smem;
    float2* As2 = is_l1 ? (float2*)(smem + 2048 * W1_STRIDE)
                        : (float2*)(smem + 1024 * W0_STRIDE);

    // ---- one-time weight preload (transposed: Wt[k][col]) ----
    if (!is_l1) {
        int nbase = bid * 32;
        #pragma unroll 4
        for (int it = 0; it < 32; it++) {
            int lin = tid + it * 256;            // 0..8191
            int c   = lin >> 8;                  // 0..31
            int kq  = (lin & 255) * 4;
            float4 v = *(const float4*)(wh0 + (size_t)(nbase + c) * HID + kq);
            Wt[(kq + 0) * W0_STRIDE + c] = v.x;
            Wt[(kq + 1) * W0_STRIDE + c] = v.y;
            Wt[(kq + 2) * W0_STRIDE + c] = v.z;
            Wt[(kq + 3) * W0_STRIDE + c] = v.w;
        }
    } else {
        int nbase = (bid - NB_L0) * 16;
        #pragma unroll 4
        for (int it = 0; it < 32; it++) {
            int lin = tid + it * 256;            // 0..8191
            int mat = lin >> 12;                 // 0: wx1, 1: wh1
            int rem = lin & 4095;
            int c   = rem >> 8;                  // 0..15
            int kq  = (rem & 255) * 4;
            const float* W = mat ? wh1 : wx1;
            float4 v = *(const float4*)(W + (size_t)(nbase + c) * HID + kq);
            int rb = mat * 1024 + kq;
            Wt[(rb + 0) * W1_STRIDE + c] = v.x;
            Wt[(rb + 1) * W1_STRIDE + c] = v.y;
            Wt[(rb + 2) * W1_STRIDE + c] = v.z;
            Wt[(rb + 3) * W1_STRIDE + c] = v.w;
        }
    }
    __syncthreads();

    const int m   = tid & 63;
    const int nq  = tid >> 6;       // 0..3
    const int kqa = nq * 8;         // A-loader k-offset within chunk

    for (int k = 0; k <= SEQ; k++) {
        bool active = is_l1 ? (k >= 1) : (k < SEQ);
        if (active) {
            if (!is_l1) {
                // ---------------- layer 0: 32 chunks of K ----------------
                const float* A = g_h0 + (size_t)k * BH + (size_t)m * HID;
                ull acc0 = 0, acc1 = 0, acc2 = 0, acc3 = 0;

                float4 pa = *(const float4*)(A + kqa);
                float4 pb = *(const float4*)(A + kqa + 4);
                sts_dup(As2, kqa, m, pa, pb);
                __syncthreads();

                for (int ct = 0; ct < 32; ct++) {
                    float4 na, nb;
                    if (ct + 1 < 32) {
                        int kt = (ct + 1) * KC;
                        na = *(const float4*)(A + kt + kqa);
                        nb = *(const float4*)(A + kt + kqa + 4);
                    }
                    const float2* Ab = As2 + (size_t)(ct & 1) * (KC * 64);
                    const float*  Wr = Wt + (size_t)(ct * KC) * W0_STRIDE + nq * 8;
                    #pragma unroll
                    for (int kk = 0; kk < KC; kk++) {
                        ull a2 = *(const ull*)&Ab[kk * 64 + m];
                        const float* wr = Wr + kk * W0_STRIDE;
                        ulonglong2 w0 = *(const ulonglong2*)(wr);
                        ulonglong2 w1 = *(const ulonglong2*)(wr + 4);
                        fma2(acc0, a2, w0.x); fma2(acc1, a2, w0.y);
                        fma2(acc2, a2, w1.x); fma2(acc3, a2, w1.y);
                    }
                    if (ct + 1 < 32) {
                        float2* dst = As2 + (size_t)((ct + 1) & 1) * (KC * 64);
                        sts_dup(dst, kqa, m, na, nb);
                    }
                    __syncthreads();
                }

                int n0 = bid * 32 + nq * 8;
                const float* xr = g_xproj0 + ((size_t)k * BATCH + m) * HID + n0;
                float4 x0 = *(const float4*)xr;
                float4 x1 = *(const float4*)(xr + 4);
                float2 p0 = up2(acc0), p1 = up2(acc1);
                float2 p2 = up2(acc2), p3 = up2(acc3);
                float4 o0 = make_float4(tanhf(p0.x + x0.x), tanhf(p0.y + x0.y),
                                        tanhf(p1.x + x0.z), tanhf(p1.y + x0.w));
                float4 o1 = make_float4(tanhf(p2.x + x1.x), tanhf(p2.y + x1.y),
                                        tanhf(p3.x + x1.z), tanhf(p3.y + x1.w));
                float* orow = g_h0 + (size_t)(k + 1) * BH + (size_t)m * HID + n0;
                *(float4*)orow = o0;
                *(float4*)(orow + 4) = o1;
            } else {
                // ---------------- layer 1: 64 chunks (wx1 then wh1) -------
                const float* A0 = g_h0 + (size_t)k * BH + (size_t)m * HID;
                const float* A1 = g_h1 + (size_t)(k - 1) * BH + (size_t)m * HID;
                ull acc0 = 0, acc1 = 0;

                float4 pa = *(const float4*)(A0 + kqa);
                float4 pb = *(const float4*)(A0 + kqa + 4);
                sts_dup(As2, kqa, m, pa, pb);
                __syncthreads();

                for (int ct = 0; ct < 64; ct++) {
                    float4 na, nb;
                    if (ct + 1 < 64) {
                        const float* src = (ct + 1 < 32) ? A0 : A1;
                        int kt = ((ct + 1) & 31) * KC;
                        na = *(const float4*)(src + kt + kqa);
                        nb = *(const float4*)(src + kt + kqa + 4);
                    }
                    const float2* Ab = As2 + (size_t)(ct & 1) * (KC * 64);
                    const float*  Wr = Wt + (size_t)(ct * KC) * W1_STRIDE + nq * 4;
                    #pragma unroll
                    for (int kk = 0; kk < KC; kk++) {
                        ull a2 = *(const ull*)&Ab[kk * 64 + m];
                        ulonglong2 w = *(const ulonglong2*)(Wr + kk * W1_STRIDE);
                        fma2(acc0, a2, w.x);
                        fma2(acc1, a2, w.y);
                    }
                    if (ct + 1 < 64) {
                        float2* dst = As2 + (size_t)((ct + 1) & 1) * (KC * 64);
                        sts_dup(dst, kqa, m, na, nb);
                    }
                    __syncthreads();
                }

                int n0 = (bid - NB_L0) * 16 + nq * 4;
                float4 bb = *(const float4*)(bh1 + n0);
                float2 p0 = up2(acc0), p1 = up2(acc1);
                float4 o = make_float4(tanhf(p0.x + bb.x), tanhf(p0.y + bb.y),
                                       tanhf(p1.x + bb.z), tanhf(p1.y + bb.w));
                *(float4*)(g_h1 + (size_t)k * BH + (size_t)m * HID + n0) = o;
            }
        }

        // ---- grid barrier (not after the final iteration) ----
        if (k < SEQ) {
            __threadfence();
            __syncthreads();
            if (tid == 0) {
                atomicAdd(&g_bar, 1u);
                unsigned target = (unsigned)(k + 1) * NBLK;
                unsigned v;
                do {
                    asm volatile("ld.global.acquire.gpu.b32 %0, [%1];"
                                 : "=r"(v) : "l"(&g_bar) : "memory");
                } while (v < target);
            }
            __syncthreads();
        }
    }
}

// ---------------- logits: out = top(8192x1024) @ v_w^T + v_b ----------------
__global__ __launch_bounds__(256, 2) void logits_kernel(
    const float* __restrict__ vw, const float* __restrict__ vb,
    float* __restrict__ out)
{
    __shared__ float As[16][132];
    __shared__ float Bs[16][132];

    int tid = threadIdx.x;
    int mbase = blockIdx.y * 128;
    int nbase = blockIdx.x * 128;
    int tx = tid & 15, ty = tid >> 4;

    const float* Ag = g_h1 + BH;  // top outputs: slots 1..128

    int rl  = tid >> 1;
    int kq8 = (tid & 1) * 8;
    int arow = mbase + rl;
    int brow = nbase + rl;
    if (brow >= VOCAB) brow = VOCAB - 1;

    const float* aro = Ag + (size_t)arow * HID + kq8;
    const float* bro = vw + (size_t)brow * HID + kq8;

    ull acc[8][4] = {};

    for (int kt = 0; kt < HID; kt += 16) {
        float4 a0 = *(const float4*)(aro + kt);
        float4 a1 = *(const float4*)(aro + kt + 4);
        float4 b0 = *(const float4*)(bro + kt);
        float4 b1 = *(const float4*)(bro + kt + 4);
        As[kq8 + 0][rl] = a0.x; As[kq8 + 1][rl] = a0.y;
        As[kq8 + 2][rl] = a0.z; As[kq8 + 3][rl] = a0.w;
        As[kq8 + 4][rl] = a1.x; As[kq8 + 5][rl] = a1.y;
        As[kq8 + 6][rl] = a1.z; As[kq8 + 7][rl] = a1.w;
        Bs[kq8 + 0][rl] = b0.x; Bs[kq8 + 1][rl] = b0.y;
        Bs[kq8 + 2][rl] = b0.z; Bs[kq8 + 3][rl] = b0.w;
        Bs[kq8 + 4][rl] = b1.x; Bs[kq8 + 5][rl] = b1.y;
        Bs[kq8 + 6][rl] = b1.z; Bs[kq8 + 7][rl] = b1.w;
        __syncthreads();

        #pragma unroll
        for (int kk = 0; kk < 16; kk++) {
            float4 aA = *(const float4*)&As[kk][ty * 8];
            float4 aB = *(const float4*)&As[kk][ty * 8 + 4];
            float4 bA = *(const float4*)&Bs[kk][tx * 8];
            float4 bB = *(const float4*)&Bs[kk][tx * 8 + 4];
            ull bp0 = pk2(bA.x, bA.y), bp1 = pk2(bA.z, bA.w);
            ull bp2 = pk2(bB.x, bB.y), bp3 = pk2(bB.z, bB.w);
            float am[8] = {aA.x, aA.y, aA.z, aA.w, aB.x, aB.y, aB.z, aB.w};
            #pragma unroll
            for (int i = 0; i < 8; i++) {
                ull a2 = pk2(am[i], am[i]);
                fma2(acc[i][0], a2, bp0);
                fma2(acc[i][1], a2, bp1);
                fma2(acc[i][2], a2, bp2);
                fma2(acc[i][3], a2, bp3);
            }
        }
        __syncthreads();
    }

    #pragma unroll
    for (int i = 0; i < 8; i++) {
        int r = mbase + ty * 8 + i;
        float* orow = out + (size_t)r * VOCAB;
        #pragma unroll
        for (int j = 0; j < 4; j++) {
            int n0 = nbase + tx * 8 + 2 * j;
            float2 p = up2(acc[i][j]);
            if (n0 < VOCAB)     orow[n0]     = p.x + vb[n0];
            if (n0 + 1 < VOCAB) orow[n0 + 1] = p.y + vb[n0 + 1];
        }
    }
}

// ---------------- finalize: hidden_final appended after logits --------------
__global__ void finalize_kernel(float* __restrict__ out) {
    int i = blockIdx.x * blockDim.x + threadIdx.x;
    if (i < BH) {
        size_t base = (size_t)ROWS * VOCAB;
        out[base + i]      = g_h0[(size_t)SEQ * BH + i];
        out[base + BH + i] = g_h1[(size_t)SEQ * BH + i];
    }
}

// ---------------- launcher ---------------------------------------------------
extern "C" void kernel_launch(void* const* d_in, const int* in_sizes, int n_in,
                              void* d_out, int out_size)
{
    const int*   inputs    = (const int*)  d_in[0];
    const float* hidden    = (const float*)d_in[1];
    const float* embedding = (const float*)d_in[2];
    const float* wx0       = (const float*)d_in[3];
    const float* wh0       = (const float*)d_in[4];
    const float* bh0       = (const float*)d_in[5];
    const float* wx1       = (const float*)d_in[6];
    const float* wh1       = (const float*)d_in[7];
    const float* bh1       = (const float*)d_in[8];
    const float* v_w       = (const float*)d_in[9];
    const float* v_b       = (const float*)d_in[10];
    float* out = (float*)d_out;

    static bool attr_set = false;
    if (!attr_set) {
        cudaFuncSetAttribute(recur_kernel,
                             cudaFuncAttributeMaxDynamicSharedMemorySize,
                             RECUR_SMEM);
        attr_set = true;
    }

    init_kernel<<<(BH + 255) / 256, 256>>>(hidden);
    xproj_kernel<<<dim3(HID / 64, ROWS / 64), 256>>>(inputs, embedding, wx0, bh0);
    recur_kernel<<<NBLK, 256, RECUR_SMEM>>>(wh0, wx1, wh1, bh1);
    logits_kernel<<<dim3((VOCAB + 127) / 128, ROWS / 128), 256>>>(v_w, v_b, out);

    long long need = (long long)ROWS * VOCAB + 2LL * BH;
    if ((long long)out_size >= need) {
        finalize_kernel<<<(BH + 255) / 256, 256>>>(out);
    }
}

// round 3
// speedup vs baseline: 1.6450x; 1.4986x over previous
#include <cuda_runtime.h>
#include <math.h>

// Problem constants
#define EMB   1024
#define HID   1024
#define SEQ   128
#define BATCH 64
#define VOCAB 10000
#define BH    (BATCH * HID)      // 65536
#define ROWS  (SEQ * BATCH)      // 8192

// Persistent recurrence config
#define NB_L0 32                 // layer-0 blocks: 32 n-cols each
#define NB_L1 64                 // layer-1 blocks: 16 n-cols each (wx1+wh1)
#define NBLK  (NB_L0 + NB_L1)    // 96 blocks, 1/SM
#define W0S   36                 // layer-0 smem W row stride (floats, 16B mult)
#define W1S   20                 // layer-1 smem W row stride
#define W0_WORDS (1024 * W0S)    // 36864 floats
#define W1_WORDS (2048 * W1S)    // 40960 floats
#define RECUR_SMEM (W1_WORDS * 4 + 192 * 8 * 8)   // 163840 + 12288 = 176128

typedef unsigned long long ull;

// ---------------- scratch (device globals; no allocation allowed) ----------
__device__ float g_xproj0[ROWS * HID];               // [t*64+m][n] row-major
__device__ float g_h0T[(SEQ + 1) * HID * BATCH];     // [k][n][m]
__device__ float g_h1T[(SEQ + 1) * HID * BATCH];     // [k][n][m]
__device__ float g_h1rm[ROWS * HID];                 // [t*64+m][n] for logits
__device__ unsigned g_bar;

// ---------------- helpers ---------------------------------------------------
__device__ __forceinline__ ull pk2(float x, float y) {
    ull r; asm("mov.b64 %0, {%1, %2};" : "=l"(r) : "f"(x), "f"(y)); return r;
}
__device__ __forceinline__ void fma2(ull& c, ull a, ull b) {
    asm("fma.rn.f32x2 %0, %1, %2, %0;" : "+l"(c) : "l"(a), "l"(b));
}
__device__ __forceinline__ float2 up2(ull v) {
    float2 r; asm("mov.b64 {%0, %1}, %2;" : "=f"(r.x), "=f"(r.y) : "l"(v)); return r;
}
__device__ __forceinline__ unsigned smem_u32(const void* p) {
    unsigned a;
    asm("{ .reg .u64 t; cvta.to.shared.u64 t, %1; cvt.u32.u64 %0, t; }"
        : "=r"(a) : "l"(p));
    return a;
}
__device__ __forceinline__ ulonglong2 lds128(unsigned a) {
    ulonglong2 r;
    asm volatile("ld.shared.v2.u64 {%0,%1}, [%2];"
                 : "=l"(r.x), "=l"(r.y) : "r"(a));
    return r;
}

// ---------------- init -------------------------------------------------------
__global__ void init_kernel(const float* __restrict__ hidden) {
    int i = blockIdx.x * blockDim.x + threadIdx.x;
    if (i == 0) g_bar = 0;
    if (i < BH) {
        int n = i >> 6, m = i & 63;
        g_h0T[i] = hidden[(size_t)m * HID + n];
        g_h1T[i] = hidden[BH + (size_t)m * HID + n];
    }
}

// ---------------- xproj: g_xproj0 = gather(emb, inputs) @ wx0^T + bh0 -------
__global__ __launch_bounds__(256) void xproj_kernel(
    const int* __restrict__ inp, const float* __restrict__ emb,
    const float* __restrict__ wx0, const float* __restrict__ bh0)
{
    __shared__ int   idx_s[64];
    __shared__ float As[16][68];
    __shared__ float Bs[16][68];

    int tid   = threadIdx.x;
    int rbase = blockIdx.y * 64;
    int nbase = blockIdx.x * 64;

    if (tid < 64) idx_s[tid] = inp[rbase + tid];
    __syncthreads();

    int rl = tid >> 2;
    int kq = (tid & 3) * 4;
    const float* arow = emb + (size_t)idx_s[rl] * EMB + kq;
    const float* brow = wx0 + (size_t)(nbase + rl) * EMB + kq;

    int ty = tid >> 4, tx = tid & 15;
    ull acc[4][2] = {};

    for (int kt = 0; kt < EMB; kt += 16) {
        float4 av = *(const float4*)(arow + kt);
        float4 bv = *(const float4*)(brow + kt);
        As[kq + 0][rl] = av.x; As[kq + 1][rl] = av.y;
        As[kq + 2][rl] = av.z; As[kq + 3][rl] = av.w;
        Bs[kq + 0][rl] = bv.x; Bs[kq + 1][rl] = bv.y;
        Bs[kq + 2][rl] = bv.z; Bs[kq + 3][rl] = bv.w;
        __syncthreads();

        #pragma unroll
        for (int kk = 0; kk < 16; kk++) {
            float4 a4 = *(const float4*)&As[kk][ty * 4];
            float4 b4 = *(const float4*)&Bs[kk][tx * 4];
            ull b01 = pk2(b4.x, b4.y), b23 = pk2(b4.z, b4.w);
            ull a;
            a = pk2(a4.x, a4.x); fma2(acc[0][0], a, b01); fma2(acc[0][1], a, b23);
            a = pk2(a4.y, a4.y); fma2(acc[1][0], a, b01); fma2(acc[1][1], a, b23);
            a = pk2(a4.z, a4.z); fma2(acc[2][0], a, b01); fma2(acc[2][1], a, b23);
            a = pk2(a4.w, a4.w); fma2(acc[3][0], a, b01); fma2(acc[3][1], a, b23);
        }
        __syncthreads();
    }

    int n0 = nbase + tx * 4;
    float4 bb = *(const float4*)(bh0 + n0);
    #pragma unroll
    for (int i = 0; i < 4; i++) {
        int r = rbase + ty * 4 + i;
        float2 p0 = up2(acc[i][0]), p1 = up2(acc[i][1]);
        float4 o = make_float4(p0.x + bb.x, p0.y + bb.y, p1.x + bb.z, p1.y + bb.w);
        *(float4*)&g_xproj0[(size_t)r * HID + n0] = o;
    }
}

// ---------------- recurrence core GEMM slice ---------------------------------
// Accumulates 16 n-outputs (8 f32x2) over 512 k for one m-row.
// A: global, element stride 64 floats (transposed h). W: smem broadcast rows.
template<int WS>
__device__ __forceinline__ void gemm512(unsigned wbase, const float* __restrict__ A,
                                        ull* acc)
{
    float bufA[16], bufB[16];
    #pragma unroll
    for (int j = 0; j < 16; j++) bufA[j] = A[j * 64];

    #pragma unroll 1
    for (int ct = 0; ct < 32; ct += 2) {
        const float* A1 = A + (size_t)(ct + 1) * 16 * 64;
        #pragma unroll
        for (int j = 0; j < 16; j++) bufB[j] = A1[j * 64];

        unsigned w0 = wbase + (unsigned)(ct * 16 * WS * 4);
        #pragma unroll
        for (int kk = 0; kk < 16; kk++) {
            ull a2 = pk2(bufA[kk], bufA[kk]);
            unsigned wa = w0 + kk * WS * 4;
            ulonglong2 x = lds128(wa);
            ulonglong2 y = lds128(wa + 16);
            ulonglong2 z = lds128(wa + 32);
            ulonglong2 t = lds128(wa + 48);
            fma2(acc[0], a2, x.x); fma2(acc[1], a2, x.y);
            fma2(acc[2], a2, y.x); fma2(acc[3], a2, y.y);
            fma2(acc[4], a2, z.x); fma2(acc[5], a2, z.y);
            fma2(acc[6], a2, t.x); fma2(acc[7], a2, t.y);
        }

        if (ct + 2 < 32) {
            const float* A2 = A + (size_t)(ct + 2) * 16 * 64;
            #pragma unroll
            for (int j = 0; j < 16; j++) bufA[j] = A2[j * 64];
        }
        unsigned w1 = w0 + (unsigned)(16 * WS * 4);
        #pragma unroll
        for (int kk = 0; kk < 16; kk++) {
            ull a2 = pk2(bufB[kk], bufB[kk]);
            unsigned wa = w1 + kk * WS * 4;
            ulonglong2 x = lds128(wa);
            ulonglong2 y = lds128(wa + 16);
            ulonglong2 z = lds128(wa + 32);
            ulonglong2 t = lds128(wa + 48);
            fma2(acc[0], a2, x.x); fma2(acc[1], a2, x.y);
            fma2(acc[2], a2, y.x); fma2(acc[3], a2, y.y);
            fma2(acc[4], a2, z.x); fma2(acc[5], a2, z.y);
            fma2(acc[6], a2, t.x); fma2(acc[7], a2, t.y);
        }
    }
}

// ---------------- persistent recurrence --------------------------------------
// Layer 0 (blocks 0..31, 32 cols): thread = (m, ng in {0,1}, q in {0,1});
//   computes 16 n over k-half q; reduce q-pairs via smem.
// Layer 1 (blocks 32..95, 16 cols): thread = (m, q in 0..3) over virtual
//   K=2048 (wx1 rows 0..1023 with h0T[k], wh1 rows 1024..2047 with h1T[k-1]).
__global__ __launch_bounds__(256, 1) void recur_kernel(
    const float* __restrict__ wh0, const float* __restrict__ wx1,
    const float* __restrict__ wh1, const float* __restrict__ bh1)
{
    extern __shared__ float smem[];
    const int tid = threadIdx.x;
    const int bid = blockIdx.x;
    const bool is_l1 = (bid >= NB_L0);
    const unsigned sbase = smem_u32(smem);

    // ---- one-time transposed weight preload into smem ----
    if (!is_l1) {
        int nb = bid * 32;
        #pragma unroll 4
        for (int it = 0; it < 128; it++) {
            int lin = it * 256 + tid;            // c*1024 + k
            int c = lin >> 10, k = lin & 1023;
            smem[k * W0S + c] = wh0[(size_t)(nb + c) * HID + k];
        }
    } else {
        int nb = (bid - NB_L0) * 16;
        #pragma unroll 4
        for (int it = 0; it < 128; it++) {
            int lin = it * 256 + tid;            // c*2048 + kv
            int c = lin >> 11, kv = lin & 2047;
            const float* W = (kv < 1024) ? wx1 : wh1;
            smem[kv * W1S + c] = W[(size_t)(nb + c) * HID + (kv & 1023)];
        }
    }
    __syncthreads();

    const int m = tid & 63;
    const int g = tid >> 6;          // 0..3

    for (int k = 0; k <= SEQ; k++) {
        bool active = is_l1 ? (k >= 1) : (k < SEQ);
        if (active) {
            if (!is_l1) {
                const int ng = g & 1, q = g >> 1;
                ull acc[8] = {};
                const float* A = g_h0T + (size_t)k * BH + (size_t)(q * 512) * 64 + m;
                unsigned wbase = sbase + (unsigned)((q * 512 * W0S + ng * 16) * 4);
                gemm512<W0S>(wbase, A, acc);

                ull* red = (ull*)(smem + W0_WORDS);
                int slot = ng * 64 + m;
                if (q == 1) {
                    #pragma unroll
                    for (int j = 0; j < 8; j++) red[slot * 8 + j] = acc[j];
                }
                __syncthreads();
                if (q == 0) {
                    int n0 = bid * 32 + ng * 16;
                    const float* xr = g_xproj0 + ((size_t)k * BATCH + m) * HID + n0;
                    float4 x0 = *(const float4*)(xr);
                    float4 x1 = *(const float4*)(xr + 4);
                    float4 x2 = *(const float4*)(xr + 8);
                    float4 x3 = *(const float4*)(xr + 12);
                    float xv[16] = {x0.x,x0.y,x0.z,x0.w, x1.x,x1.y,x1.z,x1.w,
                                    x2.x,x2.y,x2.z,x2.w, x3.x,x3.y,x3.z,x3.w};
                    float* outT = g_h0T + (size_t)(k + 1) * BH + (size_t)n0 * 64 + m;
                    #pragma unroll
                    for (int j = 0; j < 8; j++) {
                        float2 p = up2(acc[j]);
                        float2 o = up2(red[slot * 8 + j]);
                        float r0 = tanhf(p.x + o.x + xv[2 * j]);
                        float r1 = tanhf(p.y + o.y + xv[2 * j + 1]);
                        outT[(size_t)(2 * j) * 64]     = r0;
                        outT[(size_t)(2 * j + 1) * 64] = r1;
                    }
                }
            } else {
                const int q = g;
                ull acc[8] = {};
                const float* A = (q < 2)
                    ? g_h0T + (size_t)k * BH + (size_t)(q * 512) * 64 + m
                    : g_h1T + (size_t)(k - 1) * BH + (size_t)((q - 2) * 512) * 64 + m;
                unsigned wbase = sbase + (unsigned)((q * 512 * W1S) * 4);
                gemm512<W1S>(wbase, A, acc);

                ull* red = (ull*)(smem + W1_WORDS);
                if (q > 0) {
                    int slot = (q - 1) * 64 + m;
                    #pragma unroll
                    for (int j = 0; j < 8; j++) red[slot * 8 + j] = acc[j];
                }
                __syncthreads();
                if (q == 0) {
                    int n0 = (bid - NB_L0) * 16;
                    float4 b0 = *(const float4*)(bh1 + n0);
                    float4 b1 = *(const float4*)(bh1 + n0 + 4);
                    float4 b2 = *(const float4*)(bh1 + n0 + 8);
                    float4 b3 = *(const float4*)(bh1 + n0 + 12);
                    float bv[16] = {b0.x,b0.y,b0.z,b0.w, b1.x,b1.y,b1.z,b1.w,
                                    b2.x,b2.y,b2.z,b2.w, b3.x,b3.y,b3.z,b3.w};
                    float res[16];
                    #pragma unroll
                    for (int j = 0; j < 8; j++) {
                        float2 p = up2(acc[j]);
                        float2 r1 = up2(red[(0 * 64 + m) * 8 + j]);
                        float2 r2 = up2(red[(1 * 64 + m) * 8 + j]);
                        float2 r3 = up2(red[(2 * 64 + m) * 8 + j]);
                        res[2 * j]     = tanhf(p.x + r1.x + r2.x + r3.x + bv[2 * j]);
                        res[2 * j + 1] = tanhf(p.y + r1.y + r2.y + r3.y + bv[2 * j + 1]);
                    }
                    float* outT = g_h1T + (size_t)k * BH + (size_t)n0 * 64 + m;
                    #pragma unroll
                    for (int j = 0; j < 16; j++) outT[(size_t)j * 64] = res[j];
                    float* orm = g_h1rm + ((size_t)(k - 1) * BATCH + m) * HID + n0;
                    *(float4*)(orm)      = make_float4(res[0], res[1], res[2], res[3]);
                    *(float4*)(orm + 4)  = make_float4(res[4], res[5], res[6], res[7]);
                    *(float4*)(orm + 8)  = make_float4(res[8], res[9], res[10], res[11]);
                    *(float4*)(orm + 12) = make_float4(res[12], res[13], res[14], res[15]);
                }
            }
        }

        // ---- grid barrier ----
        if (k < SEQ) {
            __threadfence();
            __syncthreads();
            if (tid == 0) {
                atomicAdd(&g_bar, 1u);
                unsigned target = (unsigned)(k + 1) * NBLK;
                unsigned v;
                do {
                    asm volatile("ld.global.acquire.gpu.b32 %0, [%1];"
                                 : "=r"(v) : "l"(&g_bar) : "memory");
                } while (v < target);
            }
            __syncthreads();
        }
    }
}

// ---------------- logits: out = h1rm(8192x1024) @ v_w^T + v_b ---------------
// 128x128 tile, 256 threads, 8x8 microtile; A pre-duplicated (a,a) in smem,
// B read as ld.shared.v2.u64 — no packing movs in the inner loop.
__global__ __launch_bounds__(256, 2) void logits_kernel(
    const float* __restrict__ vw, const float* __restrict__ vb,
    float* __restrict__ out)
{
    __shared__ ull   As2[16][132];
    __shared__ float Bs[16][132];

    int tid = threadIdx.x;
    int mbase = blockIdx.y * 128;
    int nbase = blockIdx.x * 128;
    int tx = tid & 15, ty = tid >> 4;

    int rl  = tid >> 1;
    int kq8 = (tid & 1) * 8;
    int brow = nbase + rl;
    if (brow >= VOCAB) brow = VOCAB - 1;

    const float* aro = g_h1rm + (size_t)(mbase + rl) * HID + kq8;
    const float* bro = vw + (size_t)brow * HID + kq8;

    const unsigned abase = smem_u32(As2) + (unsigned)(ty * 8 * 8);
    const unsigned bbase = smem_u32(Bs)  + (unsigned)(tx * 8 * 4);

    ull acc[8][4] = {};

    for (int kt = 0; kt < HID; kt += 16) {
        float4 a0 = *(const float4*)(aro + kt);
        float4 a1 = *(const float4*)(aro + kt + 4);
        float4 b0 = *(const float4*)(bro + kt);
        float4 b1 = *(const float4*)(bro + kt + 4);
        As2[kq8 + 0][rl] = pk2(a0.x, a0.x);
        As2[kq8 + 1][rl] = pk2(a0.y, a0.y);
        As2[kq8 + 2][rl] = pk2(a0.z, a0.z);
        As2[kq8 + 3][rl] = pk2(a0.w, a0.w);
        As2[kq8 + 4][rl] = pk2(a1.x, a1.x);
        As2[kq8 + 5][rl] = pk2(a1.y, a1.y);
        As2[kq8 + 6][rl] = pk2(a1.z, a1.z);
        As2[kq8 + 7][rl] = pk2(a1.w, a1.w);
        Bs[kq8 + 0][rl] = b0.x; Bs[kq8 + 1][rl] = b0.y;
        Bs[kq8 + 2][rl] = b0.z; Bs[kq8 + 3][rl] = b0.w;
        Bs[kq8 + 4][rl] = b1.x; Bs[kq8 + 5][rl] = b1.y;
        Bs[kq8 + 6][rl] = b1.z; Bs[kq8 + 7][rl] = b1.w;
        __syncthreads();

        #pragma unroll
        for (int kk = 0; kk < 16; kk++) {
            unsigned aa = abase + (unsigned)(kk * 132 * 8);
            unsigned ba = bbase + (unsigned)(kk * 132 * 4);
            ulonglong2 A0 = lds128(aa);
            ulonglong2 A1 = lds128(aa + 16);
            ulonglong2 A2 = lds128(aa + 32);
            ulonglong2 A3 = lds128(aa + 48);
            ulonglong2 B0 = lds128(ba);
            ulonglong2 B1 = lds128(ba + 16);
            ull am[8] = {A0.x, A0.y, A1.x, A1.y, A2.x, A2.y, A3.x, A3.y};
            ull bp[4] = {B0.x, B0.y, B1.x, B1.y};
            #pragma unroll
            for (int i = 0; i < 8; i++) {
                fma2(acc[i][0], am[i], bp[0]);
                fma2(acc[i][1], am[i], bp[1]);
                fma2(acc[i][2], am[i], bp[2]);
                fma2(acc[i][3], am[i], bp[3]);
            }
        }
        __syncthreads();
    }

    #pragma unroll
    for (int i = 0; i < 8; i++) {
        int r = mbase + ty * 8 + i;
        float* orow = out + (size_t)r * VOCAB;
        #pragma unroll
        for (int j = 0; j < 4; j++) {
            int n0 = nbase + tx * 8 + 2 * j;
            float2 p = up2(acc[i][j]);
            if (n0 < VOCAB)     orow[n0]     = p.x + vb[n0];
            if (n0 + 1 < VOCAB) orow[n0 + 1] = p.y + vb[n0 + 1];
        }
    }
}

// ---------------- finalize ----------------------------------------------------
__global__ void finalize_kernel(float* __restrict__ out) {
    int i = blockIdx.x * blockDim.x + threadIdx.x;
    if (i < 2 * BH) {
        int l = i >> 16;          // BH = 65536
        int r = i & (BH - 1);
        int b = r >> 10, n = r & 1023;
        const float* src = l ? g_h1T : g_h0T;
        out[(size_t)ROWS * VOCAB + i] = src[(size_t)SEQ * BH + (size_t)n * 64 + b];
    }
}

// ---------------- launcher ----------------------------------------------------
extern "C" void kernel_launch(void* const* d_in, const int* in_sizes, int n_in,
                              void* d_out, int out_size)
{
    const int*   inputs    = (const int*)  d_in[0];
    const float* hidden    = (const float*)d_in[1];
    const float* embedding = (const float*)d_in[2];
    const float* wx0       = (const float*)d_in[3];
    const float* wh0       = (const float*)d_in[4];
    const float* bh0       = (const float*)d_in[5];
    const float* wx1       = (const float*)d_in[6];
    const float* wh1       = (const float*)d_in[7];
    const float* bh1       = (const float*)d_in[8];
    const float* v_w       = (const float*)d_in[9];
    const float* v_b       = (const float*)d_in[10];
    float* out = (float*)d_out;

    static bool attr_set = false;
    if (!attr_set) {
        cudaFuncSetAttribute(recur_kernel,
                             cudaFuncAttributeMaxDynamicSharedMemorySize,
                             RECUR_SMEM);
        attr_set = true;
    }

    init_kernel<<<(BH + 255) / 256, 256>>>(hidden);
    xproj_kernel<<<dim3(HID / 64, ROWS / 64), 256>>>(inputs, embedding, wx0, bh0);
    recur_kernel<<<NBLK, 256, RECUR_SMEM>>>(wh0, wx1, wh1, bh1);
    logits_kernel<<<dim3((VOCAB + 127) / 128, ROWS / 128), 256>>>(v_w, v_b, out);

    long long need = (long long)ROWS * VOCAB + 2LL * BH;
    if ((long long)out_size >= need) {
        finalize_kernel<<<(2 * BH + 255) / 256, 256>>>(out);
    }
}

// round 5
// speedup vs baseline: 2.9071x; 1.7673x over previous
#include <cuda_runtime.h>
#include <cuda_bf16.h>
#include <math.h>

// Problem constants
#define EMB   1024
#define HID   1024
#define SEQ   128
#define BATCH 64
#define VOCAB 10000
#define VPAD  10112              // 79 * 128
#define BH    (BATCH * HID)      // 65536
#define ROWS  (SEQ * BATCH)      // 8192

// Persistent recurrence config
#define NB_L0 32
#define NB_L1 64
#define NBLK  (NB_L0 + NB_L1)
#define W0S   36
#define W1S   20
#define W0_WORDS (1024 * W0S)
#define W1_WORDS (2048 * W1S)
#define RECUR_SMEM (W1_WORDS * 4 + 192 * 8 * 8)

// Logits mma.sync config
#define KCH  64                  // bf16 K elements per chunk (128B rows)
#define NKT  (HID / KCH)         // 16 chunks
#define OP_BYTES 16384           // one operand tile: 128 rows x 128B
#define STAGE_BYTES (4 * OP_BYTES)
#define LOGITS_SMEM (2 * STAGE_BYTES + 1024)   // 132096

typedef unsigned long long ull;

// ---------------- scratch (device globals) ----------------------------------
__device__ float g_xproj0[ROWS * HID];
__device__ float g_h0T[(SEQ + 1) * HID * BATCH];
__device__ float g_h1T[(SEQ + 1) * HID * BATCH];
__device__ float g_h1rm[ROWS * HID];
__device__ unsigned g_bar;
__device__ __nv_bfloat16 g_Ah[ROWS * HID];
__device__ __nv_bfloat16 g_Al[ROWS * HID];
__device__ __nv_bfloat16 g_Bh[VPAD * HID];   // rows >= VOCAB stay zero (BSS)
__device__ __nv_bfloat16 g_Bl[VPAD * HID];

// ---------------- generic helpers -------------------------------------------
__device__ __forceinline__ ull pk2(float x, float y) {
    ull r; asm("mov.b64 %0, {%1, %2};" : "=l"(r) : "f"(x), "f"(y)); return r;
}
__device__ __forceinline__ void fma2(ull& c, ull a, ull b) {
    asm("fma.rn.f32x2 %0, %1, %2, %0;" : "+l"(c) : "l"(a), "l"(b));
}
__device__ __forceinline__ float2 up2(ull v) {
    float2 r; asm("mov.b64 {%0, %1}, %2;" : "=f"(r.x), "=f"(r.y) : "l"(v)); return r;
}
__device__ __forceinline__ unsigned smem_u32(const void* p) {
    unsigned a;
    asm("{ .reg .u64 t; cvta.to.shared.u64 t, %1; cvt.u32.u64 %0, t; }"
        : "=r"(a) : "l"(p));
    return a;
}
__device__ __forceinline__ ulonglong2 lds128(unsigned a) {
    ulonglong2 r;
    asm volatile("ld.shared.v2.u64 {%0,%1}, [%2];"
                 : "=l"(r.x), "=l"(r.y) : "r"(a));
    return r;
}

// ---------------- PTX macros (cp.async / ldmatrix / mma) ---------------------
#define SMEM_SWIZZLE_128B(o) ((o) ^ (((o) >> 3) & 0x70))

#define CP_ASYNC16(dst, src) \
    asm volatile("cp.async.cg.shared.global [%0], [%1], 16;" \
                 :: "r"(dst), "l"(src))
#define CP_ASYNC_COMMIT() asm volatile("cp.async.commit_group;" ::: "memory")
#define CP_ASYNC_WAIT(n)  asm volatile("cp.async.wait_group %0;" :: "n"(n) : "memory")

__device__ __forceinline__ void ldsm4(unsigned* r, unsigned addr) {
    asm volatile("ldmatrix.sync.aligned.m8n8.x4.shared.b16 {%0,%1,%2,%3}, [%4];"
                 : "=r"(r[0]), "=r"(r[1]), "=r"(r[2]), "=r"(r[3]) : "r"(addr));
}
__device__ __forceinline__ void mma16816(float* c, const unsigned* a,
                                         unsigned b0, unsigned b1) {
    asm volatile(
        "mma.sync.aligned.m16n8k16.row.col.f32.bf16.bf16.f32 "
        "{%0,%1,%2,%3}, {%4,%5,%6,%7}, {%8,%9}, {%0,%1,%2,%3};"
        : "+f"(c[0]), "+f"(c[1]), "+f"(c[2]), "+f"(c[3])
        : "r"(a[0]), "r"(a[1]), "r"(a[2]), "r"(a[3]), "r"(b0), "r"(b1));
}

// ---------------- init --------------------------------------------------------
__global__ void init_kernel(const float* __restrict__ hidden) {
    int i = blockIdx.x * blockDim.x + threadIdx.x;
    if (i == 0) g_bar = 0;
    if (i < BH) {
        int n = i >> 6, m = i & 63;
        g_h0T[i] = hidden[(size_t)m * HID + n];
        g_h1T[i] = hidden[BH + (size_t)m * HID + n];
    }
}

// ---------------- xproj (unchanged) ------------------------------------------
__global__ __launch_bounds__(256) void xproj_kernel(
    const int* __restrict__ inp, const float* __restrict__ emb,
    const float* __restrict__ wx0, const float* __restrict__ bh0)
{
    __shared__ int   idx_s[64];
    __shared__ float As[16][68];
    __shared__ float Bs[16][68];

    int tid   = threadIdx.x;
    int rbase = blockIdx.y * 64;
    int nbase = blockIdx.x * 64;

    if (tid < 64) idx_s[tid] = inp[rbase + tid];
    __syncthreads();

    int rl = tid >> 2;
    int kq = (tid & 3) * 4;
    const float* arow = emb + (size_t)idx_s[rl] * EMB + kq;
    const float* brow = wx0 + (size_t)(nbase + rl) * EMB + kq;

    int ty = tid >> 4, tx = tid & 15;
    ull acc[4][2] = {};

    for (int kt = 0; kt < EMB; kt += 16) {
        float4 av = *(const float4*)(arow + kt);
        float4 bv = *(const float4*)(brow + kt);
        As[kq + 0][rl] = av.x; As[kq + 1][rl] = av.y;
        As[kq + 2][rl] = av.z; As[kq + 3][rl] = av.w;
        Bs[kq + 0][rl] = bv.x; Bs[kq + 1][rl] = bv.y;
        Bs[kq + 2][rl] = bv.z; Bs[kq + 3][rl] = bv.w;
        __syncthreads();

        #pragma unroll
        for (int kk = 0; kk < 16; kk++) {
            float4 a4 = *(const float4*)&As[kk][ty * 4];
            float4 b4 = *(const float4*)&Bs[kk][tx * 4];
            ull b01 = pk2(b4.x, b4.y), b23 = pk2(b4.z, b4.w);
            ull a;
            a = pk2(a4.x, a4.x); fma2(acc[0][0], a, b01); fma2(acc[0][1], a, b23);
            a = pk2(a4.y, a4.y); fma2(acc[1][0], a, b01); fma2(acc[1][1], a, b23);
            a = pk2(a4.z, a4.z); fma2(acc[2][0], a, b01); fma2(acc[2][1], a, b23);
            a = pk2(a4.w, a4.w); fma2(acc[3][0], a, b01); fma2(acc[3][1], a, b23);
        }
        __syncthreads();
    }

    int n0 = nbase + tx * 4;
    float4 bb = *(const float4*)(bh0 + n0);
    #pragma unroll
    for (int i = 0; i < 4; i++) {
        int r = rbase + ty * 4 + i;
        float2 p0 = up2(acc[i][0]), p1 = up2(acc[i][1]);
        float4 o = make_float4(p0.x + bb.x, p0.y + bb.y, p1.x + bb.z, p1.y + bb.w);
        *(float4*)&g_xproj0[(size_t)r * HID + n0] = o;
    }
}

// ---------------- recurrence core slice (unchanged) ---------------------------
template<int WS>
__device__ __forceinline__ void gemm512(unsigned wbase, const float* __restrict__ A,
                                        ull* acc)
{
    float bufA[16], bufB[16];
    #pragma unroll
    for (int j = 0; j < 16; j++) bufA[j] = A[j * 64];

    #pragma unroll 1
    for (int ct = 0; ct < 32; ct += 2) {
        const float* A1 = A + (size_t)(ct + 1) * 16 * 64;
        #pragma unroll
        for (int j = 0; j < 16; j++) bufB[j] = A1[j * 64];

        unsigned w0 = wbase + (unsigned)(ct * 16 * WS * 4);
        #pragma unroll
        for (int kk = 0; kk < 16; kk++) {
            ull a2 = pk2(bufA[kk], bufA[kk]);
            unsigned wa = w0 + kk * WS * 4;
            ulonglong2 x = lds128(wa);
            ulonglong2 y = lds128(wa + 16);
            ulonglong2 z = lds128(wa + 32);
            ulonglong2 t = lds128(wa + 48);
            fma2(acc[0], a2, x.x); fma2(acc[1], a2, x.y);
            fma2(acc[2], a2, y.x); fma2(acc[3], a2, y.y);
            fma2(acc[4], a2, z.x); fma2(acc[5], a2, z.y);
            fma2(acc[6], a2, t.x); fma2(acc[7], a2, t.y);
        }

        if (ct + 2 < 32) {
            const float* A2 = A + (size_t)(ct + 2) * 16 * 64;
            #pragma unroll
            for (int j = 0; j < 16; j++) bufA[j] = A2[j * 64];
        }
        unsigned w1 = w0 + (unsigned)(16 * WS * 4);
        #pragma unroll
        for (int kk = 0; kk < 16; kk++) {
            ull a2 = pk2(bufB[kk], bufB[kk]);
            unsigned wa = w1 + kk * WS * 4;
            ulonglong2 x = lds128(wa);
            ulonglong2 y = lds128(wa + 16);
            ulonglong2 z = lds128(wa + 32);
            ulonglong2 t = lds128(wa + 48);
            fma2(acc[0], a2, x.x); fma2(acc[1], a2, x.y);
            fma2(acc[2], a2, y.x); fma2(acc[3], a2, y.y);
            fma2(acc[4], a2, z.x); fma2(acc[5], a2, z.y);
            fma2(acc[6], a2, t.x); fma2(acc[7], a2, t.y);
        }
    }
}

// ---------------- persistent recurrence (unchanged) ---------------------------
__global__ __launch_bounds__(256, 1) void recur_kernel(
    const float* __restrict__ wh0, const float* __restrict__ wx1,
    const float* __restrict__ wh1, const float* __restrict__ bh1)
{
    extern __shared__ float smem[];
    const int tid = threadIdx.x;
    const int bid = blockIdx.x;
    const bool is_l1 = (bid >= NB_L0);
    const unsigned sbase = smem_u32(smem);

    if (!is_l1) {
        int nb = bid * 32;
        #pragma unroll 4
        for (int it = 0; it < 128; it++) {
            int lin = it * 256 + tid;
            int c = lin >> 10, k = lin & 1023;
            smem[k * W0S + c] = wh0[(size_t)(nb + c) * HID + k];
        }
    } else {
        int nb = (bid - NB_L0) * 16;
        #pragma unroll 4
        for (int it = 0; it < 128; it++) {
            int lin = it * 256 + tid;
            int c = lin >> 11, kv = lin & 2047;
            const float* W = (kv < 1024) ? wx1 : wh1;
            smem[kv * W1S + c] = W[(size_t)(nb + c) * HID + (kv & 1023)];
        }
    }
    __syncthreads();

    const int m = tid & 63;
    const int g = tid >> 6;

    for (int k = 0; k <= SEQ; k++) {
        bool active = is_l1 ? (k >= 1) : (k < SEQ);
        if (active) {
            if (!is_l1) {
                const int ng = g & 1, q = g >> 1;
                ull acc[8] = {};
                const float* A = g_h0T + (size_t)k * BH + (size_t)(q * 512) * 64 + m;
                unsigned wbase = sbase + (unsigned)((q * 512 * W0S + ng * 16) * 4);
                gemm512<W0S>(wbase, A, acc);

                ull* red = (ull*)(smem + W0_WORDS);
                int slot = ng * 64 + m;
                if (q == 1) {
                    #pragma unroll
                    for (int j = 0; j < 8; j++) red[slot * 8 + j] = acc[j];
                }
                __syncthreads();
                if (q == 0) {
                    int n0 = bid * 32 + ng * 16;
                    const float* xr = g_xproj0 + ((size_t)k * BATCH + m) * HID + n0;
                    float4 x0 = *(const float4*)(xr);
                    float4 x1 = *(const float4*)(xr + 4);
                    float4 x2 = *(const float4*)(xr + 8);
                    float4 x3 = *(const float4*)(xr + 12);
                    float xv[16] = {x0.x,x0.y,x0.z,x0.w, x1.x,x1.y,x1.z,x1.w,
                                    x2.x,x2.y,x2.z,x2.w, x3.x,x3.y,x3.z,x3.w};
                    float* outT = g_h0T + (size_t)(k + 1) * BH + (size_t)n0 * 64 + m;
                    #pragma unroll
                    for (int j = 0; j < 8; j++) {
                        float2 p = up2(acc[j]);
                        float2 o = up2(red[slot * 8 + j]);
                        float r0 = tanhf(p.x + o.x + xv[2 * j]);
                        float r1 = tanhf(p.y + o.y + xv[2 * j + 1]);
                        outT[(size_t)(2 * j) * 64]     = r0;
                        outT[(size_t)(2 * j + 1) * 64] = r1;
                    }
                }
            } else {
                const int q = g;
                ull acc[8] = {};
                const float* A = (q < 2)
                    ? g_h0T + (size_t)k * BH + (size_t)(q * 512) * 64 + m
                    : g_h1T + (size_t)(k - 1) * BH + (size_t)((q - 2) * 512) * 64 + m;
                unsigned wbase = sbase + (unsigned)((q * 512 * W1S) * 4);
                gemm512<W1S>(wbase, A, acc);

                ull* red = (ull*)(smem + W1_WORDS);
                if (q > 0) {
                    int slot = (q - 1) * 64 + m;
                    #pragma unroll
                    for (int j = 0; j < 8; j++) red[slot * 8 + j] = acc[j];
                }
                __syncthreads();
                if (q == 0) {
                    int n0 = (bid - NB_L0) * 16;
                    float4 b0 = *(const float4*)(bh1 + n0);
                    float4 b1 = *(const float4*)(bh1 + n0 + 4);
                    float4 b2 = *(const float4*)(bh1 + n0 + 8);
                    float4 b3 = *(const float4*)(bh1 + n0 + 12);
                    float bv[16] = {b0.x,b0.y,b0.z,b0.w, b1.x,b1.y,b1.z,b1.w,
                                    b2.x,b2.y,b2.z,b2.w, b3.x,b3.y,b3.z,b3.w};
                    float res[16];
                    #pragma unroll
                    for (int j = 0; j < 8; j++) {
                        float2 p = up2(acc[j]);
                        float2 r1 = up2(red[(0 * 64 + m) * 8 + j]);
                        float2 r2 = up2(red[(1 * 64 + m) * 8 + j]);
                        float2 r3 = up2(red[(2 * 64 + m) * 8 + j]);
                        res[2 * j]     = tanhf(p.x + r1.x + r2.x + r3.x + bv[2 * j]);
                        res[2 * j + 1] = tanhf(p.y + r1.y + r2.y + r3.y + bv[2 * j + 1]);
                    }
                    float* outT = g_h1T + (size_t)k * BH + (size_t)n0 * 64 + m;
                    #pragma unroll
                    for (int j = 0; j < 16; j++) outT[(size_t)j * 64] = res[j];
                    float* orm = g_h1rm + ((size_t)(k - 1) * BATCH + m) * HID + n0;
                    *(float4*)(orm)      = make_float4(res[0], res[1], res[2], res[3]);
                    *(float4*)(orm + 4)  = make_float4(res[4], res[5], res[6], res[7]);
                    *(float4*)(orm + 8)  = make_float4(res[8], res[9], res[10], res[11]);
                    *(float4*)(orm + 12) = make_float4(res[12], res[13], res[14], res[15]);
                }
            }
        }

        if (k < SEQ) {
            __threadfence();
            __syncthreads();
            if (tid == 0) {
                atomicAdd(&g_bar, 1u);
                unsigned target = (unsigned)(k + 1) * NBLK;
                unsigned v;
                do {
                    asm volatile("ld.global.acquire.gpu.b32 %0, [%1];"
                                 : "=r"(v) : "l"(&g_bar) : "memory");
                } while (v < target);
            }
            __syncthreads();
        }
    }
}

// ---------------- bf16 split conversions -------------------------------------
__global__ __launch_bounds__(256) void convertA_kernel() {
    int i = (blockIdx.x * 256 + threadIdx.x) * 4;
    if (i >= ROWS * HID) return;
    float4 a = *(const float4*)&g_h1rm[i];
    __nv_bfloat16 h0 = __float2bfloat16(a.x), h1 = __float2bfloat16(a.y);
    __nv_bfloat16 h2 = __float2bfloat16(a.z), h3 = __float2bfloat16(a.w);
    ((__nv_bfloat162*)g_Ah)[i / 2]     = __nv_bfloat162(h0, h1);
    ((__nv_bfloat162*)g_Ah)[i / 2 + 1] = __nv_bfloat162(h2, h3);
    __nv_bfloat16 l0 = __float2bfloat16(a.x - __bfloat162float(h0));
    __nv_bfloat16 l1 = __float2bfloat16(a.y - __bfloat162float(h1));
    __nv_bfloat16 l2 = __float2bfloat16(a.z - __bfloat162float(h2));
    __nv_bfloat16 l3 = __float2bfloat16(a.w - __bfloat162float(h3));
    ((__nv_bfloat162*)g_Al)[i / 2]     = __nv_bfloat162(l0, l1);
    ((__nv_bfloat162*)g_Al)[i / 2 + 1] = __nv_bfloat162(l2, l3);
}

__global__ __launch_bounds__(256) void convertB_kernel(const float* __restrict__ vw) {
    int i = (blockIdx.x * 256 + threadIdx.x) * 4;
    if (i >= VOCAB * HID) return;
    float4 a = *(const float4*)&vw[i];
    __nv_bfloat16 h0 = __float2bfloat16(a.x), h1 = __float2bfloat16(a.y);
    __nv_bfloat16 h2 = __float2bfloat16(a.z), h3 = __float2bfloat16(a.w);
    ((__nv_bfloat162*)g_Bh)[i / 2]     = __nv_bfloat162(h0, h1);
    ((__nv_bfloat162*)g_Bh)[i / 2 + 1] = __nv_bfloat162(h2, h3);
    __nv_bfloat16 l0 = __float2bfloat16(a.x - __bfloat162float(h0));
    __nv_bfloat16 l1 = __float2bfloat16(a.y - __bfloat162float(h1));
    __nv_bfloat16 l2 = __float2bfloat16(a.z - __bfloat162float(h2));
    __nv_bfloat16 l3 = __float2bfloat16(a.w - __bfloat162float(h3));
    ((__nv_bfloat162*)g_Bl)[i / 2]     = __nv_bfloat162(l0, l1);
    ((__nv_bfloat162*)g_Bl)[i / 2 + 1] = __nv_bfloat162(l2, l3);
}

// ---------------- logits via mma.sync split-bf16 ------------------------------
// D[128,128] += Ah@Bh^T + Ah@Bl^T + Al@Bh^T, fp32 register accum, 8 warps.
__device__ __forceinline__ void load_stage(unsigned sb, int stage, int kt,
                                           int mbase, int nbase, int tid)
{
    unsigned stoff = sb + (unsigned)stage * STAGE_BYTES;
    const char* gp[4] = {(const char*)g_Ah, (const char*)g_Al,
                         (const char*)g_Bh, (const char*)g_Bl};
    int rb[4] = {mbase, mbase, nbase, nbase};
    #pragma unroll
    for (int op = 0; op < 4; op++) {
        #pragma unroll
        for (int j = 0; j < 4; j++) {
            int chunk = tid + j * 256;          // 0..1023
            int row = chunk >> 3, boff = (chunk & 7) * 16;
            const char* src = gp[op] + ((size_t)rb[op] + row) * (HID * 2)
                            + kt * 128 + boff;
            unsigned dst = stoff + op * OP_BYTES
                         + SMEM_SWIZZLE_128B((unsigned)(row * 128 + boff));
            CP_ASYNC16(dst, src);
        }
    }
}

__global__ __launch_bounds__(256, 1) void logits_mma_kernel(
    const float* __restrict__ vb, float* __restrict__ out)
{
    extern __shared__ char dsm[];
    const int tid  = threadIdx.x;
    const int lane = tid & 31, wid = tid >> 5;
    const int mbase = blockIdx.y * 128;
    const int nbase = blockIdx.x * 128;
    const int warp_m = (wid >> 2) * 64;
    const int warp_n = (wid & 3) * 32;

    const unsigned sb = (smem_u32(dsm) + 1023u) & ~1023u;

    // ldmatrix per-lane address components (SW128-swizzled rows of 128B)
    const unsigned xm  = (unsigned)((lane & 7) << 4);
    const int rowA = (lane & 7) + ((lane >> 3) & 1) * 8;
    const unsigned kbA = (unsigned)((lane >> 4) * 16);
    const int rowB = (lane & 7) + ((lane >> 4) << 3);
    const unsigned kbB = (unsigned)(((lane >> 3) & 1) * 16);

    unsigned aoffA[4], aoffB[2];
    #pragma unroll
    for (int mt = 0; mt < 4; mt++)
        aoffA[mt] = (unsigned)((warp_m + mt * 16 + rowA) * 128);
    #pragma unroll
    for (int nt = 0; nt < 2; nt++)
        aoffB[nt] = (unsigned)((warp_n + nt * 16 + rowB) * 128);

    float acc[4][4][4] = {};

    load_stage(sb, 0, 0, mbase, nbase, tid);
    CP_ASYNC_COMMIT();

    #pragma unroll 1
    for (int kt = 0; kt < NKT; kt++) {
        const int s = kt & 1;
        if (kt + 1 < NKT) {
            load_stage(sb, s ^ 1, kt + 1, mbase, nbase, tid);
            CP_ASYNC_COMMIT();
            CP_ASYNC_WAIT(1);
        } else {
            CP_ASYNC_WAIT(0);
        }
        __syncthreads();

        unsigned st = sb + (unsigned)s * STAGE_BYTES;
        #pragma unroll
        for (int ks = 0; ks < 4; ks++) {
            unsigned kA = ((unsigned)(ks * 32) + kbA) ^ xm;
            unsigned kB = ((unsigned)(ks * 32) + kbB) ^ xm;
            unsigned ah[4][4], al[4][4], bh[2][4], bl[2][4];
            #pragma unroll
            for (int mt = 0; mt < 4; mt++) {
                ldsm4(ah[mt], st + 0 * OP_BYTES + aoffA[mt] + kA);
                ldsm4(al[mt], st + 1 * OP_BYTES + aoffA[mt] + kA);
            }
            #pragma unroll
            for (int nt = 0; nt < 2; nt++) {
                ldsm4(bh[nt], st + 2 * OP_BYTES + aoffB[nt] + kB);
                ldsm4(bl[nt], st + 3 * OP_BYTES + aoffB[nt] + kB);
            }
            #pragma unroll
            for (int mt = 0; mt < 4; mt++) {
                #pragma unroll
                for (int n2 = 0; n2 < 2; n2++) {
                    mma16816(acc[mt][n2 * 2],     ah[mt], bh[n2][0], bh[n2][1]);
                    mma16816(acc[mt][n2 * 2],     al[mt], bh[n2][0], bh[n2][1]);
                    mma16816(acc[mt][n2 * 2],     ah[mt], bl[n2][0], bl[n2][1]);
                    mma16816(acc[mt][n2 * 2 + 1], ah[mt], bh[n2][2], bh[n2][3]);
                    mma16816(acc[mt][n2 * 2 + 1], al[mt], bh[n2][2], bh[n2][3]);
                    mma16816(acc[mt][n2 * 2 + 1], ah[mt], bl[n2][2], bl[n2][3]);
                }
            }
        }
        __syncthreads();
    }

    // ---- epilogue: accum -> smem transpose -> coalesced STG + bias ----
    float* sm = (float*)dsm;                 // 128 x 129 fp32 = 66048 B
    const int r0l = lane >> 2;
    const int c0l = 2 * (lane & 3);
    #pragma unroll
    for (int mt = 0; mt < 4; mt++) {
        #pragma unroll
        for (int nt = 0; nt < 4; nt++) {
            int row = warp_m + mt * 16 + r0l;
            int col = warp_n + nt * 8 + c0l;
            sm[row * 129 + col]           = acc[mt][nt][0];
            sm[row * 129 + col + 1]       = acc[mt][nt][1];
            sm[(row + 8) * 129 + col]     = acc[mt][nt][2];
            sm[(row + 8) * 129 + col + 1] = acc[mt][nt][3];
        }
    }
    __syncthreads();

    const int c4 = tid & 31;
    const int rg = tid >> 5;                 // 0..7
    const int n0 = nbase + c4 * 4;
    float b0 = (n0 + 0 < VOCAB) ? vb[n0 + 0] : 0.f;
    float b1 = (n0 + 1 < VOCAB) ? vb[n0 + 1] : 0.f;
    float b2 = (n0 + 2 < VOCAB) ? vb[n0 + 2] : 0.f;
    float b3 = (n0 + 3 < VOCAB) ? vb[n0 + 3] : 0.f;
    const bool full = (nbase + 128 <= VOCAB);

    #pragma unroll 4
    for (int it = 0; it < 16; it++) {
        int row = it * 8 + rg;
        const float* sr = sm + row * 129 + c4 * 4;
        float4 v = make_float4(sr[0] + b0, sr[1] + b1, sr[2] + b2, sr[3] + b3);
        float* orow = out + (size_t)(mbase + row) * VOCAB;
        if (full) {
            *(float4*)(orow + n0) = v;
        } else {
            if (n0 + 0 < VOCAB) orow[n0 + 0] = v.x;
            if (n0 + 1 < VOCAB) orow[n0 + 1] = v.y;
            if (n0 + 2 < VOCAB) orow[n0 + 2] = v.z;
            if (n0 + 3 < VOCAB) orow[n0 + 3] = v.w;
        }
    }
}

// ---------------- finalize -----------------------------------------------------
__global__ void finalize_kernel(float* __restrict__ out) {
    int i = blockIdx.x * blockDim.x + threadIdx.x;
    if (i < 2 * BH) {
        int l = i >> 16;
        int r = i & (BH - 1);
        int b = r >> 10, n = r & 1023;
        const float* src = l ? g_h1T : g_h0T;
        out[(size_t)ROWS * VOCAB + i] = src[(size_t)SEQ * BH + (size_t)n * 64 + b];
    }
}

// ---------------- launcher ------------------------------------------------------
extern "C" void kernel_launch(void* const* d_in, const int* in_sizes, int n_in,
                              void* d_out, int out_size)
{
    const int*   inputs    = (const int*)  d_in[0];
    const float* hidden    = (const float*)d_in[1];
    const float* embedding = (const float*)d_in[2];
    const float* wx0       = (const float*)d_in[3];
    const float* wh0       = (const float*)d_in[4];
    const float* bh0       = (const float*)d_in[5];
    const float* wx1       = (const float*)d_in[6];
    const float* wh1       = (const float*)d_in[7];
    const float* bh1       = (const float*)d_in[8];
    const float* v_w       = (const float*)d_in[9];
    const float* v_b       = (const float*)d_in[10];
    float* out = (float*)d_out;

    static bool attr_set = false;
    if (!attr_set) {
        cudaFuncSetAttribute(recur_kernel,
                             cudaFuncAttributeMaxDynamicSharedMemorySize,
                             RECUR_SMEM);
        cudaFuncSetAttribute(logits_mma_kernel,
                             cudaFuncAttributeMaxDynamicSharedMemorySize,
                             LOGITS_SMEM);
        attr_set = true;
    }

    init_kernel<<<(BH + 255) / 256, 256>>>(hidden);
    convertB_kernel<<<(VOCAB * HID / 4 + 255) / 256, 256>>>(v_w);
    xproj_kernel<<<dim3(HID / 64, ROWS / 64), 256>>>(inputs, embedding, wx0, bh0);
    recur_kernel<<<NBLK, 256, RECUR_SMEM>>>(wh0, wx1, wh1, bh1);
    convertA_kernel<<<(ROWS * HID / 4 + 255) / 256, 256>>>();
    logits_mma_kernel<<<dim3(VPAD / 128, ROWS / 128), 256, LOGITS_SMEM>>>(v_b, out);

    long long need = (long long)ROWS * VOCAB + 2LL * BH;
    if ((long long)out_size >= need) {
        finalize_kernel<<<(2 * BH + 255) / 256, 256>>>(out);
    }
}

// round 6
// speedup vs baseline: 4.3673x; 1.5023x over previous
#include <cuda_runtime.h>
#include <cuda_bf16.h>
#include <math.h>

// Problem constants
#define EMB   1024
#define HID   1024
#define SEQ   128
#define BATCH 64
#define VOCAB 10000
#define VPAD  10112              // 79 * 128
#define BH    (BATCH * HID)      // 65536
#define ROWS  (SEQ * BATCH)      // 8192

// Persistent recurrence config (HMMA)
#define NB_L0 32                 // layer-0 blocks: 32 n-cols each
#define NB_L1 64                 // layer-1 blocks: 16 n-cols (wx1+wh1)
#define NBLK  (NB_L0 + NB_L1)
#define A_BASE 131072            // smem offset of A stages (after weights)
#define L0_STAGE 16384           // h0 hi+lo chunk (64m x 64k bf16 x2)
#define L1_STAGE 32768           // + h1 hi+lo
#define RECUR_SMEM (131072 + 3 * 32768)   // 229376

// Logits mma.sync config
#define KCH  64
#define NKT  (HID / KCH)
#define OP_BYTES 16384
#define STAGE_BYTES (4 * OP_BYTES)
#define LOGITS_SMEM (2 * STAGE_BYTES + 1024)

typedef unsigned long long ull;

// ---------------- scratch (device globals) ----------------------------------
__device__ float g_xproj0[ROWS * HID];
__device__ unsigned g_bar;
// hidden states as bf16 hi/lo pairs; slot s = state after step s-1 (slot0=init)
__device__ __nv_bfloat16 g_h0h[(SEQ + 1) * BH];
__device__ __nv_bfloat16 g_h0l[(SEQ + 1) * BH];
__device__ __nv_bfloat16 g_h1h[(SEQ + 1) * BH];
__device__ __nv_bfloat16 g_h1l[(SEQ + 1) * BH];
// vocab weights split
__device__ __nv_bfloat16 g_Bh[VPAD * HID];   // rows >= VOCAB stay zero
__device__ __nv_bfloat16 g_Bl[VPAD * HID];

// ---------------- generic helpers -------------------------------------------
__device__ __forceinline__ ull pk2(float x, float y) {
    ull r; asm("mov.b64 %0, {%1, %2};" : "=l"(r) : "f"(x), "f"(y)); return r;
}
__device__ __forceinline__ void fma2(ull& c, ull a, ull b) {
    asm("fma.rn.f32x2 %0, %1, %2, %0;" : "+l"(c) : "l"(a), "l"(b));
}
__device__ __forceinline__ float2 up2(ull v) {
    float2 r; asm("mov.b64 {%0, %1}, %2;" : "=f"(r.x), "=f"(r.y) : "l"(v)); return r;
}
__device__ __forceinline__ unsigned smem_u32(const void* p) {
    unsigned a;
    asm("{ .reg .u64 t; cvta.to.shared.u64 t, %1; cvt.u32.u64 %0, t; }"
        : "=r"(a) : "l"(p));
    return a;
}

#define SMEM_SWIZZLE_128B(o) ((o) ^ (((o) >> 3) & 0x70))

#define CP_ASYNC16(dst, src) \
    asm volatile("cp.async.cg.shared.global [%0], [%1], 16;" \
                 :: "r"(dst), "l"(src))
#define CP_ASYNC_COMMIT() asm volatile("cp.async.commit_group;" ::: "memory")
#define CP_ASYNC_WAIT(n)  asm volatile("cp.async.wait_group %0;" :: "n"(n) : "memory")

__device__ __forceinline__ void ldsm4(unsigned* r, unsigned addr) {
    asm volatile("ldmatrix.sync.aligned.m8n8.x4.shared.b16 {%0,%1,%2,%3}, [%4];"
                 : "=r"(r[0]), "=r"(r[1]), "=r"(r[2]), "=r"(r[3]) : "r"(addr));
}
__device__ __forceinline__ void mma16816(float* c, const unsigned* a,
                                         unsigned b0, unsigned b1) {
    asm volatile(
        "mma.sync.aligned.m16n8k16.row.col.f32.bf16.bf16.f32 "
        "{%0,%1,%2,%3}, {%4,%5,%6,%7}, {%8,%9}, {%0,%1,%2,%3};"
        : "+f"(c[0]), "+f"(c[1]), "+f"(c[2]), "+f"(c[3])
        : "r"(a[0]), "r"(a[1]), "r"(a[2]), "r"(a[3]), "r"(b0), "r"(b1));
}

__device__ __forceinline__ void split_bf16(float v, __nv_bfloat16& h,
                                           __nv_bfloat16& l) {
    h = __float2bfloat16(v);
    l = __float2bfloat16(v - __bfloat162float(h));
}

// ---------------- init: split initial hidden into hi/lo slot 0 ---------------
__global__ void init_kernel(const float* __restrict__ hidden) {
    int i = blockIdx.x * blockDim.x + threadIdx.x;
    if (i == 0) g_bar = 0;
    if (i < BH) {
        __nv_bfloat16 h, l;
        split_bf16(hidden[i], h, l);
        g_h0h[i] = h; g_h0l[i] = l;
        split_bf16(hidden[BH + i], h, l);
        g_h1h[i] = h; g_h1l[i] = l;
    }
}

// ---------------- xproj (fp32 f32x2, unchanged) ------------------------------
__global__ __launch_bounds__(256) void xproj_kernel(
    const int* __restrict__ inp, const float* __restrict__ emb,
    const float* __restrict__ wx0, const float* __restrict__ bh0)
{
    __shared__ int   idx_s[64];
    __shared__ float As[16][68];
    __shared__ float Bs[16][68];

    int tid   = threadIdx.x;
    int rbase = blockIdx.y * 64;
    int nbase = blockIdx.x * 64;

    if (tid < 64) idx_s[tid] = inp[rbase + tid];
    __syncthreads();

    int rl = tid >> 2;
    int kq = (tid & 3) * 4;
    const float* arow = emb + (size_t)idx_s[rl] * EMB + kq;
    const float* brow = wx0 + (size_t)(nbase + rl) * EMB + kq;

    int ty = tid >> 4, tx = tid & 15;
    ull acc[4][2] = {};

    for (int kt = 0; kt < EMB; kt += 16) {
        float4 av = *(const float4*)(arow + kt);
        float4 bv = *(const float4*)(brow + kt);
        As[kq + 0][rl] = av.x; As[kq + 1][rl] = av.y;
        As[kq + 2][rl] = av.z; As[kq + 3][rl] = av.w;
        Bs[kq + 0][rl] = bv.x; Bs[kq + 1][rl] = bv.y;
        Bs[kq + 2][rl] = bv.z; Bs[kq + 3][rl] = bv.w;
        __syncthreads();

        #pragma unroll
        for (int kk = 0; kk < 16; kk++) {
            float4 a4 = *(const float4*)&As[kk][ty * 4];
            float4 b4 = *(const float4*)&Bs[kk][tx * 4];
            ull b01 = pk2(b4.x, b4.y), b23 = pk2(b4.z, b4.w);
            ull a;
            a = pk2(a4.x, a4.x); fma2(acc[0][0], a, b01); fma2(acc[0][1], a, b23);
            a = pk2(a4.y, a4.y); fma2(acc[1][0], a, b01); fma2(acc[1][1], a, b23);
            a = pk2(a4.z, a4.z); fma2(acc[2][0], a, b01); fma2(acc[2][1], a, b23);
            a = pk2(a4.w, a4.w); fma2(acc[3][0], a, b01); fma2(acc[3][1], a, b23);
        }
        __syncthreads();
    }

    int n0 = nbase + tx * 4;
    float4 bb = *(const float4*)(bh0 + n0);
    #pragma unroll
    for (int i = 0; i < 4; i++) {
        int r = rbase + ty * 4 + i;
        float2 p0 = up2(acc[i][0]), p1 = up2(acc[i][1]);
        float4 o = make_float4(p0.x + bb.x, p0.y + bb.y, p1.x + bb.z, p1.y + bb.w);
        *(float4*)&g_xproj0[(size_t)r * HID + n0] = o;
    }
}

// ---------------- recur: chunk loader ----------------------------------------
// Loads one 64m x 64k hi/lo pair into stage (hi at +0, lo at +8192), swizzled.
__device__ __forceinline__ void load_chunk2(unsigned dstbase, const char* h,
                                            const char* l, int c, int tid)
{
    #pragma unroll
    for (int j = 0; j < 2; j++) {
        int seg = tid + j * 256;                    // 0..511
        int row = seg >> 3;
        unsigned b16 = (unsigned)((seg & 7) * 16);
        unsigned off = SMEM_SWIZZLE_128B((unsigned)(row * 128) + b16);
        const char* s1 = h + (size_t)row * 2048 + (size_t)c * 128 + b16;
        const char* s2 = l + (size_t)row * 2048 + (size_t)c * 128 + b16;
        CP_ASYNC16(dstbase + off, s1);
        CP_ASYNC16(dstbase + 8192 + off, s2);
    }
}

// ---------------- recur: layer-0 step (HMMA) ----------------------------------
// D[64m x 32n] = h0[k] @ wh0_slice^T (3 split-bf16 products), +xproj, tanh.
__device__ __forceinline__ void step_l0(char* sm, unsigned sb, int bid, int k,
                                        int tid, int lane, int wid)
{
    const char* a0h = (const char*)(g_h0h + (size_t)k * BH);
    const char* a0l = (const char*)(g_h0l + (size_t)k * BH);
    const int wm = wid >> 1, wn = wid & 1;
    const unsigned xm   = (unsigned)((lane & 7) << 4);
    const unsigned aoffA = (unsigned)((wm * 16 + (lane & 7) + ((lane >> 3) & 1) * 8) * 128);
    const unsigned kbA  = (unsigned)((lane >> 4) * 16);
    const unsigned boffB = (unsigned)((wn * 16 + (lane & 7) + ((lane >> 4) << 3)) * 128);
    const unsigned kbB  = (unsigned)(((lane >> 3) & 1) * 16);

    float acc[2][4] = {};

    #pragma unroll
    for (int p = 0; p < 3; p++) {
        load_chunk2(sb + A_BASE + p * L0_STAGE, a0h, a0l, p, tid);
        CP_ASYNC_COMMIT();
    }

    #pragma unroll 1
    for (int c = 0; c < 16; c++) {
        CP_ASYNC_WAIT(2);
        __syncthreads();
        if (c + 3 < 16) {
            load_chunk2(sb + A_BASE + ((c + 3) & 3) * L0_STAGE, a0h, a0l, c + 3, tid);
            CP_ASYNC_COMMIT();
        }
        unsigned stg = sb + A_BASE + (c & 3) * L0_STAGE;
        unsigned wbh = sb + (unsigned)(c * 4096);
        unsigned wbl = wbh + 65536;
        #pragma unroll
        for (int ks = 0; ks < 4; ks++) {
            unsigned kA = ((unsigned)(ks * 32) + kbA) ^ xm;
            unsigned kB = ((unsigned)(ks * 32) + kbB) ^ xm;
            unsigned ah[4], al[4], bh[4], bl[4];
            ldsm4(ah, stg + aoffA + kA);
            ldsm4(al, stg + 8192 + aoffA + kA);
            ldsm4(bh, wbh + boffB + kB);
            ldsm4(bl, wbl + boffB + kB);
            mma16816(acc[0], ah, bh[0], bh[1]);
            mma16816(acc[0], al, bh[0], bh[1]);
            mma16816(acc[0], ah, bl[0], bl[1]);
            mma16816(acc[1], ah, bh[2], bh[3]);
            mma16816(acc[1], al, bh[2], bh[3]);
            mma16816(acc[1], ah, bl[2], bl[3]);
        }
    }

    // epilogue: + xproj, tanh, split, store slot k+1
    int r = lane >> 2, c0 = 2 * (lane & 3);
    int mrow = wm * 16 + r;
    size_t slot = (size_t)(k + 1) * BH;
    #pragma unroll
    for (int n2 = 0; n2 < 2; n2++) {
        int gn = bid * 32 + wn * 16 + n2 * 8 + c0;
        const float* xp0 = g_xproj0 + ((size_t)k * BATCH + mrow) * HID + gn;
        const float* xp1 = g_xproj0 + ((size_t)k * BATCH + mrow + 8) * HID + gn;
        float2 x0 = *(const float2*)xp0;
        float2 x1 = *(const float2*)xp1;
        float t0 = tanhf(acc[n2][0] + x0.x);
        float t1 = tanhf(acc[n2][1] + x0.y);
        float t2 = tanhf(acc[n2][2] + x1.x);
        float t3 = tanhf(acc[n2][3] + x1.y);
        __nv_bfloat16 h0, l0, h1, l1, h2, l2, h3, l3;
        split_bf16(t0, h0, l0); split_bf16(t1, h1, l1);
        split_bf16(t2, h2, l2); split_bf16(t3, h3, l3);
        size_t o0 = slot + (size_t)mrow * HID + gn;
        size_t o1 = slot + (size_t)(mrow + 8) * HID + gn;
        *(__nv_bfloat162*)(g_h0h + o0) = __nv_bfloat162(h0, h1);
        *(__nv_bfloat162*)(g_h0l + o0) = __nv_bfloat162(l0, l1);
        *(__nv_bfloat162*)(g_h0h + o1) = __nv_bfloat162(h2, h3);
        *(__nv_bfloat162*)(g_h0l + o1) = __nv_bfloat162(l2, l3);
    }
}

// ---------------- recur: layer-1 step (HMMA) ----------------------------------
// D[64m x 16n] = h0[k] @ wx1^T + h1[k-1] @ wh1^T; warps split by kq (matrix).
__device__ __forceinline__ void step_l1(char* sm, unsigned sb, int bid, int k,
                                        int tid, int lane, int wid,
                                        const float* __restrict__ bh1)
{
    const char* a0h = (const char*)(g_h0h + (size_t)k * BH);
    const char* a0l = (const char*)(g_h0l + (size_t)k * BH);
    const char* a1h = (const char*)(g_h1h + (size_t)(k - 1) * BH);
    const char* a1l = (const char*)(g_h1l + (size_t)(k - 1) * BH);
    const int wm = wid >> 1, kq = wid & 1;
    const unsigned xm   = (unsigned)((lane & 7) << 4);
    const unsigned aoffA = (unsigned)((wm * 16 + (lane & 7) + ((lane >> 3) & 1) * 8) * 128);
    const unsigned kbA  = (unsigned)((lane >> 4) * 16);
    const unsigned boffB = (unsigned)(((lane & 7) + ((lane >> 4) << 3)) * 128);
    const unsigned kbB  = (unsigned)(((lane >> 3) & 1) * 16);

    float acc[2][4] = {};

    #pragma unroll
    for (int p = 0; p < 2; p++) {
        unsigned st = sb + A_BASE + p * L1_STAGE;
        load_chunk2(st,         a0h, a0l, p, tid);
        load_chunk2(st + 16384, a1h, a1l, p, tid);
        CP_ASYNC_COMMIT();
    }

    const unsigned aq = (unsigned)(kq * 16384);

    #pragma unroll 1
    for (int c = 0; c < 16; c++) {
        CP_ASYNC_WAIT(1);
        __syncthreads();
        if (c + 2 < 16) {
            int s = (c + 2) % 3;
            unsigned st = sb + A_BASE + s * L1_STAGE;
            load_chunk2(st,         a0h, a0l, c + 2, tid);
            load_chunk2(st + 16384, a1h, a1l, c + 2, tid);
            CP_ASYNC_COMMIT();
        }
        unsigned stg = sb + A_BASE + (c % 3) * L1_STAGE + aq;
        unsigned wbh = sb + (unsigned)(kq * 65536 + c * 2048);
        unsigned wbl = wbh + 32768;
        #pragma unroll
        for (int ks = 0; ks < 4; ks++) {
            unsigned kA = ((unsigned)(ks * 32) + kbA) ^ xm;
            unsigned kB = ((unsigned)(ks * 32) + kbB) ^ xm;
            unsigned ah[4], al[4], bh[4], bl[4];
            ldsm4(ah, stg + aoffA + kA);
            ldsm4(al, stg + 8192 + aoffA + kA);
            ldsm4(bh, wbh + boffB + kB);
            ldsm4(bl, wbl + boffB + kB);
            mma16816(acc[0], ah, bh[0], bh[1]);
            mma16816(acc[0], al, bh[0], bh[1]);
            mma16816(acc[0], ah, bl[0], bl[1]);
            mma16816(acc[1], ah, bh[2], bh[3]);
            mma16816(acc[1], al, bh[2], bh[3]);
            mma16816(acc[1], ah, bl[2], bl[3]);
        }
    }

    // reduce kq pairs via smem (stage-1 region is free: last read at c=13)
    float* red = (float*)(sm + A_BASE + L1_STAGE);
    int r = lane >> 2, c0 = 2 * (lane & 3);
    int mrow = wm * 16 + r;
    if (kq == 1) {
        #pragma unroll
        for (int n2 = 0; n2 < 2; n2++) {
            int col = n2 * 8 + c0;
            *(float2*)&red[mrow * 16 + col]       = make_float2(acc[n2][0], acc[n2][1]);
            *(float2*)&red[(mrow + 8) * 16 + col] = make_float2(acc[n2][2], acc[n2][3]);
        }
    }
    __syncthreads();
    if (kq == 0) {
        size_t slot = (size_t)k * BH;
        int gnb = (bid - NB_L0) * 16;
        #pragma unroll
        for (int n2 = 0; n2 < 2; n2++) {
            int col = n2 * 8 + c0;
            int gn = gnb + col;
            float2 r0 = *(const float2*)&red[mrow * 16 + col];
            float2 r1 = *(const float2*)&red[(mrow + 8) * 16 + col];
            float2 bv = *(const float2*)(bh1 + gn);
            float t0 = tanhf(acc[n2][0] + r0.x + bv.x);
            float t1 = tanhf(acc[n2][1] + r0.y + bv.y);
            float t2 = tanhf(acc[n2][2] + r1.x + bv.x);
            float t3 = tanhf(acc[n2][3] + r1.y + bv.y);
            __nv_bfloat16 h0, l0, h1, l1, h2, l2, h3, l3;
            split_bf16(t0, h0, l0); split_bf16(t1, h1, l1);
            split_bf16(t2, h2, l2); split_bf16(t3, h3, l3);
            size_t o0 = slot + (size_t)mrow * HID + gn;
            size_t o1 = slot + (size_t)(mrow + 8) * HID + gn;
            *(__nv_bfloat162*)(g_h1h + o0) = __nv_bfloat162(h0, h1);
            *(__nv_bfloat162*)(g_h1l + o0) = __nv_bfloat162(l0, l1);
            *(__nv_bfloat162*)(g_h1h + o1) = __nv_bfloat162(h2, h3);
            *(__nv_bfloat162*)(g_h1l + o1) = __nv_bfloat162(l2, l3);
        }
    }
}

// ---------------- persistent recurrence (HMMA, weights smem-resident) --------
__global__ __launch_bounds__(256, 1) void recur_kernel(
    const float* __restrict__ wh0, const float* __restrict__ wx1,
    const float* __restrict__ wh1, const float* __restrict__ bh1)
{
    extern __shared__ char sm[];
    const int tid = threadIdx.x;
    const int lane = tid & 31, wid = tid >> 5;
    const int bid = blockIdx.x;
    const bool is_l1 = (bid >= NB_L0);
    const unsigned sb = smem_u32(sm);

    // ---- one-time weight preload: split bf16 into swizzled 64k-chunks ----
    if (!is_l1) {
        int nb = bid * 32;
        #pragma unroll 4
        for (int it = 0; it < 128; it++) {
            int idx = it * 256 + tid;               // n*1024 + k
            int n = idx >> 10, kk = idx & 1023;
            float w = wh0[(size_t)(nb + n) * HID + kk];
            __nv_bfloat16 h, l; split_bf16(w, h, l);
            int c = kk >> 6;
            unsigned off = SMEM_SWIZZLE_128B((unsigned)(n * 128 + (kk & 63) * 2));
            *(__nv_bfloat16*)(sm + c * 4096 + off) = h;
            *(__nv_bfloat16*)(sm + 65536 + c * 4096 + off) = l;
        }
    } else {
        int nb = (bid - NB_L0) * 16;
        #pragma unroll 4
        for (int it = 0; it < 128; it++) {
            int idx = it * 256 + tid;               // mat*16384 + n*1024 + k
            int mat = idx >> 14;
            int rr = idx & 16383;
            int n = rr >> 10, kk = rr & 1023;
            const float* W = mat ? wh1 : wx1;
            float w = W[(size_t)(nb + n) * HID + kk];
            __nv_bfloat16 h, l; split_bf16(w, h, l);
            int c = kk >> 6;
            unsigned off = SMEM_SWIZZLE_128B((unsigned)(n * 128 + (kk & 63) * 2));
            char* base = sm + mat * 65536;
            *(__nv_bfloat16*)(base + c * 2048 + off) = h;
            *(__nv_bfloat16*)(base + 32768 + c * 2048 + off) = l;
        }
    }
    __syncthreads();

    for (int k = 0; k <= SEQ; k++) {
        bool active = is_l1 ? (k >= 1) : (k < SEQ);
        if (active) {
            if (!is_l1) step_l0(sm, sb, bid, k, tid, lane, wid);
            else        step_l1(sm, sb, bid, k, tid, lane, wid, bh1);
        }

        if (k < SEQ) {
            __threadfence();
            __syncthreads();
            if (tid == 0) {
                atomicAdd(&g_bar, 1u);
                unsigned target = (unsigned)(k + 1) * NBLK;
                unsigned v;
                do {
                    asm volatile("ld.global.acquire.gpu.b32 %0, [%1];"
                                 : "=r"(v) : "l"(&g_bar) : "memory");
                } while (v < target);
            }
            __syncthreads();
        }
    }
}

// ---------------- bf16 split conversion for vocab weights --------------------
__global__ __launch_bounds__(256) void convertB_kernel(const float* __restrict__ vw) {
    int i = (blockIdx.x * 256 + threadIdx.x) * 4;
    if (i >= VOCAB * HID) return;
    float4 a = *(const float4*)&vw[i];
    __nv_bfloat16 h0, l0, h1, l1, h2, l2, h3, l3;
    split_bf16(a.x, h0, l0); split_bf16(a.y, h1, l1);
    split_bf16(a.z, h2, l2); split_bf16(a.w, h3, l3);
    ((__nv_bfloat162*)g_Bh)[i / 2]     = __nv_bfloat162(h0, h1);
    ((__nv_bfloat162*)g_Bh)[i / 2 + 1] = __nv_bfloat162(h2, h3);
    ((__nv_bfloat162*)g_Bl)[i / 2]     = __nv_bfloat162(l0, l1);
    ((__nv_bfloat162*)g_Bl)[i / 2 + 1] = __nv_bfloat162(l2, l3);
}

// ---------------- logits via mma.sync split-bf16 (A = g_h1 slots 1..128) -----
__device__ __forceinline__ void load_stage(unsigned sb, int stage, int kt,
                                           int mbase, int nbase, int tid)
{
    unsigned stoff = sb + (unsigned)stage * STAGE_BYTES;
    const char* gp[4] = {(const char*)(g_h1h + BH), (const char*)(g_h1l + BH),
                         (const char*)g_Bh, (const char*)g_Bl};
    int rb[4] = {mbase, mbase, nbase, nbase};
    #pragma unroll
    for (int op = 0; op < 4; op++) {
        #pragma unroll
        for (int j = 0; j < 4; j++) {
            int chunk = tid + j * 256;
            int row = chunk >> 3, boff = (chunk & 7) * 16;
            const char* src = gp[op] + ((size_t)rb[op] + row) * (HID * 2)
                            + kt * 128 + boff;
            unsigned dst = stoff + op * OP_BYTES
                         + SMEM_SWIZZLE_128B((unsigned)(row * 128 + boff));
            CP_ASYNC16(dst, src);
        }
    }
}

__global__ __launch_bounds__(256, 1) void logits_mma_kernel(
    const float* __restrict__ vb, float* __restrict__ out)
{
    extern __shared__ char dsm[];
    const int tid  = threadIdx.x;
    const int lane = tid & 31, wid = tid >> 5;
    const int mbase = blockIdx.y * 128;
    const int nbase = blockIdx.x * 128;
    const int warp_m = (wid >> 2) * 64;
    const int warp_n = (wid & 3) * 32;

    const unsigned sb = (smem_u32(dsm) + 1023u) & ~1023u;

    const unsigned xm  = (unsigned)((lane & 7) << 4);
    const int rowA = (lane & 7) + ((lane >> 3) & 1) * 8;
    const unsigned kbA = (unsigned)((lane >> 4) * 16);
    const int rowB = (lane & 7) + ((lane >> 4) << 3);
    const unsigned kbB = (unsigned)(((lane >> 3) & 1) * 16);

    unsigned aoffA[4], aoffB[2];
    #pragma unroll
    for (int mt = 0; mt < 4; mt++)
        aoffA[mt] = (unsigned)((warp_m + mt * 16 + rowA) * 128);
    #pragma unroll
    for (int nt = 0; nt < 2; nt++)
        aoffB[nt] = (unsigned)((warp_n + nt * 16 + rowB) * 128);

    float acc[4][4][4] = {};

    load_stage(sb, 0, 0, mbase, nbase, tid);
    CP_ASYNC_COMMIT();

    #pragma unroll 1
    for (int kt = 0; kt < NKT; kt++) {
        const int s = kt & 1;
        if (kt + 1 < NKT) {
            load_stage(sb, s ^ 1, kt + 1, mbase, nbase, tid);
            CP_ASYNC_COMMIT();
            CP_ASYNC_WAIT(1);
        } else {
            CP_ASYNC_WAIT(0);
        }
        __syncthreads();

        unsigned st = sb + (unsigned)s * STAGE_BYTES;
        #pragma unroll
        for (int ks = 0; ks < 4; ks++) {
            unsigned kA = ((unsigned)(ks * 32) + kbA) ^ xm;
            unsigned kB = ((unsigned)(ks * 32) + kbB) ^ xm;
            unsigned ah[4][4], al[4][4], bh[2][4], bl[2][4];
            #pragma unroll
            for (int mt = 0; mt < 4; mt++) {
                ldsm4(ah[mt], st + 0 * OP_BYTES + aoffA[mt] + kA);
                ldsm4(al[mt], st + 1 * OP_BYTES + aoffA[mt] + kA);
            }
            #pragma unroll
            for (int nt = 0; nt < 2; nt++) {
                ldsm4(bh[nt], st + 2 * OP_BYTES + aoffB[nt] + kB);
                ldsm4(bl[nt], st + 3 * OP_BYTES + aoffB[nt] + kB);
            }
            #pragma unroll
            for (int mt = 0; mt < 4; mt++) {
                #pragma unroll
                for (int n2 = 0; n2 < 2; n2++) {
                    mma16816(acc[mt][n2 * 2],     ah[mt], bh[n2][0], bh[n2][1]);
                    mma16816(acc[mt][n2 * 2],     al[mt], bh[n2][0], bh[n2][1]);
                    mma16816(acc[mt][n2 * 2],     ah[mt], bl[n2][0], bl[n2][1]);
                    mma16816(acc[mt][n2 * 2 + 1], ah[mt], bh[n2][2], bh[n2][3]);
                    mma16816(acc[mt][n2 * 2 + 1], al[mt], bh[n2][2], bh[n2][3]);
                    mma16816(acc[mt][n2 * 2 + 1], ah[mt], bl[n2][2], bl[n2][3]);
                }
            }
        }
        __syncthreads();
    }

    // epilogue: accum -> smem transpose -> coalesced STG + bias
    float* sm = (float*)dsm;
    const int r0l = lane >> 2;
    const int c0l = 2 * (lane & 3);
    #pragma unroll
    for (int mt = 0; mt < 4; mt++) {
        #pragma unroll
        for (int nt = 0; nt < 4; nt++) {
            int row = warp_m + mt * 16 + r0l;
            int col = warp_n + nt * 8 + c0l;
            sm[row * 129 + col]           = acc[mt][nt][0];
            sm[row * 129 + col + 1]       = acc[mt][nt][1];
            sm[(row + 8) * 129 + col]     = acc[mt][nt][2];
            sm[(row + 8) * 129 + col + 1] = acc[mt][nt][3];
        }
    }
    __syncthreads();

    const int c4 = tid & 31;
    const int rg = tid >> 5;
    const int n0 = nbase + c4 * 4;
    float b0 = (n0 + 0 < VOCAB) ? vb[n0 + 0] : 0.f;
    float b1 = (n0 + 1 < VOCAB) ? vb[n0 + 1] : 0.f;
    float b2 = (n0 + 2 < VOCAB) ? vb[n0 + 2] : 0.f;
    float b3 = (n0 + 3 < VOCAB) ? vb[n0 + 3] : 0.f;
    const bool full = (nbase + 128 <= VOCAB);

    #pragma unroll 4
    for (int it = 0; it < 16; it++) {
        int row = it * 8 + rg;
        const float* sr = sm + row * 129 + c4 * 4;
        float4 v = make_float4(sr[0] + b0, sr[1] + b1, sr[2] + b2, sr[3] + b3);
        float* orow = out + (size_t)(mbase + row) * VOCAB;
        if (full) {
            *(float4*)(orow + n0) = v;
        } else {
            if (n0 + 0 < VOCAB) orow[n0 + 0] = v.x;
            if (n0 + 1 < VOCAB) orow[n0 + 1] = v.y;
            if (n0 + 2 < VOCAB) orow[n0 + 2] = v.z;
            if (n0 + 3 < VOCAB) orow[n0 + 3] = v.w;
        }
    }
}

// ---------------- finalize: hidden_final = hi + lo at slot SEQ ----------------
__global__ void finalize_kernel(float* __restrict__ out) {
    int i = blockIdx.x * blockDim.x + threadIdx.x;
    if (i < 2 * BH) {
        int l = i >> 16;                 // BH = 65536
        int r = i & (BH - 1);
        const __nv_bfloat16* hs = l ? g_h1h : g_h0h;
        const __nv_bfloat16* ls = l ? g_h1l : g_h0l;
        out[(size_t)ROWS * VOCAB + i] =
            __bfloat162float(hs[(size_t)SEQ * BH + r]) +
            __bfloat162float(ls[(size_t)SEQ * BH + r]);
    }
}

// ---------------- launcher ------------------------------------------------------
extern "C" void kernel_launch(void* const* d_in, const int* in_sizes, int n_in,
                              void* d_out, int out_size)
{
    const int*   inputs    = (const int*)  d_in[0];
    const float* hidden    = (const float*)d_in[1];
    const float* embedding = (const float*)d_in[2];
    const float* wx0       = (const float*)d_in[3];
    const float* wh0       = (const float*)d_in[4];
    const float* bh0       = (const float*)d_in[5];
    const float* wx1       = (const float*)d_in[6];
    const float* wh1       = (const float*)d_in[7];
    const float* bh1       = (const float*)d_in[8];
    const float* v_w       = (const float*)d_in[9];
    const float* v_b       = (const float*)d_in[10];
    float* out = (float*)d_out;

    static bool attr_set = false;
    if (!attr_set) {
        cudaFuncSetAttribute(recur_kernel,
                             cudaFuncAttributeMaxDynamicSharedMemorySize,
                             RECUR_SMEM);
        cudaFuncSetAttribute(logits_mma_kernel,
                             cudaFuncAttributeMaxDynamicSharedMemorySize,
                             LOGITS_SMEM);
        attr_set = true;
    }

    init_kernel<<<(BH + 255) / 256, 256>>>(hidden);
    convertB_kernel<<<(VOCAB * HID / 4 + 255) / 256, 256>>>(v_w);
    xproj_kernel<<<dim3(HID / 64, ROWS / 64), 256>>>(inputs, embedding, wx0, bh0);
    recur_kernel<<<NBLK, 256, RECUR_SMEM>>>(wh0, wx1, wh1, bh1);
    logits_mma_kernel<<<dim3(VPAD / 128, ROWS / 128), 256, LOGITS_SMEM>>>(v_b, out);

    long long need = (long long)ROWS * VOCAB + 2LL * BH;
    if ((long long)out_size >= need) {
        finalize_kernel<<<(2 * BH + 255) / 256, 256>>>(out);
    }
}

// round 7
// speedup vs baseline: 4.9745x; 1.1390x over previous
#include <cuda_runtime.h>
#include <cuda_bf16.h>
#include <math.h>

// Problem constants
#define EMB   1024
#define HID   1024
#define SEQ   128
#define BATCH 64
#define VOCAB 10000
#define VPAD  10112              // 79 * 128
#define BH    (BATCH * HID)      // 65536
#define ROWS  (SEQ * BATCH)      // 8192

// Persistent recurrence config (HMMA, 512 threads: 8 compute + 8 loader warps)
#define NB_L0 32                 // layer-0 blocks: 32 n-cols each
#define NB_L1 64                 // layer-1 blocks: 16 n-cols (wx1+wh1)
#define NBLK  (NB_L0 + NB_L1)
#define A_BASE 131072            // smem offset of A stages (after weights)
#define L0_STAGE 16384           // h0 hi+lo chunk (64m x 64k bf16 x2)
#define L1_STAGE 32768           // + h1 hi+lo
#define RECUR_SMEM (131072 + 3 * 32768)   // 229376

// GEMM (logits / xproj) mma.sync config
#define KCH  64
#define NKT  (HID / KCH)
#define OP_BYTES 16384
#define STAGE_BYTES (4 * OP_BYTES)
#define LOGITS_SMEM (2 * STAGE_BYTES + 1024)

typedef unsigned long long ull;

// ---------------- scratch (device globals) ----------------------------------
__device__ float g_xproj0[ROWS * HID];
__device__ unsigned g_bar;
// hidden states as bf16 hi/lo pairs; slot s = state after step s-1 (slot0=init)
__device__ __nv_bfloat16 g_h0h[(SEQ + 1) * BH];
__device__ __nv_bfloat16 g_h0l[(SEQ + 1) * BH];
__device__ __nv_bfloat16 g_h1h[(SEQ + 1) * BH];
__device__ __nv_bfloat16 g_h1l[(SEQ + 1) * BH];
// split weights
__device__ __nv_bfloat16 g_Bh[VPAD * HID];   // v_w; rows >= VOCAB stay zero
__device__ __nv_bfloat16 g_Bl[VPAD * HID];
__device__ __nv_bfloat16 g_Eh[VOCAB * HID];  // embedding
__device__ __nv_bfloat16 g_El[VOCAB * HID];
__device__ __nv_bfloat16 g_Wh[HID * HID];    // wx0
__device__ __nv_bfloat16 g_Wl[HID * HID];

// ---------------- generic helpers -------------------------------------------
__device__ __forceinline__ unsigned smem_u32(const void* p) {
    unsigned a;
    asm("{ .reg .u64 t; cvta.to.shared.u64 t, %1; cvt.u32.u64 %0, t; }"
        : "=r"(a) : "l"(p));
    return a;
}

#define SMEM_SWIZZLE_128B(o) ((o) ^ (((o) >> 3) & 0x70))

#define CP_ASYNC16(dst, src) \
    asm volatile("cp.async.cg.shared.global [%0], [%1], 16;" \
                 :: "r"(dst), "l"(src))
#define CP_ASYNC_COMMIT() asm volatile("cp.async.commit_group;" ::: "memory")
#define CP_ASYNC_WAIT(n)  asm volatile("cp.async.wait_group %0;" :: "n"(n) : "memory")

__device__ __forceinline__ void ldsm4(unsigned* r, unsigned addr) {
    asm volatile("ldmatrix.sync.aligned.m8n8.x4.shared.b16 {%0,%1,%2,%3}, [%4];"
                 : "=r"(r[0]), "=r"(r[1]), "=r"(r[2]), "=r"(r[3]) : "r"(addr));
}
__device__ __forceinline__ void mma16816(float* c, const unsigned* a,
                                         unsigned b0, unsigned b1) {
    asm volatile(
        "mma.sync.aligned.m16n8k16.row.col.f32.bf16.bf16.f32 "
        "{%0,%1,%2,%3}, {%4,%5,%6,%7}, {%8,%9}, {%0,%1,%2,%3};"
        : "+f"(c[0]), "+f"(c[1]), "+f"(c[2]), "+f"(c[3])
        : "r"(a[0]), "r"(a[1]), "r"(a[2]), "r"(a[3]), "r"(b0), "r"(b1));
}

__device__ __forceinline__ void split_bf16(float v, __nv_bfloat16& h,
                                           __nv_bfloat16& l) {
    h = __float2bfloat16(v);
    l = __float2bfloat16(v - __bfloat162float(h));
}

// ---------------- init: split initial hidden into hi/lo slot 0 ---------------
__global__ void init_kernel(const float* __restrict__ hidden) {
    int i = blockIdx.x * blockDim.x + threadIdx.x;
    if (i == 0) g_bar = 0;
    if (i < BH) {
        __nv_bfloat16 h, l;
        split_bf16(hidden[i], h, l);
        g_h0h[i] = h; g_h0l[i] = l;
        split_bf16(hidden[BH + i], h, l);
        g_h1h[i] = h; g_h1l[i] = l;
    }
}

// ---------------- generic fp32 -> bf16 hi/lo split ----------------------------
__global__ __launch_bounds__(256) void convert_split_kernel(
    const float* __restrict__ src, __nv_bfloat16* __restrict__ dh,
    __nv_bfloat16* __restrict__ dl, int n4)
{
    int i = blockIdx.x * 256 + threadIdx.x;
    if (i >= n4) return;
    float4 a = ((const float4*)src)[i];
    __nv_bfloat16 h0, l0, h1, l1, h2, l2, h3, l3;
    split_bf16(a.x, h0, l0); split_bf16(a.y, h1, l1);
    split_bf16(a.z, h2, l2); split_bf16(a.w, h3, l3);
    ((__nv_bfloat162*)dh)[i * 2]     = __nv_bfloat162(h0, h1);
    ((__nv_bfloat162*)dh)[i * 2 + 1] = __nv_bfloat162(h2, h3);
    ((__nv_bfloat162*)dl)[i * 2]     = __nv_bfloat162(l0, l1);
    ((__nv_bfloat162*)dl)[i * 2 + 1] = __nv_bfloat162(l2, l3);
}

// ---------------- recur: chunk loader (256 loader threads) --------------------
__device__ __forceinline__ void load_chunk2(unsigned dstbase, const char* h,
                                            const char* l, int c, int lt)
{
    #pragma unroll
    for (int j = 0; j < 2; j++) {
        int seg = lt + j * 256;                     // 0..511
        int row = seg >> 3;
        unsigned b16 = (unsigned)((seg & 7) * 16);
        unsigned off = SMEM_SWIZZLE_128B((unsigned)(row * 128) + b16);
        const char* s1 = h + (size_t)row * 2048 + (size_t)c * 128 + b16;
        const char* s2 = l + (size_t)row * 2048 + (size_t)c * 128 + b16;
        CP_ASYNC16(dstbase + off, s1);
        CP_ASYNC16(dstbase + 8192 + off, s2);
    }
}

// ---------------- recur: layer-0 step (warp-specialized) ----------------------
__device__ __forceinline__ void step_l0(char* sm, unsigned sb, int bid, int k,
                                        int tid, int lane, int wid, bool ldr)
{
    const char* a0h = (const char*)(g_h0h + (size_t)k * BH);
    const char* a0l = (const char*)(g_h0l + (size_t)k * BH);
    const int lt = tid & 255;
    const int wm = wid >> 1, wn = wid & 1;
    const unsigned xm   = (unsigned)((lane & 7) << 4);
    const unsigned aoffA = (unsigned)((wm * 16 + (lane & 7) + ((lane >> 3) & 1) * 8) * 128);
    const unsigned kbA  = (unsigned)((lane >> 4) * 16);
    const unsigned boffB = (unsigned)((wn * 16 + (lane & 7) + ((lane >> 4) << 3)) * 128);
    const unsigned kbB  = (unsigned)(((lane >> 3) & 1) * 16);

    float acc[2][4] = {};

    if (ldr) {
        #pragma unroll
        for (int p = 0; p < 3; p++) {
            load_chunk2(sb + A_BASE + p * L0_STAGE, a0h, a0l, p, lt);
            CP_ASYNC_COMMIT();
        }
    }

    #pragma unroll 1
    for (int c = 0; c < 16; c++) {
        if (ldr) CP_ASYNC_WAIT(2);
        __syncthreads();
        if (ldr) {
            if (c + 3 < 16) {
                load_chunk2(sb + A_BASE + ((c + 3) & 3) * L0_STAGE, a0h, a0l,
                            c + 3, lt);
                CP_ASYNC_COMMIT();
            }
        } else {
            unsigned stg = sb + A_BASE + (c & 3) * L0_STAGE;
            unsigned wbh = sb + (unsigned)(c * 4096);
            unsigned wbl = wbh + 65536;
            #pragma unroll
            for (int ks = 0; ks < 4; ks++) {
                unsigned kA = ((unsigned)(ks * 32) + kbA) ^ xm;
                unsigned kB = ((unsigned)(ks * 32) + kbB) ^ xm;
                unsigned ah[4], al[4], bh[4], bl[4];
                ldsm4(ah, stg + aoffA + kA);
                ldsm4(al, stg + 8192 + aoffA + kA);
                ldsm4(bh, wbh + boffB + kB);
                ldsm4(bl, wbl + boffB + kB);
                mma16816(acc[0], ah, bh[0], bh[1]);
                mma16816(acc[0], al, bh[0], bh[1]);
                mma16816(acc[0], ah, bl[0], bl[1]);
                mma16816(acc[1], ah, bh[2], bh[3]);
                mma16816(acc[1], al, bh[2], bh[3]);
                mma16816(acc[1], ah, bl[2], bl[3]);
            }
        }
    }

    if (!ldr) {
        // epilogue: + xproj, tanh, split, store slot k+1
        int r = lane >> 2, c0 = 2 * (lane & 3);
        int mrow = wm * 16 + r;
        size_t slot = (size_t)(k + 1) * BH;
        #pragma unroll
        for (int n2 = 0; n2 < 2; n2++) {
            int gn = bid * 32 + wn * 16 + n2 * 8 + c0;
            const float* xp0 = g_xproj0 + ((size_t)k * BATCH + mrow) * HID + gn;
            const float* xp1 = g_xproj0 + ((size_t)k * BATCH + mrow + 8) * HID + gn;
            float2 x0 = *(const float2*)xp0;
            float2 x1 = *(const float2*)xp1;
            float t0 = tanhf(acc[n2][0] + x0.x);
            float t1 = tanhf(acc[n2][1] + x0.y);
            float t2 = tanhf(acc[n2][2] + x1.x);
            float t3 = tanhf(acc[n2][3] + x1.y);
            __nv_bfloat16 h0, l0, h1, l1, h2, l2, h3, l3;
            split_bf16(t0, h0, l0); split_bf16(t1, h1, l1);
            split_bf16(t2, h2, l2); split_bf16(t3, h3, l3);
            size_t o0 = slot + (size_t)mrow * HID + gn;
            size_t o1 = slot + (size_t)(mrow + 8) * HID + gn;
            *(__nv_bfloat162*)(g_h0h + o0) = __nv_bfloat162(h0, h1);
            *(__nv_bfloat162*)(g_h0l + o0) = __nv_bfloat162(l0, l1);
            *(__nv_bfloat162*)(g_h0h + o1) = __nv_bfloat162(h2, h3);
            *(__nv_bfloat162*)(g_h0l + o1) = __nv_bfloat162(l2, l3);
        }
    }
}

// ---------------- recur: layer-1 step (warp-specialized) ----------------------
__device__ __forceinline__ void step_l1(char* sm, unsigned sb, int bid, int k,
                                        int tid, int lane, int wid, bool ldr,
                                        const float* __restrict__ bh1)
{
    const char* a0h = (const char*)(g_h0h + (size_t)k * BH);
    const char* a0l = (const char*)(g_h0l + (size_t)k * BH);
    const char* a1h = (const char*)(g_h1h + (size_t)(k - 1) * BH);
    const char* a1l = (const char*)(g_h1l + (size_t)(k - 1) * BH);
    const int lt = tid & 255;
    const int wm = wid >> 1, kq = wid & 1;
    const unsigned xm   = (unsigned)((lane & 7) << 4);
    const unsigned aoffA = (unsigned)((wm * 16 + (lane & 7) + ((lane >> 3) & 1) * 8) * 128);
    const unsigned kbA  = (unsigned)((lane >> 4) * 16);
    const unsigned boffB = (unsigned)(((lane & 7) + ((lane >> 4) << 3)) * 128);
    const unsigned kbB  = (unsigned)(((lane >> 3) & 1) * 16);

    float acc[2][4] = {};

    if (ldr) {
        #pragma unroll
        for (int p = 0; p < 2; p++) {
            unsigned st = sb + A_BASE + p * L1_STAGE;
            load_chunk2(st,         a0h, a0l, p, lt);
            load_chunk2(st + 16384, a1h, a1l, p, lt);
            CP_ASYNC_COMMIT();
        }
    }

    const unsigned aq = (unsigned)(kq * 16384);

    #pragma unroll 1
    for (int c = 0; c < 16; c++) {
        if (ldr) CP_ASYNC_WAIT(1);
        __syncthreads();
        if (ldr) {
            if (c + 2 < 16) {
                int s = (c + 2) % 3;
                unsigned st = sb + A_BASE + s * L1_STAGE;
                load_chunk2(st,         a0h, a0l, c + 2, lt);
                load_chunk2(st + 16384, a1h, a1l, c + 2, lt);
                CP_ASYNC_COMMIT();
            }
        } else {
            unsigned stg = sb + A_BASE + (c % 3) * L1_STAGE + aq;
            unsigned wbh = sb + (unsigned)(kq * 65536 + c * 2048);
            unsigned wbl = wbh + 32768;
            #pragma unroll
            for (int ks = 0; ks < 4; ks++) {
                unsigned kA = ((unsigned)(ks * 32) + kbA) ^ xm;
                unsigned kB = ((unsigned)(ks * 32) + kbB) ^ xm;
                unsigned ah[4], al[4], bh[4], bl[4];
                ldsm4(ah, stg + aoffA + kA);
                ldsm4(al, stg + 8192 + aoffA + kA);
                ldsm4(bh, wbh + boffB + kB);
                ldsm4(bl, wbl + boffB + kB);
                mma16816(acc[0], ah, bh[0], bh[1]);
                mma16816(acc[0], al, bh[0], bh[1]);
                mma16816(acc[0], ah, bl[0], bl[1]);
                mma16816(acc[1], ah, bh[2], bh[3]);
                mma16816(acc[1], al, bh[2], bh[3]);
                mma16816(acc[1], ah, bl[2], bl[3]);
            }
        }
    }

    // reduce kq pairs via smem (stage-1 region free after loop)
    float* red = (float*)(sm + A_BASE + L1_STAGE);
    int r = lane >> 2, c0 = 2 * (lane & 3);
    int mrow = wm * 16 + r;
    if (!ldr && kq == 1) {
        #pragma unroll
        for (int n2 = 0; n2 < 2; n2++) {
            int col = n2 * 8 + c0;
            *(float2*)&red[mrow * 16 + col]       = make_float2(acc[n2][0], acc[n2][1]);
            *(float2*)&red[(mrow + 8) * 16 + col] = make_float2(acc[n2][2], acc[n2][3]);
        }
    }
    __syncthreads();
    if (!ldr && kq == 0) {
        size_t slot = (size_t)k * BH;
        int gnb = (bid - NB_L0) * 16;
        #pragma unroll
        for (int n2 = 0; n2 < 2; n2++) {
            int col = n2 * 8 + c0;
            int gn = gnb + col;
            float2 r0 = *(const float2*)&red[mrow * 16 + col];
            float2 r1 = *(const float2*)&red[(mrow + 8) * 16 + col];
            float2 bv = *(const float2*)(bh1 + gn);
            float t0 = tanhf(acc[n2][0] + r0.x + bv.x);
            float t1 = tanhf(acc[n2][1] + r0.y + bv.y);
            float t2 = tanhf(acc[n2][2] + r1.x + bv.x);
            float t3 = tanhf(acc[n2][3] + r1.y + bv.y);
            __nv_bfloat16 h0, l0, h1, l1, h2, l2, h3, l3;
            split_bf16(t0, h0, l0); split_bf16(t1, h1, l1);
            split_bf16(t2, h2, l2); split_bf16(t3, h3, l3);
            size_t o0 = slot + (size_t)mrow * HID + gn;
            size_t o1 = slot + (size_t)(mrow + 8) * HID + gn;
            *(__nv_bfloat162*)(g_h1h + o0) = __nv_bfloat162(h0, h1);
            *(__nv_bfloat162*)(g_h1l + o0) = __nv_bfloat162(l0, l1);
            *(__nv_bfloat162*)(g_h1h + o1) = __nv_bfloat162(h2, h3);
            *(__nv_bfloat162*)(g_h1l + o1) = __nv_bfloat162(l2, l3);
        }
    }
}

// ---------------- persistent recurrence (512 threads) -------------------------
__global__ __launch_bounds__(512, 1) void recur_kernel(
    const float* __restrict__ wh0, const float* __restrict__ wx1,
    const float* __restrict__ wh1, const float* __restrict__ bh1)
{
    extern __shared__ char sm[];
    const int tid = threadIdx.x;
    const int lane = tid & 31, wid = tid >> 5;
    const bool ldr = (wid >= 8);
    const int bid = blockIdx.x;
    const bool is_l1 = (bid >= NB_L0);
    const unsigned sb = smem_u32(sm);

    // ---- one-time weight preload: split bf16 into swizzled 64k-chunks ----
    if (!is_l1) {
        int nb = bid * 32;
        #pragma unroll 4
        for (int it = 0; it < 64; it++) {
            int idx = it * 512 + tid;               // n*1024 + k
            int n = idx >> 10, kk = idx & 1023;
            float w = wh0[(size_t)(nb + n) * HID + kk];
            __nv_bfloat16 h, l; split_bf16(w, h, l);
            int c = kk >> 6;
            unsigned off = SMEM_SWIZZLE_128B((unsigned)(n * 128 + (kk & 63) * 2));
            *(__nv_bfloat16*)(sm + c * 4096 + off) = h;
            *(__nv_bfloat16*)(sm + 65536 + c * 4096 + off) = l;
        }
    } else {
        int nb = (bid - NB_L0) * 16;
        #pragma unroll 4
        for (int it = 0; it < 64; it++) {
            int idx = it * 512 + tid;               // mat*16384 + n*1024 + k
            int mat = idx >> 14;
            int rr = idx & 16383;
            int n = rr >> 10, kk = rr & 1023;
            const float* W = mat ? wh1 : wx1;
            float w = W[(size_t)(nb + n) * HID + kk];
            __nv_bfloat16 h, l; split_bf16(w, h, l);
            int c = kk >> 6;
            unsigned off = SMEM_SWIZZLE_128B((unsigned)(n * 128 + (kk & 63) * 2));
            char* base = sm + mat * 65536;
            *(__nv_bfloat16*)(base + c * 2048 + off) = h;
            *(__nv_bfloat16*)(base + 32768 + c * 2048 + off) = l;
        }
    }
    __syncthreads();

    for (int k = 0; k <= SEQ; k++) {
        bool active = is_l1 ? (k >= 1) : (k < SEQ);
        if (active) {
            if (!is_l1) step_l0(sm, sb, bid, k, tid, lane, wid, ldr);
            else        step_l1(sm, sb, bid, k, tid, lane, wid, ldr, bh1);
        }

        if (k < SEQ) {
            __threadfence();
            __syncthreads();
            if (tid == 0) {
                atomicAdd(&g_bar, 1u);
                unsigned target = (unsigned)(k + 1) * NBLK;
                unsigned v;
                do {
                    asm volatile("ld.global.acquire.gpu.b32 %0, [%1];"
                                 : "=r"(v) : "l"(&g_bar) : "memory");
                } while (v < target);
            }
            __syncthreads();
        }
    }
}

// ---------------- shared GEMM machinery (logits + xproj) ----------------------
__device__ __forceinline__ void load_stage4(unsigned sb, int stage, int kt,
                                            const char* a_h, const char* a_l,
                                            const char* b_h, const char* b_l,
                                            const int* arow_idx, int nbase,
                                            int tid)
{
    unsigned stoff = sb + (unsigned)stage * STAGE_BYTES;
    #pragma unroll
    for (int j = 0; j < 4; j++) {
        int chunk = tid + j * 256;
        int row = chunk >> 3, boff = (chunk & 7) * 16;
        size_t arow = arow_idx ? (size_t)arow_idx[row] : (size_t)row;
        unsigned dsw = SMEM_SWIZZLE_128B((unsigned)(row * 128 + boff));
        size_t aoff = arow * (HID * 2) + (size_t)kt * 128 + boff;
        size_t boff2 = (size_t)(nbase + row) * (HID * 2) + (size_t)kt * 128 + boff;
        CP_ASYNC16(stoff + 0 * OP_BYTES + dsw, a_h + aoff);
        CP_ASYNC16(stoff + 1 * OP_BYTES + dsw, a_l + aoff);
        CP_ASYNC16(stoff + 2 * OP_BYTES + dsw, b_h + boff2);
        CP_ASYNC16(stoff + 3 * OP_BYTES + dsw, b_l + boff2);
    }
}

// Computes acc[4][4][4] for a 128x128 tile (3 split-bf16 products).
__device__ __forceinline__ void gemm_tile_mma(
    unsigned sb, const char* a_h, const char* a_l,
    const char* b_h, const char* b_l, const int* arow_idx,
    int nbase, int tid, int lane, int wid, float acc[4][4][4])
{
    const int warp_m = (wid >> 2) * 64;
    const int warp_n = (wid & 3) * 32;
    const unsigned xm  = (unsigned)((lane & 7) << 4);
    const int rowA = (lane & 7) + ((lane >> 3) & 1) * 8;
    const unsigned kbA = (unsigned)((lane >> 4) * 16);
    const int rowB = (lane & 7) + ((lane >> 4) << 3);
    const unsigned kbB = (unsigned)(((lane >> 3) & 1) * 16);

    unsigned aoffA[4], aoffB[2];
    #pragma unroll
    for (int mt = 0; mt < 4; mt++)
        aoffA[mt] = (unsigned)((warp_m + mt * 16 + rowA) * 128);
    #pragma unroll
    for (int nt = 0; nt < 2; nt++)
        aoffB[nt] = (unsigned)((warp_n + nt * 16 + rowB) * 128);

    load_stage4(sb, 0, 0, a_h, a_l, b_h, b_l, arow_idx, nbase, tid);
    CP_ASYNC_COMMIT();

    #pragma unroll 1
    for (int kt = 0; kt < NKT; kt++) {
        const int s = kt & 1;
        if (kt + 1 < NKT) {
            load_stage4(sb, s ^ 1, kt + 1, a_h, a_l, b_h, b_l, arow_idx,
                        nbase, tid);
            CP_ASYNC_COMMIT();
            CP_ASYNC_WAIT(1);
        } else {
            CP_ASYNC_WAIT(0);
        }
        __syncthreads();

        unsigned st = sb + (unsigned)s * STAGE_BYTES;
        #pragma unroll
        for (int ks = 0; ks < 4; ks++) {
            unsigned kA = ((unsigned)(ks * 32) + kbA) ^ xm;
            unsigned kB = ((unsigned)(ks * 32) + kbB) ^ xm;
            unsigned ah[4][4], al[4][4], bh[2][4], bl[2][4];
            #pragma unroll
            for (int mt = 0; mt < 4; mt++) {
                ldsm4(ah[mt], st + 0 * OP_BYTES + aoffA[mt] + kA);
                ldsm4(al[mt], st + 1 * OP_BYTES + aoffA[mt] + kA);
            }
            #pragma unroll
            for (int nt = 0; nt < 2; nt++) {
                ldsm4(bh[nt], st + 2 * OP_BYTES + aoffB[nt] + kB);
                ldsm4(bl[nt], st + 3 * OP_BYTES + aoffB[nt] + kB);
            }
            #pragma unroll
            for (int mt = 0; mt < 4; mt++) {
                #pragma unroll
                for (int n2 = 0; n2 < 2; n2++) {
                    mma16816(acc[mt][n2 * 2],     ah[mt], bh[n2][0], bh[n2][1]);
                    mma16816(acc[mt][n2 * 2],     al[mt], bh[n2][0], bh[n2][1]);
                    mma16816(acc[mt][n2 * 2],     ah[mt], bl[n2][0], bl[n2][1]);
                    mma16816(acc[mt][n2 * 2 + 1], ah[mt], bh[n2][2], bh[n2][3]);
                    mma16816(acc[mt][n2 * 2 + 1], al[mt], bh[n2][2], bh[n2][3]);
                    mma16816(acc[mt][n2 * 2 + 1], ah[mt], bl[n2][2], bl[n2][3]);
                }
            }
        }
        __syncthreads();
    }
}

// acc -> smem (128x129) transpose
__device__ __forceinline__ void acc_to_smem(float* sm, int lane, int wid,
                                            const float acc[4][4][4])
{
    const int warp_m = (wid >> 2) * 64;
    const int warp_n = (wid & 3) * 32;
    const int r0l = lane >> 2;
    const int c0l = 2 * (lane & 3);
    #pragma unroll
    for (int mt = 0; mt < 4; mt++) {
        #pragma unroll
        for (int nt = 0; nt < 4; nt++) {
            int row = warp_m + mt * 16 + r0l;
            int col = warp_n + nt * 8 + c0l;
            sm[row * 129 + col]           = acc[mt][nt][0];
            sm[row * 129 + col + 1]       = acc[mt][nt][1];
            sm[(row + 8) * 129 + col]     = acc[mt][nt][2];
            sm[(row + 8) * 129 + col + 1] = acc[mt][nt][3];
        }
    }
}

// ---------------- logits kernel ------------------------------------------------
__global__ __launch_bounds__(256, 1) void logits_mma_kernel(
    const float* __restrict__ vb, float* __restrict__ out)
{
    extern __shared__ char dsm[];
    const int tid  = threadIdx.x;
    const int lane = tid & 31, wid = tid >> 5;
    const int mbase = blockIdx.y * 128;
    const int nbase = blockIdx.x * 128;
    const unsigned sb = (smem_u32(dsm) + 1023u) & ~1023u;

    float acc[4][4][4] = {};
    gemm_tile_mma(sb, (const char*)(g_h1h + BH + (size_t)mbase * HID),
                  (const char*)(g_h1l + BH + (size_t)mbase * HID),
                  (const char*)g_Bh, (const char*)g_Bl, 0,
                  nbase, tid, lane, wid, acc);

    float* sm = (float*)dsm;
    acc_to_smem(sm, lane, wid, acc);
    __syncthreads();

    const int c4 = tid & 31;
    const int rg = tid >> 5;
    const int n0 = nbase + c4 * 4;
    float b0 = (n0 + 0 < VOCAB) ? vb[n0 + 0] : 0.f;
    float b1 = (n0 + 1 < VOCAB) ? vb[n0 + 1] : 0.f;
    float b2 = (n0 + 2 < VOCAB) ? vb[n0 + 2] : 0.f;
    float b3 = (n0 + 3 < VOCAB) ? vb[n0 + 3] : 0.f;
    const bool full = (nbase + 128 <= VOCAB);

    #pragma unroll 4
    for (int it = 0; it < 16; it++) {
        int row = it * 8 + rg;
        const float* sr = sm + row * 129 + c4 * 4;
        float4 v = make_float4(sr[0] + b0, sr[1] + b1, sr[2] + b2, sr[3] + b3);
        float* orow = out + (size_t)(mbase + row) * VOCAB;
        if (full) {
            *(float4*)(orow + n0) = v;
        } else {
            if (n0 + 0 < VOCAB) orow[n0 + 0] = v.x;
            if (n0 + 1 < VOCAB) orow[n0 + 1] = v.y;
            if (n0 + 2 < VOCAB) orow[n0 + 2] = v.z;
            if (n0 + 3 < VOCAB) orow[n0 + 3] = v.w;
        }
    }
}

// ---------------- xproj kernel (gathered-A HMMA) -------------------------------
__global__ __launch_bounds__(256, 1) void xproj_mma_kernel(
    const int* __restrict__ inp, const float* __restrict__ bh0)
{
    extern __shared__ char dsm[];
    __shared__ int idx_s[128];
    const int tid  = threadIdx.x;
    const int lane = tid & 31, wid = tid >> 5;
    const int mbase = blockIdx.y * 128;
    const int nbase = blockIdx.x * 128;
    const unsigned sb = (smem_u32(dsm) + 1023u) & ~1023u;

    if (tid < 128) idx_s[tid] = inp[mbase + tid];
    __syncthreads();

    float acc[4][4][4] = {};
    gemm_tile_mma(sb, (const char*)g_Eh, (const char*)g_El,
                  (const char*)g_Wh, (const char*)g_Wl, idx_s,
                  nbase, tid, lane, wid, acc);

    float* sm = (float*)dsm;
    acc_to_smem(sm, lane, wid, acc);
    __syncthreads();

    const int c4 = tid & 31;
    const int rg = tid >> 5;
    const int n0 = nbase + c4 * 4;
    float4 bb = *(const float4*)(bh0 + n0);

    #pragma unroll 4
    for (int it = 0; it < 16; it++) {
        int row = it * 8 + rg;
        const float* sr = sm + row * 129 + c4 * 4;
        float4 v = make_float4(sr[0] + bb.x, sr[1] + bb.y,
                               sr[2] + bb.z, sr[3] + bb.w);
        *(float4*)(g_xproj0 + (size_t)(mbase + row) * HID + n0) = v;
    }
}

// ---------------- finalize: hidden_final = hi + lo at slot SEQ ----------------
__global__ void finalize_kernel(float* __restrict__ out) {
    int i = blockIdx.x * blockDim.x + threadIdx.x;
    if (i < 2 * BH) {
        int l = i >> 16;                 // BH = 65536
        int r = i & (BH - 1);
        const __nv_bfloat16* hs = l ? g_h1h : g_h0h;
        const __nv_bfloat16* ls = l ? g_h1l : g_h0l;
        out[(size_t)ROWS * VOCAB + i] =
            __bfloat162float(hs[(size_t)SEQ * BH + r]) +
            __bfloat162float(ls[(size_t)SEQ * BH + r]);
    }
}

// ---------------- launcher ------------------------------------------------------
extern "C" void kernel_launch(void* const* d_in, const int* in_sizes, int n_in,
                              void* d_out, int out_size)
{
    const int*   inputs    = (const int*)  d_in[0];
    const float* hidden    = (const float*)d_in[1];
    const float* embedding = (const float*)d_in[2];
    const float* wx0       = (const float*)d_in[3];
    const float* wh0       = (const float*)d_in[4];
    const float* bh0       = (const float*)d_in[5];
    const float* wx1       = (const float*)d_in[6];
    const float* wh1       = (const float*)d_in[7];
    const float* bh1       = (const float*)d_in[8];
    const float* v_w       = (const float*)d_in[9];
    const float* v_b       = (const float*)d_in[10];
    float* out = (float*)d_out;

    static bool attr_set = false;
    if (!attr_set) {
        cudaFuncSetAttribute(recur_kernel,
                             cudaFuncAttributeMaxDynamicSharedMemorySize,
                             RECUR_SMEM);
        cudaFuncSetAttribute(logits_mma_kernel,
                             cudaFuncAttributeMaxDynamicSharedMemorySize,
                             LOGITS_SMEM);
        cudaFuncSetAttribute(xproj_mma_kernel,
                             cudaFuncAttributeMaxDynamicSharedMemorySize,
                             LOGITS_SMEM);
        attr_set = true;
    }

    // splits for vocab weights, embedding, wx0
    __nv_bfloat16 *dBh, *dBl, *dEh, *dEl, *dWh, *dWl;
    cudaGetSymbolAddress((void**)&dBh, g_Bh);
    cudaGetSymbolAddress((void**)&dBl, g_Bl);
    cudaGetSymbolAddress((void**)&dEh, g_Eh);
    cudaGetSymbolAddress((void**)&dEl, g_El);
    cudaGetSymbolAddress((void**)&dWh, g_Wh);
    cudaGetSymbolAddress((void**)&dWl, g_Wl);

    init_kernel<<<(BH + 255) / 256, 256>>>(hidden);
    convert_split_kernel<<<(VOCAB * HID / 4 + 255) / 256, 256>>>(v_w, dBh, dBl,
                                                                 VOCAB * HID / 4);
    convert_split_kernel<<<(VOCAB * HID / 4 + 255) / 256, 256>>>(embedding, dEh,
                                                                 dEl, VOCAB * HID / 4);
    convert_split_kernel<<<(HID * HID / 4 + 255) / 256, 256>>>(wx0, dWh, dWl,
                                                               HID * HID / 4);
    xproj_mma_kernel<<<dim3(HID / 128, ROWS / 128), 256, LOGITS_SMEM>>>(inputs, bh0);
    recur_kernel<<<NBLK, 512, RECUR_SMEM>>>(wh0, wx1, wh1, bh1);
    logits_mma_kernel<<<dim3(VPAD / 128, ROWS / 128), 256, LOGITS_SMEM>>>(v_b, out);

    long long need = (long long)ROWS * VOCAB + 2LL * BH;
    if ((long long)out_size >= need) {
        finalize_kernel<<<(2 * BH + 255) / 256, 256>>>(out);
    }
}

// round 8
// speedup vs baseline: 5.0978x; 1.0248x over previous
#include <cuda_runtime.h>
#include <cuda_bf16.h>
#include <math.h>

// Problem constants
#define EMB   1024
#define HID   1024
#define SEQ   128
#define BATCH 64
#define VOCAB 10000
#define VPAD  10112              // 79 * 128
#define BH    (BATCH * HID)      // 65536
#define ROWS  (SEQ * BATCH)      // 8192

// h layout: [slot][16 chunks][8KB swizzled (64 rows x 128B)]
#define H_SLOT_BYTES  131072
#define H_CHUNK_BYTES 8192
// tile layout (B/X/W): [128-row tile][16 chunks][16KB swizzled]
#define T_TILE_BYTES  262144
#define T_CHUNK_BYTES 16384

// Persistent recurrence config
#define NB_L0 32
#define NB_L1 64
#define NBLK  (NB_L0 + NB_L1)
#define A_BASE 131072            // smem offset of A stages (after weights)
#define L0_STAGE 16384
#define L1_STAGE 32768
#define RECUR_SMEM (131072 + 3 * 32768)   // 229376

// 128x128 GEMM (logits / xproj) config
#define NKT  16
#define OP_BYTES 16384
#define STAGE_BYTES (4 * OP_BYTES)
#define GEMM_SMEM (2 * STAGE_BYTES + 1024)   // 132096

typedef unsigned long long ull;

// ---------------- scratch (device globals) ----------------------------------
__device__ float g_xproj0[ROWS * HID];
__device__ unsigned g_bar;
// hidden states, bf16 hi/lo, chunk-swizzled; slot s = state after step s-1
__device__ __nv_bfloat16 g_h0h[(SEQ + 1) * BH];
__device__ __nv_bfloat16 g_h0l[(SEQ + 1) * BH];
__device__ __nv_bfloat16 g_h1h[(SEQ + 1) * BH];
__device__ __nv_bfloat16 g_h1l[(SEQ + 1) * BH];
// tiled split weights / gathered embedding
__device__ __nv_bfloat16 g_Bh[VPAD * HID];   // v_w tiles; pad rows stay zero
__device__ __nv_bfloat16 g_Bl[VPAD * HID];
__device__ __nv_bfloat16 g_Wh[HID * HID];    // wx0 tiles
__device__ __nv_bfloat16 g_Wl[HID * HID];
__device__ __nv_bfloat16 g_Xh[ROWS * HID];   // gathered emb tiles
__device__ __nv_bfloat16 g_Xl[ROWS * HID];

// ---------------- helpers -----------------------------------------------------
__device__ __forceinline__ unsigned smem_u32(const void* p) {
    unsigned a;
    asm("{ .reg .u64 t; cvta.to.shared.u64 t, %1; cvt.u32.u64 %0, t; }"
        : "=r"(a) : "l"(p));
    return a;
}

#define SWZ(o) ((o) ^ (((o) >> 3) & 0x70))

__device__ __forceinline__ unsigned hoff_bytes(int slot, int m, int k) {
    unsigned o = (unsigned)(m * 128 + (k & 63) * 2);
    return (unsigned)(slot * H_SLOT_BYTES + ((k >> 6) * H_CHUNK_BYTES)) + SWZ(o);
}

#define MBAR_INIT(addr, cnt) \
    asm volatile("mbarrier.init.shared.b64 [%0], %1;" \
                 :: "r"((unsigned)(addr)), "r"((unsigned)(cnt)) : "memory")
#define MBAR_EXPECT_TX(addr, tx) \
    asm volatile("mbarrier.arrive.expect_tx.shared.b64 _, [%0], %1;" \
                 :: "r"((unsigned)(addr)), "r"((unsigned)(tx)) : "memory")

#define MBARRIER_WAIT_PARITY(addr, par) do {                                  \
    unsigned _m = (unsigned)(addr), _p = (unsigned)(par), _d;                 \
    asm volatile("{\n\t.reg .pred p;\n\t"                                     \
        "mbarrier.try_wait.parity.acquire.cta.shared::cta.b64 p, [%1], %2;\n\t" \
        "selp.b32 %0, 1, 0, p;\n\t}"                                          \
        : "=r"(_d) : "r"(_m), "r"(_p) : "memory");                            \
    if (!_d) {                                                                \
        asm volatile("{\n\t.reg .pred P1;\n\t"                                \
            "WL_%=:\n\t"                                                      \
            "mbarrier.try_wait.parity.acquire.cta.shared::cta.b64 P1, [%0], %1, 0x989680;\n\t" \
            "@P1 bra.uni WD_%=;\n\t"                                          \
            "bra.uni WL_%=;\n\t"                                              \
            "WD_%=:\n\t}" :: "r"(_m), "r"(_p) : "memory");                    \
    }                                                                         \
} while (0)

__device__ __forceinline__ void bulk_g2s(unsigned dst, const void* src,
                                         unsigned bytes, unsigned mbar) {
    asm volatile(
        "cp.async.bulk.shared::cluster.global.mbarrier::complete_tx::bytes "
        "[%0], [%1], %2, [%3];"
        :: "r"(dst), "l"(src), "r"(bytes), "r"(mbar) : "memory");
}

__device__ __forceinline__ void ldsm4(unsigned* r, unsigned addr) {
    asm volatile("ldmatrix.sync.aligned.m8n8.x4.shared.b16 {%0,%1,%2,%3}, [%4];"
                 : "=r"(r[0]), "=r"(r[1]), "=r"(r[2]), "=r"(r[3]) : "r"(addr));
}
__device__ __forceinline__ void mma16816(float* c, const unsigned* a,
                                         unsigned b0, unsigned b1) {
    asm volatile(
        "mma.sync.aligned.m16n8k16.row.col.f32.bf16.bf16.f32 "
        "{%0,%1,%2,%3}, {%4,%5,%6,%7}, {%8,%9}, {%0,%1,%2,%3};"
        : "+f"(c[0]), "+f"(c[1]), "+f"(c[2]), "+f"(c[3])
        : "r"(a[0]), "r"(a[1]), "r"(a[2]), "r"(a[3]), "r"(b0), "r"(b1));
}

__device__ __forceinline__ void split_bf16(float v, __nv_bfloat16& h,
                                           __nv_bfloat16& l) {
    h = __float2bfloat16(v);
    l = __float2bfloat16(v - __bfloat162float(h));
}

// ---------------- init: initial hidden -> slot 0 (swizzled) -------------------
__global__ void init_kernel(const float* __restrict__ hidden) {
    int i = blockIdx.x * blockDim.x + threadIdx.x;
    if (i == 0) g_bar = 0;
    if (i < BH) {
        int b = i >> 10, n = i & 1023;
        unsigned off = hoff_bytes(0, b, n);
        __nv_bfloat16 h, l;
        split_bf16(hidden[i], h, l);
        *(__nv_bfloat16*)((char*)g_h0h + off) = h;
        *(__nv_bfloat16*)((char*)g_h0l + off) = l;
        split_bf16(hidden[BH + i], h, l);
        *(__nv_bfloat16*)((char*)g_h1h + off) = h;
        *(__nv_bfloat16*)((char*)g_h1l + off) = l;
    }
}

// ---------------- convert fp32 rows -> split bf16 tiles (swizzled) ------------
// dst layout: [r>>7 tile][k>>6 chunk][swizzled (r&127)*128 + (k&63)*2]
__global__ __launch_bounds__(256) void conv_tiles_kernel(
    const float* __restrict__ src, const int* __restrict__ idx,
    __nv_bfloat16* __restrict__ dh, __nv_bfloat16* __restrict__ dl, int total4)
{
    int i = blockIdx.x * 256 + threadIdx.x;
    if (i >= total4) return;
    int e = i * 4;
    int r = e >> 10, k = e & 1023;
    int srow = idx ? idx[r] : r;
    float4 a = *(const float4*)(src + (size_t)srow * 1024 + k);
    __nv_bfloat16 h0, l0, h1, l1, h2, l2, h3, l3;
    split_bf16(a.x, h0, l0); split_bf16(a.y, h1, l1);
    split_bf16(a.z, h2, l2); split_bf16(a.w, h3, l3);
    unsigned o = (unsigned)((r & 127) * 128 + (k & 63) * 2);
    unsigned off = (unsigned)((r >> 7) * T_TILE_BYTES + (k >> 6) * T_CHUNK_BYTES)
                 + SWZ(o);
    *(__nv_bfloat162*)((char*)dh + off)     = __nv_bfloat162(h0, h1);
    *(__nv_bfloat162*)((char*)dh + off + 4) = __nv_bfloat162(h2, h3);
    *(__nv_bfloat162*)((char*)dl + off)     = __nv_bfloat162(l0, l1);
    *(__nv_bfloat162*)((char*)dl + off + 4) = __nv_bfloat162(l2, l3);
}

// ---------------- recur: layer-0 step -----------------------------------------
__device__ __forceinline__ void step_l0(unsigned sb, unsigned mbb, int bid,
                                        int k, int u0, int tid, int lane, int wid)
{
    const char* a0h = (const char*)g_h0h + (size_t)k * H_SLOT_BYTES;
    const char* a0l = (const char*)g_h0l + (size_t)k * H_SLOT_BYTES;

    if (tid == 0) {
        #pragma unroll
        for (int j = 0; j < 3; j++) {
            int s = (u0 + j) & 3;
            unsigned dst = sb + A_BASE + s * L0_STAGE;
            MBAR_EXPECT_TX(mbb + s * 8, 16384u);
            bulk_g2s(dst,        a0h + j * H_CHUNK_BYTES, 8192, mbb + s * 8);
            bulk_g2s(dst + 8192, a0l + j * H_CHUNK_BYTES, 8192, mbb + s * 8);
        }
    }

    const int wm = wid >> 1, wn = wid & 1;
    const unsigned xm    = (unsigned)((lane & 7) << 4);
    const unsigned aoffA = (unsigned)((wm * 16 + (lane & 7) + ((lane >> 3) & 1) * 8) * 128);
    const unsigned kbA   = (unsigned)((lane >> 4) * 16);
    const unsigned boffB = (unsigned)((wn * 16 + (lane & 7) + ((lane >> 4) << 3)) * 128);
    const unsigned kbB   = (unsigned)(((lane >> 3) & 1) * 16);

    float acc[2][4] = {};

    #pragma unroll 1
    for (int c = 0; c < 16; c++) {
        int uu = u0 + c;
        int s = uu & 3;
        MBARRIER_WAIT_PARITY(mbb + s * 8, (uu >> 2) & 1);
        __syncthreads();
        if (tid == 0 && c + 3 < 16) {
            int s2 = (uu + 3) & 3;
            unsigned dst = sb + A_BASE + s2 * L0_STAGE;
            MBAR_EXPECT_TX(mbb + s2 * 8, 16384u);
            bulk_g2s(dst,        a0h + (c + 3) * H_CHUNK_BYTES, 8192, mbb + s2 * 8);
            bulk_g2s(dst + 8192, a0l + (c + 3) * H_CHUNK_BYTES, 8192, mbb + s2 * 8);
        }
        unsigned stg = sb + A_BASE + s * L0_STAGE;
        unsigned wbh = sb + (unsigned)(c * 4096);
        unsigned wbl = wbh + 65536;
        #pragma unroll
        for (int ks = 0; ks < 4; ks++) {
            unsigned kA = ((unsigned)(ks * 32) + kbA) ^ xm;
            unsigned kB = ((unsigned)(ks * 32) + kbB) ^ xm;
            unsigned ah[4], al[4], bh[4], bl[4];
            ldsm4(ah, stg + aoffA + kA);
            ldsm4(al, stg + 8192 + aoffA + kA);
            ldsm4(bh, wbh + boffB + kB);
            ldsm4(bl, wbl + boffB + kB);
            mma16816(acc[0], ah, bh[0], bh[1]);
            mma16816(acc[0], al, bh[0], bh[1]);
            mma16816(acc[0], ah, bl[0], bl[1]);
            mma16816(acc[0], al, bl[0], bl[1]);
            mma16816(acc[1], ah, bh[2], bh[3]);
            mma16816(acc[1], al, bh[2], bh[3]);
            mma16816(acc[1], ah, bl[2], bl[3]);
            mma16816(acc[1], al, bl[2], bl[3]);
        }
    }

    // epilogue: + xproj, tanh, split, store slot k+1 (swizzled layout)
    int r = lane >> 2, c0 = 2 * (lane & 3);
    int mrow = wm * 16 + r;
    #pragma unroll
    for (int n2 = 0; n2 < 2; n2++) {
        int gn = bid * 32 + wn * 16 + n2 * 8 + c0;
        const float* xp0 = g_xproj0 + ((size_t)k * BATCH + mrow) * HID + gn;
        const float* xp1 = g_xproj0 + ((size_t)k * BATCH + mrow + 8) * HID + gn;
        float2 x0 = *(const float2*)xp0;
        float2 x1 = *(const float2*)xp1;
        float t0 = tanhf(acc[n2][0] + x0.x);
        float t1 = tanhf(acc[n2][1] + x0.y);
        float t2 = tanhf(acc[n2][2] + x1.x);
        float t3 = tanhf(acc[n2][3] + x1.y);
        __nv_bfloat16 h0, l0, h1, l1, h2, l2, h3, l3;
        split_bf16(t0, h0, l0); split_bf16(t1, h1, l1);
        split_bf16(t2, h2, l2); split_bf16(t3, h3, l3);
        unsigned o0 = hoff_bytes(k + 1, mrow, gn);
        unsigned o1 = hoff_bytes(k + 1, mrow + 8, gn);
        *(__nv_bfloat162*)((char*)g_h0h + o0) = __nv_bfloat162(h0, h1);
        *(__nv_bfloat162*)((char*)g_h0l + o0) = __nv_bfloat162(l0, l1);
        *(__nv_bfloat162*)((char*)g_h0h + o1) = __nv_bfloat162(h2, h3);
        *(__nv_bfloat162*)((char*)g_h0l + o1) = __nv_bfloat162(l2, l3);
    }
}

// ---------------- recur: layer-1 step -----------------------------------------
__device__ __forceinline__ void step_l1(char* smc, unsigned sb, unsigned mbb,
                                        int bid, int k, int u0, int tid,
                                        int lane, int wid,
                                        const float* __restrict__ bh1)
{
    const char* a0h = (const char*)g_h0h + (size_t)k * H_SLOT_BYTES;
    const char* a0l = (const char*)g_h0l + (size_t)k * H_SLOT_BYTES;
    const char* a1h = (const char*)g_h1h + (size_t)(k - 1) * H_SLOT_BYTES;
    const char* a1l = (const char*)g_h1l + (size_t)(k - 1) * H_SLOT_BYTES;

    if (tid == 0) {
        #pragma unroll
        for (int j = 0; j < 2; j++) {
            int s = (u0 + j) % 3;
            unsigned dst = sb + A_BASE + s * L1_STAGE;
            MBAR_EXPECT_TX(mbb + s * 8, 32768u);
            bulk_g2s(dst,         a0h + j * H_CHUNK_BYTES, 8192, mbb + s * 8);
            bulk_g2s(dst + 8192,  a0l + j * H_CHUNK_BYTES, 8192, mbb + s * 8);
            bulk_g2s(dst + 16384, a1h + j * H_CHUNK_BYTES, 8192, mbb + s * 8);
            bulk_g2s(dst + 24576, a1l + j * H_CHUNK_BYTES, 8192, mbb + s * 8);
        }
    }

    const int wm = wid >> 1, kq = wid & 1;
    const unsigned xm    = (unsigned)((lane & 7) << 4);
    const unsigned aoffA = (unsigned)((wm * 16 + (lane & 7) + ((lane >> 3) & 1) * 8) * 128);
    const unsigned kbA   = (unsigned)((lane >> 4) * 16);
    const unsigned boffB = (unsigned)(((lane & 7) + ((lane >> 4) << 3)) * 128);
    const unsigned kbB   = (unsigned)(((lane >> 3) & 1) * 16);
    const unsigned aq    = (unsigned)(kq * 16384);

    float acc[2][4] = {};

    #pragma unroll 1
    for (int c = 0; c < 16; c++) {
        int uu = u0 + c;
        int s = uu % 3;
        MBARRIER_WAIT_PARITY(mbb + s * 8, (uu / 3) & 1);
        __syncthreads();
        if (tid == 0 && c + 2 < 16) {
            int s2 = (uu + 2) % 3;
            unsigned dst = sb + A_BASE + s2 * L1_STAGE;
            MBAR_EXPECT_TX(mbb + s2 * 8, 32768u);
            bulk_g2s(dst,         a0h + (c + 2) * H_CHUNK_BYTES, 8192, mbb + s2 * 8);
            bulk_g2s(dst + 8192,  a0l + (c + 2) * H_CHUNK_BYTES, 8192, mbb + s2 * 8);
            bulk_g2s(dst + 16384, a1h + (c + 2) * H_CHUNK_BYTES, 8192, mbb + s2 * 8);
            bulk_g2s(dst + 24576, a1l + (c + 2) * H_CHUNK_BYTES, 8192, mbb + s2 * 8);
        }
        unsigned stg = sb + A_BASE + s * L1_STAGE + aq;
        unsigned wbh = sb + (unsigned)(kq * 65536 + c * 2048);
        unsigned wbl = wbh + 32768;
        #pragma unroll
        for (int ks = 0; ks < 4; ks++) {
            unsigned kA = ((unsigned)(ks * 32) + kbA) ^ xm;
            unsigned kB = ((unsigned)(ks * 32) + kbB) ^ xm;
            unsigned ah[4], al[4], bh[4], bl[4];
            ldsm4(ah, stg + aoffA + kA);
            ldsm4(al, stg + 8192 + aoffA + kA);
            ldsm4(bh, wbh + boffB + kB);
            ldsm4(bl, wbl + boffB + kB);
            mma16816(acc[0], ah, bh[0], bh[1]);
            mma16816(acc[0], al, bh[0], bh[1]);
            mma16816(acc[0], ah, bl[0], bl[1]);
            mma16816(acc[0], al, bl[0], bl[1]);
            mma16816(acc[1], ah, bh[2], bh[3]);
            mma16816(acc[1], al, bh[2], bh[3]);
            mma16816(acc[1], ah, bl[2], bl[3]);
            mma16816(acc[1], al, bl[2], bl[3]);
        }
    }

    // kq-pair reduction in the stage used by chunk 15 (free until next step)
    float* red = (float*)(smc + A_BASE + ((u0 + 15) % 3) * L1_STAGE);
    int r = lane >> 2, c0 = 2 * (lane & 3);
    int mrow = wm * 16 + r;
    if (kq == 1) {
        #pragma unroll
        for (int n2 = 0; n2 < 2; n2++) {
            int col = n2 * 8 + c0;
            *(float2*)&red[mrow * 16 + col]       = make_float2(acc[n2][0], acc[n2][1]);
            *(float2*)&red[(mrow + 8) * 16 + col] = make_float2(acc[n2][2], acc[n2][3]);
        }
    }
    __syncthreads();
    if (kq == 0) {
        int gnb = (bid - NB_L0) * 16;
        #pragma unroll
        for (int n2 = 0; n2 < 2; n2++) {
            int col = n2 * 8 + c0;
            int gn = gnb + col;
            float2 r0 = *(const float2*)&red[mrow * 16 + col];
            float2 r1 = *(const float2*)&red[(mrow + 8) * 16 + col];
            float2 bv = *(const float2*)(bh1 + gn);
            float t0 = tanhf(acc[n2][0] + r0.x + bv.x);
            float t1 = tanhf(acc[n2][1] + r0.y + bv.y);
            float t2 = tanhf(acc[n2][2] + r1.x + bv.x);
            float t3 = tanhf(acc[n2][3] + r1.y + bv.y);
            __nv_bfloat16 h0, l0, h1, l1, h2, l2, h3, l3;
            split_bf16(t0, h0, l0); split_bf16(t1, h1, l1);
            split_bf16(t2, h2, l2); split_bf16(t3, h3, l3);
            unsigned o0 = hoff_bytes(k, mrow, gn);
            unsigned o1 = hoff_bytes(k, mrow + 8, gn);
            *(__nv_bfloat162*)((char*)g_h1h + o0) = __nv_bfloat162(h0, h1);
            *(__nv_bfloat162*)((char*)g_h1l + o0) = __nv_bfloat162(l0, l1);
            *(__nv_bfloat162*)((char*)g_h1h + o1) = __nv_bfloat162(h2, h3);
            *(__nv_bfloat162*)((char*)g_h1l + o1) = __nv_bfloat162(l2, l3);
        }
    }
}

// ---------------- persistent recurrence ----------------------------------------
__global__ __launch_bounds__(256, 1) void recur_kernel(
    const float* __restrict__ wh0, const float* __restrict__ wx1,
    const float* __restrict__ wh1, const float* __restrict__ bh1)
{
    extern __shared__ char sm[];
    __shared__ ull s_mbar[4];
    const int tid = threadIdx.x;
    const int lane = tid & 31, wid = tid >> 5;
    const int bid = blockIdx.x;
    const bool is_l1 = (bid >= NB_L0);
    const unsigned sb = smem_u32(sm);
    const unsigned mbb = smem_u32(&s_mbar[0]);

    if (tid == 0) {
        #pragma unroll
        for (int s = 0; s < 4; s++) MBAR_INIT(mbb + s * 8, 1);
    }

    // ---- one-time weight preload: split bf16, swizzled 64k-chunks ----
    if (!is_l1) {
        int nb = bid * 32;
        #pragma unroll 4
        for (int it = 0; it < 128; it++) {
            int idx = it * 256 + tid;               // n*1024 + k
            int n = idx >> 10, kk = idx & 1023;
            float w = wh0[(size_t)(nb + n) * HID + kk];
            __nv_bfloat16 h, l; split_bf16(w, h, l);
            int c = kk >> 6;
            unsigned off = SWZ((unsigned)(n * 128 + (kk & 63) * 2));
            *(__nv_bfloat16*)(sm + c * 4096 + off) = h;
            *(__nv_bfloat16*)(sm + 65536 + c * 4096 + off) = l;
        }
    } else {
        int nb = (bid - NB_L0) * 16;
        #pragma unroll 4
        for (int it = 0; it < 128; it++) {
            int idx = it * 256 + tid;               // mat*16384 + n*1024 + k
            int mat = idx >> 14;
            int rr = idx & 16383;
            int n = rr >> 10, kk = rr & 1023;
            const float* W = mat ? wh1 : wx1;
            float w = W[(size_t)(nb + n) * HID + kk];
            __nv_bfloat16 h, l; split_bf16(w, h, l);
            int c = kk >> 6;
            unsigned off = SWZ((unsigned)(n * 128 + (kk & 63) * 2));
            char* base = sm + mat * 65536;
            *(__nv_bfloat16*)(base + c * 2048 + off) = h;
            *(__nv_bfloat16*)(base + 32768 + c * 2048 + off) = l;
        }
    }
    __syncthreads();

    int u = 0;
    for (int k = 0; k <= SEQ; k++) {
        bool active = is_l1 ? (k >= 1) : (k < SEQ);
        if (active) {
            if (!is_l1) step_l0(sb, mbb, bid, k, u, tid, lane, wid);
            else        step_l1(sm, sb, mbb, bid, k, u, tid, lane, wid, bh1);
            u += 16;
        }

        if (k < SEQ) {
            __threadfence();
            __syncthreads();
            if (tid == 0) {
                atomicAdd(&g_bar, 1u);
                unsigned target = (unsigned)(k + 1) * NBLK;
                unsigned v;
                do {
                    asm volatile("ld.global.acquire.gpu.b32 %0, [%1];"
                                 : "=r"(v) : "l"(&g_bar) : "memory");
                } while (v < target);
            }
            __syncthreads();
        }
    }
}

// ---------------- 128x128 tile compute (shared by logits/xproj) ----------------
template<bool FOURTH>
__device__ __forceinline__ void compute_chunk128(
    unsigned st, const unsigned* aoffA, const unsigned* aoffB,
    unsigned kbA, unsigned kbB, unsigned xm, float acc[4][4][4])
{
    #pragma unroll
    for (int ks = 0; ks < 4; ks++) {
        unsigned kA = ((unsigned)(ks * 32) + kbA) ^ xm;
        unsigned kB = ((unsigned)(ks * 32) + kbB) ^ xm;
        unsigned ah[4][4], al[4][4], bh[2][4], bl[2][4];
        #pragma unroll
        for (int mt = 0; mt < 4; mt++) {
            ldsm4(ah[mt], st + 0 * OP_BYTES + aoffA[mt] + kA);
            ldsm4(al[mt], st + 1 * OP_BYTES + aoffA[mt] + kA);
        }
        #pragma unroll
        for (int nt = 0; nt < 2; nt++) {
            ldsm4(bh[nt], st + 2 * OP_BYTES + aoffB[nt] + kB);
            ldsm4(bl[nt], st + 3 * OP_BYTES + aoffB[nt] + kB);
        }
        #pragma unroll
        for (int mt = 0; mt < 4; mt++) {
            #pragma unroll
            for (int n2 = 0; n2 < 2; n2++) {
                mma16816(acc[mt][n2 * 2],     ah[mt], bh[n2][0], bh[n2][1]);
                mma16816(acc[mt][n2 * 2],     al[mt], bh[n2][0], bh[n2][1]);
                mma16816(acc[mt][n2 * 2],     ah[mt], bl[n2][0], bl[n2][1]);
                if (FOURTH)
                    mma16816(acc[mt][n2 * 2], al[mt], bl[n2][0], bl[n2][1]);
                mma16816(acc[mt][n2 * 2 + 1], ah[mt], bh[n2][2], bh[n2][3]);
                mma16816(acc[mt][n2 * 2 + 1], al[mt], bh[n2][2], bh[n2][3]);
                mma16816(acc[mt][n2 * 2 + 1], ah[mt], bl[n2][2], bl[n2][3]);
                if (FOURTH)
                    mma16816(acc[mt][n2 * 2 + 1], al[mt], bl[n2][2], bl[n2][3]);
            }
        }
    }
}

__device__ __forceinline__ void tile_geometry(int lane, int wid,
                                              unsigned* aoffA, unsigned* aoffB,
                                              unsigned& kbA, unsigned& kbB,
                                              unsigned& xm)
{
    const int warp_m = (wid >> 2) * 64;
    const int warp_n = (wid & 3) * 32;
    xm  = (unsigned)((lane & 7) << 4);
    const int rowA = (lane & 7) + ((lane >> 3) & 1) * 8;
    kbA = (unsigned)((lane >> 4) * 16);
    const int rowB = (lane & 7) + ((lane >> 4) << 3);
    kbB = (unsigned)(((lane >> 3) & 1) * 16);
    #pragma unroll
    for (int mt = 0; mt < 4; mt++)
        aoffA[mt] = (unsigned)((warp_m + mt * 16 + rowA) * 128);
    #pragma unroll
    for (int nt = 0; nt < 2; nt++)
        aoffB[nt] = (unsigned)((warp_n + nt * 16 + rowB) * 128);
}

__device__ __forceinline__ void acc_to_smem(float* sm, int lane, int wid,
                                            const float acc[4][4][4])
{
    const int warp_m = (wid >> 2) * 64;
    const int warp_n = (wid & 3) * 32;
    const int r0l = lane >> 2;
    const int c0l = 2 * (lane & 3);
    #pragma unroll
    for (int mt = 0; mt < 4; mt++) {
        #pragma unroll
        for (int nt = 0; nt < 4; nt++) {
            int row = warp_m + mt * 16 + r0l;
            int col = warp_n + nt * 8 + c0l;
            sm[row * 129 + col]           = acc[mt][nt][0];
            sm[row * 129 + col + 1]       = acc[mt][nt][1];
            sm[(row + 8) * 129 + col]     = acc[mt][nt][2];
            sm[(row + 8) * 129 + col + 1] = acc[mt][nt][3];
        }
    }
}

// ---------------- logits kernel -------------------------------------------------
__global__ __launch_bounds__(256, 1) void logits_mma_kernel(
    const float* __restrict__ vb, float* __restrict__ out)
{
    extern __shared__ char dsm[];
    __shared__ ull s_mb[2];
    const int tid  = threadIdx.x;
    const int lane = tid & 31, wid = tid >> 5;
    const int mbase = blockIdx.y * 128;
    const int nbase = blockIdx.x * 128;
    const unsigned sb = (smem_u32(dsm) + 1023u) & ~1023u;
    const unsigned mbb = smem_u32(&s_mb[0]);

    if (tid == 0) { MBAR_INIT(mbb, 1); MBAR_INIT(mbb + 8, 1); }
    __syncthreads();

    const int s0 = mbase / 64 + 1;      // h1 slots
    const char* ahb = (const char*)g_h1h;
    const char* alb = (const char*)g_h1l;
    const char* bhb = (const char*)g_Bh + (size_t)(nbase >> 7) * T_TILE_BYTES;
    const char* blb = (const char*)g_Bl + (size_t)(nbase >> 7) * T_TILE_BYTES;

    unsigned aoffA[4], aoffB[2], kbA, kbB, xm;
    tile_geometry(lane, wid, aoffA, aoffB, kbA, kbB, xm);
    float acc[4][4][4] = {};

    if (tid == 0) {
        MBAR_EXPECT_TX(mbb, 65536u);
        unsigned dst = sb;
        bulk_g2s(dst,                 ahb + (size_t)s0 * H_SLOT_BYTES, 8192, mbb);
        bulk_g2s(dst + 8192,          ahb + (size_t)(s0 + 1) * H_SLOT_BYTES, 8192, mbb);
        bulk_g2s(dst + OP_BYTES,      alb + (size_t)s0 * H_SLOT_BYTES, 8192, mbb);
        bulk_g2s(dst + OP_BYTES + 8192, alb + (size_t)(s0 + 1) * H_SLOT_BYTES, 8192, mbb);
        bulk_g2s(dst + 2 * OP_BYTES,  bhb, 16384, mbb);
        bulk_g2s(dst + 3 * OP_BYTES,  blb, 16384, mbb);
    }

    #pragma unroll 1
    for (int c = 0; c < NKT; c++) {
        unsigned mb = mbb + (unsigned)((c & 1) * 8);
        MBARRIER_WAIT_PARITY(mb, (c >> 1) & 1);
        __syncthreads();
        if (tid == 0 && c + 1 < NKT) {
            int kt = c + 1;
            unsigned mb2 = mbb + (unsigned)((kt & 1) * 8);
            unsigned dst = sb + (unsigned)((kt & 1) * STAGE_BYTES);
            MBAR_EXPECT_TX(mb2, 65536u);
            bulk_g2s(dst,                   ahb + (size_t)s0 * H_SLOT_BYTES + kt * H_CHUNK_BYTES, 8192, mb2);
            bulk_g2s(dst + 8192,            ahb + (size_t)(s0 + 1) * H_SLOT_BYTES + kt * H_CHUNK_BYTES, 8192, mb2);
            bulk_g2s(dst + OP_BYTES,        alb + (size_t)s0 * H_SLOT_BYTES + kt * H_CHUNK_BYTES, 8192, mb2);
            bulk_g2s(dst + OP_BYTES + 8192, alb + (size_t)(s0 + 1) * H_SLOT_BYTES + kt * H_CHUNK_BYTES, 8192, mb2);
            bulk_g2s(dst + 2 * OP_BYTES,    bhb + kt * T_CHUNK_BYTES, 16384, mb2);
            bulk_g2s(dst + 3 * OP_BYTES,    blb + kt * T_CHUNK_BYTES, 16384, mb2);
        }
        unsigned st = sb + (unsigned)((c & 1) * STAGE_BYTES);
        compute_chunk128<false>(st, aoffA, aoffB, kbA, kbB, xm, acc);
    }
    __syncthreads();

    float* sm = (float*)dsm;
    acc_to_smem(sm, lane, wid, acc);
    __syncthreads();

    const int c4 = tid & 31;
    const int rg = tid >> 5;
    const int n0 = nbase + c4 * 4;
    float b0 = (n0 + 0 < VOCAB) ? vb[n0 + 0] : 0.f;
    float b1 = (n0 + 1 < VOCAB) ? vb[n0 + 1] : 0.f;
    float b2 = (n0 + 2 < VOCAB) ? vb[n0 + 2] : 0.f;
    float b3 = (n0 + 3 < VOCAB) ? vb[n0 + 3] : 0.f;
    const bool full = (nbase + 128 <= VOCAB);

    #pragma unroll 4
    for (int it = 0; it < 16; it++) {
        int row = it * 8 + rg;
        const float* sr = sm + row * 129 + c4 * 4;
        float4 v = make_float4(sr[0] + b0, sr[1] + b1, sr[2] + b2, sr[3] + b3);
        float* orow = out + (size_t)(mbase + row) * VOCAB;
        if (full) {
            *(float4*)(orow + n0) = v;
        } else {
            if (n0 + 0 < VOCAB) orow[n0 + 0] = v.x;
            if (n0 + 1 < VOCAB) orow[n0 + 1] = v.y;
            if (n0 + 2 < VOCAB) orow[n0 + 2] = v.z;
            if (n0 + 3 < VOCAB) orow[n0 + 3] = v.w;
        }
    }
}

// ---------------- xproj kernel ---------------------------------------------------
__global__ __launch_bounds__(256, 1) void xproj_mma_kernel(
    const float* __restrict__ bh0)
{
    extern __shared__ char dsm[];
    __shared__ ull s_mb[2];
    const int tid  = threadIdx.x;
    const int lane = tid & 31, wid = tid >> 5;
    const int mbase = blockIdx.y * 128;
    const int nbase = blockIdx.x * 128;
    const unsigned sb = (smem_u32(dsm) + 1023u) & ~1023u;
    const unsigned mbb = smem_u32(&s_mb[0]);

    if (tid == 0) { MBAR_INIT(mbb, 1); MBAR_INIT(mbb + 8, 1); }
    __syncthreads();

    const char* ahb = (const char*)g_Xh + (size_t)(mbase >> 7) * T_TILE_BYTES;
    const char* alb = (const char*)g_Xl + (size_t)(mbase >> 7) * T_TILE_BYTES;
    const char* bhb = (const char*)g_Wh + (size_t)(nbase >> 7) * T_TILE_BYTES;
    const char* blb = (const char*)g_Wl + (size_t)(nbase >> 7) * T_TILE_BYTES;

    unsigned aoffA[4], aoffB[2], kbA, kbB, xm;
    tile_geometry(lane, wid, aoffA, aoffB, kbA, kbB, xm);
    float acc[4][4][4] = {};

    if (tid == 0) {
        MBAR_EXPECT_TX(mbb, 65536u);
        bulk_g2s(sb,                ahb, 16384, mbb);
        bulk_g2s(sb + OP_BYTES,     alb, 16384, mbb);
        bulk_g2s(sb + 2 * OP_BYTES, bhb, 16384, mbb);
        bulk_g2s(sb + 3 * OP_BYTES, blb, 16384, mbb);
    }

    #pragma unroll 1
    for (int c = 0; c < NKT; c++) {
        unsigned mb = mbb + (unsigned)((c & 1) * 8);
        MBARRIER_WAIT_PARITY(mb, (c >> 1) & 1);
        __syncthreads();
        if (tid == 0 && c + 1 < NKT) {
            int kt = c + 1;
            unsigned mb2 = mbb + (unsigned)((kt & 1) * 8);
            unsigned dst = sb + (unsigned)((kt & 1) * STAGE_BYTES);
            MBAR_EXPECT_TX(mb2, 65536u);
            bulk_g2s(dst,                ahb + kt * T_CHUNK_BYTES, 16384, mb2);
            bulk_g2s(dst + OP_BYTES,     alb + kt * T_CHUNK_BYTES, 16384, mb2);
            bulk_g2s(dst + 2 * OP_BYTES, bhb + kt * T_CHUNK_BYTES, 16384, mb2);
            bulk_g2s(dst + 3 * OP_BYTES, blb + kt * T_CHUNK_BYTES, 16384, mb2);
        }
        unsigned st = sb + (unsigned)((c & 1) * STAGE_BYTES);
        compute_chunk128<true>(st, aoffA, aoffB, kbA, kbB, xm, acc);
    }
    __syncthreads();

    float* sm = (float*)dsm;
    acc_to_smem(sm, lane, wid, acc);
    __syncthreads();

    const int c4 = tid & 31;
    const int rg = tid >> 5;
    const int n0 = nbase + c4 * 4;
    float4 bb = *(const float4*)(bh0 + n0);

    #pragma unroll 4
    for (int it = 0; it < 16; it++) {
        int row = it * 8 + rg;
        const float* sr = sm + row * 129 + c4 * 4;
        float4 v = make_float4(sr[0] + bb.x, sr[1] + bb.y,
                               sr[2] + bb.z, sr[3] + bb.w);
        *(float4*)(g_xproj0 + (size_t)(mbase + row) * HID + n0) = v;
    }
}

// ---------------- finalize: hidden_final = hi + lo at slot SEQ ------------------
__global__ void finalize_kernel(float* __restrict__ out) {
    int i = blockIdx.x * blockDim.x + threadIdx.x;
    if (i < 2 * BH) {
        int l = i >> 16;                 // BH = 65536
        int r = i & (BH - 1);
        int b = r >> 10, n = r & 1023;
        unsigned off = hoff_bytes(SEQ, b, n);
        const char* hs = l ? (const char*)g_h1h : (const char*)g_h0h;
        const char* ls = l ? (const char*)g_h1l : (const char*)g_h0l;
        out[(size_t)ROWS * VOCAB + i] =
            __bfloat162float(*(const __nv_bfloat16*)(hs + off)) +
            __bfloat162float(*(const __nv_bfloat16*)(ls + off));
    }
}

// ---------------- launcher --------------------------------------------------------
extern "C" void kernel_launch(void* const* d_in, const int* in_sizes, int n_in,
                              void* d_out, int out_size)
{
    const int*   inputs    = (const int*)  d_in[0];
    const float* hidden    = (const float*)d_in[1];
    const float* embedding = (const float*)d_in[2];
    const float* wx0       = (const float*)d_in[3];
    const float* wh0       = (const float*)d_in[4];
    const float* bh0       = (const float*)d_in[5];
    const float* wx1       = (const float*)d_in[6];
    const float* wh1       = (const float*)d_in[7];
    const float* bh1       = (const float*)d_in[8];
    const float* v_w       = (const float*)d_in[9];
    const float* v_b       = (const float*)d_in[10];
    float* out = (float*)d_out;

    static bool attr_set = false;
    if (!attr_set) {
        cudaFuncSetAttribute(recur_kernel,
                             cudaFuncAttributeMaxDynamicSharedMemorySize,
                             RECUR_SMEM);
        cudaFuncSetAttribute(logits_mma_kernel,
                             cudaFuncAttributeMaxDynamicSharedMemorySize,
                             GEMM_SMEM);
        cudaFuncSetAttribute(xproj_mma_kernel,
                             cudaFuncAttributeMaxDynamicSharedMemorySize,
                             GEMM_SMEM);
        attr_set = true;
    }

    __nv_bfloat16 *dBh, *dBl, *dWh, *dWl, *dXh, *dXl;
    cudaGetSymbolAddress((void**)&dBh, g_Bh);
    cudaGetSymbolAddress((void**)&dBl, g_Bl);
    cudaGetSymbolAddress((void**)&dWh, g_Wh);
    cudaGetSymbolAddress((void**)&dWl, g_Wl);
    cudaGetSymbolAddress((void**)&dXh, g_Xh);
    cudaGetSymbolAddress((void**)&dXl, g_Xl);

    init_kernel<<<(BH + 255) / 256, 256>>>(hidden);
    conv_tiles_kernel<<<(VOCAB * HID / 4 + 255) / 256, 256>>>(
        v_w, 0, dBh, dBl, VOCAB * HID / 4);
    conv_tiles_kernel<<<(HID * HID / 4 + 255) / 256, 256>>>(
        wx0, 0, dWh, dWl, HID * HID / 4);
    conv_tiles_kernel<<<(ROWS * HID / 4 + 255) / 256, 256>>>(
        embedding, inputs, dXh, dXl, ROWS * HID / 4);
    xproj_mma_kernel<<<dim3(HID / 128, ROWS / 128), 256, GEMM_SMEM>>>(bh0);
    recur_kernel<<<NBLK, 256, RECUR_SMEM>>>(wh0, wx1, wh1, bh1);
    logits_mma_kernel<<<dim3(VPAD / 128, ROWS / 128), 256, GEMM_SMEM>>>(v_b, out);

    long long need = (long long)ROWS * VOCAB + 2LL * BH;
    if ((long long)out_size >= need) {
        finalize_kernel<<<(2 * BH + 255) / 256, 256>>>(out);
    }
}

// round 9
// speedup vs baseline: 5.7584x; 1.1296x over previous
#include <cuda_runtime.h>
#include <cuda_bf16.h>
#include <math.h>

// Problem constants
#define EMB   1024
#define HID   1024
#define SEQ   128
#define BATCH 64
#define VOCAB 10000
#define VPAD  10112              // 79 * 128
#define BH    (BATCH * HID)      // 65536
#define ROWS  (SEQ * BATCH)      // 8192

// h layout: [slot][16 chunks][8KB swizzled (64 rows x 128B)]
#define H_SLOT_BYTES  131072
#define H_CHUNK_BYTES 8192
// tile layout (B/X/W): [128-row tile][16 chunks][16KB swizzled]
#define T_TILE_BYTES  262144
#define T_CHUNK_BYTES 16384

// Persistent recurrence config
#define NB_L0 32
#define NB_L1 64
#define NBLK  (NB_L0 + NB_L1)
#define A_BASE 131072            // smem offset of A stages (after weights)
#define L0_STAGE 16384
#define L1_STAGE 32768
#define RECUR_SMEM (131072 + 3 * 32768)   // 229376

// 128x128 GEMM (logits / xproj) config
#define NKT  16
#define OP_BYTES 16384
#define STAGE_BYTES (4 * OP_BYTES)
#define GEMM_SMEM (2 * STAGE_BYTES + 1024)   // 132096

typedef unsigned long long ull;

// ---------------- scratch (device globals) ----------------------------------
__device__ float g_xproj0[ROWS * HID];
__device__ unsigned g_bar;
// hidden states, bf16 hi/lo, chunk-swizzled; slot s = state after step s-1
__device__ __nv_bfloat16 g_h0h[(SEQ + 1) * BH];
__device__ __nv_bfloat16 g_h0l[(SEQ + 1) * BH];
__device__ __nv_bfloat16 g_h1h[(SEQ + 1) * BH];
__device__ __nv_bfloat16 g_h1l[(SEQ + 1) * BH];
// tiled split weights / gathered embedding
__device__ __nv_bfloat16 g_Bh[VPAD * HID];   // v_w tiles; pad rows stay zero
__device__ __nv_bfloat16 g_Bl[VPAD * HID];
__device__ __nv_bfloat16 g_Wh[HID * HID];    // wx0 tiles
__device__ __nv_bfloat16 g_Wl[HID * HID];
__device__ __nv_bfloat16 g_Xh[ROWS * HID];   // gathered emb tiles
__device__ __nv_bfloat16 g_Xl[ROWS * HID];

// ---------------- helpers -----------------------------------------------------
__device__ __forceinline__ unsigned smem_u32(const void* p) {
    unsigned a;
    asm("{ .reg .u64 t; cvta.to.shared.u64 t, %1; cvt.u32.u64 %0, t; }"
        : "=r"(a) : "l"(p));
    return a;
}

#define SWZ(o) ((o) ^ (((o) >> 3) & 0x70))

__device__ __forceinline__ unsigned hoff_bytes(int slot, int m, int k) {
    unsigned o = (unsigned)(m * 128 + (k & 63) * 2);
    return (unsigned)(slot * H_SLOT_BYTES + ((k >> 6) * H_CHUNK_BYTES)) + SWZ(o);
}

#define MBAR_INIT(addr, cnt) \
    asm volatile("mbarrier.init.shared.b64 [%0], %1;" \
                 :: "r"((unsigned)(addr)), "r"((unsigned)(cnt)) : "memory")
#define MBAR_EXPECT_TX(addr, tx) \
    asm volatile("mbarrier.arrive.expect_tx.shared.b64 _, [%0], %1;" \
                 :: "r"((unsigned)(addr)), "r"((unsigned)(tx)) : "memory")
#define MBAR_ARRIVE(addr) \
    asm volatile("mbarrier.arrive.shared.b64 _, [%0];" \
                 :: "r"((unsigned)(addr)) : "memory")
#define BAR_SYNC(id, n) \
    asm volatile("bar.sync %0, %1;" :: "r"(id), "r"(n) : "memory")

#define MBARRIER_WAIT_PARITY(addr, par) do {                                  \
    unsigned _m = (unsigned)(addr), _p = (unsigned)(par), _d;                 \
    asm volatile("{\n\t.reg .pred p;\n\t"                                     \
        "mbarrier.try_wait.parity.acquire.cta.shared::cta.b64 p, [%1], %2;\n\t" \
        "selp.b32 %0, 1, 0, p;\n\t}"                                          \
        : "=r"(_d) : "r"(_m), "r"(_p) : "memory");                            \
    if (!_d) {                                                                \
        asm volatile("{\n\t.reg .pred P1;\n\t"                                \
            "WL_%=:\n\t"                                                      \
            "mbarrier.try_wait.parity.acquire.cta.shared::cta.b64 P1, [%0], %1, 0x989680;\n\t" \
            "@P1 bra.uni WD_%=;\n\t"                                          \
            "bra.uni WL_%=;\n\t"                                              \
            "WD_%=:\n\t}" :: "r"(_m), "r"(_p) : "memory");                    \
    }                                                                         \
} while (0)

__device__ __forceinline__ void bulk_g2s(unsigned dst, const void* src,
                                         unsigned bytes, unsigned mbar) {
    asm volatile(
        "cp.async.bulk.shared::cluster.global.mbarrier::complete_tx::bytes "
        "[%0], [%1], %2, [%3];"
        :: "r"(dst), "l"(src), "r"(bytes), "r"(mbar) : "memory");
}

__device__ __forceinline__ void ldsm4(unsigned* r, unsigned addr) {
    asm volatile("ldmatrix.sync.aligned.m8n8.x4.shared.b16 {%0,%1,%2,%3}, [%4];"
                 : "=r"(r[0]), "=r"(r[1]), "=r"(r[2]), "=r"(r[3]) : "r"(addr));
}
__device__ __forceinline__ void mma16816(float* c, const unsigned* a,
                                         unsigned b0, unsigned b1) {
    asm volatile(
        "mma.sync.aligned.m16n8k16.row.col.f32.bf16.bf16.f32 "
        "{%0,%1,%2,%3}, {%4,%5,%6,%7}, {%8,%9}, {%0,%1,%2,%3};"
        : "+f"(c[0]), "+f"(c[1]), "+f"(c[2]), "+f"(c[3])
        : "r"(a[0]), "r"(a[1]), "r"(a[2]), "r"(a[3]), "r"(b0), "r"(b1));
}

__device__ __forceinline__ void split_bf16(float v, __nv_bfloat16& h,
                                           __nv_bfloat16& l) {
    h = __float2bfloat16(v);
    l = __float2bfloat16(v - __bfloat162float(h));
}

// ---------------- init: initial hidden -> slot 0 (swizzled) -------------------
__global__ void init_kernel(const float* __restrict__ hidden) {
    int i = blockIdx.x * blockDim.x + threadIdx.x;
    if (i == 0) g_bar = 0;
    if (i < BH) {
        int b = i >> 10, n = i & 1023;
        unsigned off = hoff_bytes(0, b, n);
        __nv_bfloat16 h, l;
        split_bf16(hidden[i], h, l);
        *(__nv_bfloat16*)((char*)g_h0h + off) = h;
        *(__nv_bfloat16*)((char*)g_h0l + off) = l;
        split_bf16(hidden[BH + i], h, l);
        *(__nv_bfloat16*)((char*)g_h1h + off) = h;
        *(__nv_bfloat16*)((char*)g_h1l + off) = l;
    }
}

// ---------------- convert fp32 rows -> split bf16 tiles (swizzled) ------------
__global__ __launch_bounds__(256) void conv_tiles_kernel(
    const float* __restrict__ src, const int* __restrict__ idx,
    __nv_bfloat16* __restrict__ dh, __nv_bfloat16* __restrict__ dl, int total4)
{
    int i = blockIdx.x * 256 + threadIdx.x;
    if (i >= total4) return;
    int e = i * 4;
    int r = e >> 10, k = e & 1023;
    int srow = idx ? idx[r] : r;
    float4 a = *(const float4*)(src + (size_t)srow * 1024 + k);
    __nv_bfloat16 h0, l0, h1, l1, h2, l2, h3, l3;
    split_bf16(a.x, h0, l0); split_bf16(a.y, h1, l1);
    split_bf16(a.z, h2, l2); split_bf16(a.w, h3, l3);
    unsigned o = (unsigned)((r & 127) * 128 + (k & 63) * 2);
    unsigned off = (unsigned)((r >> 7) * T_TILE_BYTES + (k >> 6) * T_CHUNK_BYTES)
                 + SWZ(o);
    *(__nv_bfloat162*)((char*)dh + off)     = __nv_bfloat162(h0, h1);
    *(__nv_bfloat162*)((char*)dh + off + 4) = __nv_bfloat162(h2, h3);
    *(__nv_bfloat162*)((char*)dl + off)     = __nv_bfloat162(l0, l1);
    *(__nv_bfloat162*)((char*)dl + off + 4) = __nv_bfloat162(l2, l3);
}

// ---------------- recur: layer-0 step (free-running warps) --------------------
__device__ __forceinline__ void step_l0(unsigned sb, unsigned mbf, unsigned mbe,
                                        int bid, int k, int u0, int tid,
                                        int lane, int wid)
{
    const char* a0h = (const char*)g_h0h + (size_t)k * H_SLOT_BYTES;
    const char* a0l = (const char*)g_h0l + (size_t)k * H_SLOT_BYTES;

    if (tid == 256) {
        // producer: gated only by empty-ring
        #pragma unroll 1
        for (int c = 0; c < 16; c++) {
            int uu = u0 + c, s = uu & 3, q = uu >> 2;
            if (q > 0) MBARRIER_WAIT_PARITY(mbe + s * 8, (q - 1) & 1);
            unsigned dst = sb + A_BASE + s * L0_STAGE;
            MBAR_EXPECT_TX(mbf + s * 8, 16384u);
            bulk_g2s(dst,        a0h + c * H_CHUNK_BYTES, 8192, mbf + s * 8);
            bulk_g2s(dst + 8192, a0l + c * H_CHUNK_BYTES, 8192, mbf + s * 8);
        }
    } else if (wid < 8) {
        const int wm = wid >> 1, wn = wid & 1;
        const unsigned xm    = (unsigned)((lane & 7) << 4);
        const unsigned aoffA = (unsigned)((wm * 16 + (lane & 7) + ((lane >> 3) & 1) * 8) * 128);
        const unsigned kbA   = (unsigned)((lane >> 4) * 16);
        const unsigned boffB = (unsigned)((wn * 16 + (lane & 7) + ((lane >> 4) << 3)) * 128);
        const unsigned kbB   = (unsigned)(((lane >> 3) & 1) * 16);

        float acc[2][4] = {};

        #pragma unroll 1
        for (int c = 0; c < 16; c++) {
            int uu = u0 + c, s = uu & 3, q = uu >> 2;
            MBARRIER_WAIT_PARITY(mbf + s * 8, q & 1);
            unsigned stg = sb + A_BASE + s * L0_STAGE;
            unsigned wbh = sb + (unsigned)(c * 4096);
            unsigned wbl = wbh + 65536;
            #pragma unroll
            for (int ks = 0; ks < 4; ks++) {
                unsigned kA = ((unsigned)(ks * 32) + kbA) ^ xm;
                unsigned kB = ((unsigned)(ks * 32) + kbB) ^ xm;
                unsigned ah[4], al[4], bh[4], bl[4];
                ldsm4(ah, stg + aoffA + kA);
                ldsm4(al, stg + 8192 + aoffA + kA);
                ldsm4(bh, wbh + boffB + kB);
                ldsm4(bl, wbl + boffB + kB);
                mma16816(acc[0], ah, bh[0], bh[1]);
                mma16816(acc[0], al, bh[0], bh[1]);
                mma16816(acc[0], ah, bl[0], bl[1]);
                mma16816(acc[0], al, bl[0], bl[1]);
                mma16816(acc[1], ah, bh[2], bh[3]);
                mma16816(acc[1], al, bh[2], bh[3]);
                mma16816(acc[1], ah, bl[2], bl[3]);
                mma16816(acc[1], al, bl[2], bl[3]);
            }
            if (lane == 0) MBAR_ARRIVE(mbe + s * 8);
        }

        // epilogue: + xproj, tanh, split, store slot k+1 (swizzled layout)
        int r = lane >> 2, c0 = 2 * (lane & 3);
        int mrow = wm * 16 + r;
        #pragma unroll
        for (int n2 = 0; n2 < 2; n2++) {
            int gn = bid * 32 + wn * 16 + n2 * 8 + c0;
            const float* xp0 = g_xproj0 + ((size_t)k * BATCH + mrow) * HID + gn;
            const float* xp1 = g_xproj0 + ((size_t)k * BATCH + mrow + 8) * HID + gn;
            float2 x0 = *(const float2*)xp0;
            float2 x1 = *(const float2*)xp1;
            float t0 = tanhf(acc[n2][0] + x0.x);
            float t1 = tanhf(acc[n2][1] + x0.y);
            float t2 = tanhf(acc[n2][2] + x1.x);
            float t3 = tanhf(acc[n2][3] + x1.y);
            __nv_bfloat16 h0, l0, h1, l1, h2, l2, h3, l3;
            split_bf16(t0, h0, l0); split_bf16(t1, h1, l1);
            split_bf16(t2, h2, l2); split_bf16(t3, h3, l3);
            unsigned o0 = hoff_bytes(k + 1, mrow, gn);
            unsigned o1 = hoff_bytes(k + 1, mrow + 8, gn);
            *(__nv_bfloat162*)((char*)g_h0h + o0) = __nv_bfloat162(h0, h1);
            *(__nv_bfloat162*)((char*)g_h0l + o0) = __nv_bfloat162(l0, l1);
            *(__nv_bfloat162*)((char*)g_h0h + o1) = __nv_bfloat162(h2, h3);
            *(__nv_bfloat162*)((char*)g_h0l + o1) = __nv_bfloat162(l2, l3);
        }
    }
}

// ---------------- recur: layer-1 step (free-running warps) --------------------
__device__ __forceinline__ void step_l1(char* smc, unsigned sb, unsigned mbf,
                                        unsigned mbe, int bid, int k, int u0,
                                        int tid, int lane, int wid,
                                        const float* __restrict__ bh1)
{
    const char* a0h = (const char*)g_h0h + (size_t)k * H_SLOT_BYTES;
    const char* a0l = (const char*)g_h0l + (size_t)k * H_SLOT_BYTES;
    const char* a1h = (const char*)g_h1h + (size_t)(k - 1) * H_SLOT_BYTES;
    const char* a1l = (const char*)g_h1l + (size_t)(k - 1) * H_SLOT_BYTES;

    if (tid == 256) {
        #pragma unroll 1
        for (int c = 0; c < 16; c++) {
            int uu = u0 + c, s = uu % 3, q = uu / 3;
            if (q > 0) MBARRIER_WAIT_PARITY(mbe + s * 8, (q - 1) & 1);
            unsigned dst = sb + A_BASE + s * L1_STAGE;
            MBAR_EXPECT_TX(mbf + s * 8, 32768u);
            bulk_g2s(dst,         a0h + c * H_CHUNK_BYTES, 8192, mbf + s * 8);
            bulk_g2s(dst + 8192,  a0l + c * H_CHUNK_BYTES, 8192, mbf + s * 8);
            bulk_g2s(dst + 16384, a1h + c * H_CHUNK_BYTES, 8192, mbf + s * 8);
            bulk_g2s(dst + 24576, a1l + c * H_CHUNK_BYTES, 8192, mbf + s * 8);
        }
    } else if (wid < 8) {
        const int wm = wid >> 1, kq = wid & 1;
        const unsigned xm    = (unsigned)((lane & 7) << 4);
        const unsigned aoffA = (unsigned)((wm * 16 + (lane & 7) + ((lane >> 3) & 1) * 8) * 128);
        const unsigned kbA   = (unsigned)((lane >> 4) * 16);
        const unsigned boffB = (unsigned)(((lane & 7) + ((lane >> 4) << 3)) * 128);
        const unsigned kbB   = (unsigned)(((lane >> 3) & 1) * 16);
        const unsigned aq    = (unsigned)(kq * 16384);

        float acc[2][4] = {};

        #pragma unroll 1
        for (int c = 0; c < 16; c++) {
            int uu = u0 + c, s = uu % 3, q = uu / 3;
            MBARRIER_WAIT_PARITY(mbf + s * 8, q & 1);
            unsigned stg = sb + A_BASE + s * L1_STAGE + aq;
            unsigned wbh = sb + (unsigned)(kq * 65536 + c * 2048);
            unsigned wbl = wbh + 32768;
            #pragma unroll
            for (int ks = 0; ks < 4; ks++) {
                unsigned kA = ((unsigned)(ks * 32) + kbA) ^ xm;
                unsigned kB = ((unsigned)(ks * 32) + kbB) ^ xm;
                unsigned ah[4], al[4], bh[4], bl[4];
                ldsm4(ah, stg + aoffA + kA);
                ldsm4(al, stg + 8192 + aoffA + kA);
                ldsm4(bh, wbh + boffB + kB);
                ldsm4(bl, wbl + boffB + kB);
                mma16816(acc[0], ah, bh[0], bh[1]);
                mma16816(acc[0], al, bh[0], bh[1]);
                mma16816(acc[0], ah, bl[0], bl[1]);
                mma16816(acc[0], al, bl[0], bl[1]);
                mma16816(acc[1], ah, bh[2], bh[3]);
                mma16816(acc[1], al, bh[2], bh[3]);
                mma16816(acc[1], ah, bl[2], bl[3]);
                mma16816(acc[1], al, bl[2], bl[3]);
            }
            if (lane == 0) MBAR_ARRIVE(mbe + s * 8);
        }

        // kq-pair reduction in the stage used by chunk 15 (safe: compute warps
        // all past chunk 15 after BAR 1; producer blocked at step barrier)
        float* red = (float*)(smc + A_BASE + ((u0 + 15) % 3) * L1_STAGE);
        int r = lane >> 2, c0 = 2 * (lane & 3);
        int mrow = wm * 16 + r;
        BAR_SYNC(1, 256);
        if (kq == 1) {
            #pragma unroll
            for (int n2 = 0; n2 < 2; n2++) {
                int col = n2 * 8 + c0;
                *(float2*)&red[mrow * 16 + col]       = make_float2(acc[n2][0], acc[n2][1]);
                *(float2*)&red[(mrow + 8) * 16 + col] = make_float2(acc[n2][2], acc[n2][3]);
            }
        }
        BAR_SYNC(1, 256);
        if (kq == 0) {
            int gnb = (bid - NB_L0) * 16;
            #pragma unroll
            for (int n2 = 0; n2 < 2; n2++) {
                int col = n2 * 8 + c0;
                int gn = gnb + col;
                float2 r0 = *(const float2*)&red[mrow * 16 + col];
                float2 r1 = *(const float2*)&red[(mrow + 8) * 16 + col];
                float2 bv = *(const float2*)(bh1 + gn);
                float t0 = tanhf(acc[n2][0] + r0.x + bv.x);
                float t1 = tanhf(acc[n2][1] + r0.y + bv.y);
                float t2 = tanhf(acc[n2][2] + r1.x + bv.x);
                float t3 = tanhf(acc[n2][3] + r1.y + bv.y);
                __nv_bfloat16 h0, l0, h1, l1, h2, l2, h3, l3;
                split_bf16(t0, h0, l0); split_bf16(t1, h1, l1);
                split_bf16(t2, h2, l2); split_bf16(t3, h3, l3);
                unsigned o0 = hoff_bytes(k, mrow, gn);
                unsigned o1 = hoff_bytes(k, mrow + 8, gn);
                *(__nv_bfloat162*)((char*)g_h1h + o0) = __nv_bfloat162(h0, h1);
                *(__nv_bfloat162*)((char*)g_h1l + o0) = __nv_bfloat162(l0, l1);
                *(__nv_bfloat162*)((char*)g_h1h + o1) = __nv_bfloat162(h2, h3);
                *(__nv_bfloat162*)((char*)g_h1l + o1) = __nv_bfloat162(l2, l3);
            }
        }
    }
}

// ---------------- persistent recurrence (288 threads: 8 compute + 1 producer) --
__global__ __launch_bounds__(288, 1) void recur_kernel(
    const float* __restrict__ wh0, const float* __restrict__ wx1,
    const float* __restrict__ wh1, const float* __restrict__ bh1)
{
    extern __shared__ char sm[];
    __shared__ ull s_full[4], s_empty[4];
    const int tid = threadIdx.x;
    const int lane = tid & 31, wid = tid >> 5;
    const int bid = blockIdx.x;
    const bool is_l1 = (bid >= NB_L0);
    const unsigned sb = smem_u32(sm);
    const unsigned mbf = smem_u32(&s_full[0]);
    const unsigned mbe = smem_u32(&s_empty[0]);

    if (tid == 0) {
        #pragma unroll
        for (int s = 0; s < 4; s++) {
            MBAR_INIT(mbf + s * 8, 1);
            MBAR_INIT(mbe + s * 8, 8);
        }
    }

    // ---- one-time weight preload: split bf16, swizzled 64k-chunks ----
    if (!is_l1) {
        int nb = bid * 32;
        for (int idx = tid; idx < 32 * 1024; idx += 288) {
            int n = idx >> 10, kk = idx & 1023;
            float w = wh0[(size_t)(nb + n) * HID + kk];
            __nv_bfloat16 h, l; split_bf16(w, h, l);
            int c = kk >> 6;
            unsigned off = SWZ((unsigned)(n * 128 + (kk & 63) * 2));
            *(__nv_bfloat16*)(sm + c * 4096 + off) = h;
            *(__nv_bfloat16*)(sm + 65536 + c * 4096 + off) = l;
        }
    } else {
        int nb = (bid - NB_L0) * 16;
        for (int idx = tid; idx < 2 * 16 * 1024; idx += 288) {
            int mat = idx >> 14;
            int rr = idx & 16383;
            int n = rr >> 10, kk = rr & 1023;
            const float* W = mat ? wh1 : wx1;
            float w = W[(size_t)(nb + n) * HID + kk];
            __nv_bfloat16 h, l; split_bf16(w, h, l);
            int c = kk >> 6;
            unsigned off = SWZ((unsigned)(n * 128 + (kk & 63) * 2));
            char* base = sm + mat * 65536;
            *(__nv_bfloat16*)(base + c * 2048 + off) = h;
            *(__nv_bfloat16*)(base + 32768 + c * 2048 + off) = l;
        }
    }
    __syncthreads();

    int u = 0;
    for (int k = 0; k <= SEQ; k++) {
        bool active = is_l1 ? (k >= 1) : (k < SEQ);
        if (active) {
            if (!is_l1) step_l0(sb, mbf, mbe, bid, k, u, tid, lane, wid);
            else        step_l1(sm, sb, mbf, mbe, bid, k, u, tid, lane, wid, bh1);
            u += 16;
        }

        if (k < SEQ) {
            __syncthreads();
            if (tid == 0) {
                asm volatile("red.release.gpu.global.add.u32 [%0], %1;"
                             :: "l"(&g_bar), "r"(1u) : "memory");
                unsigned target = (unsigned)(k + 1) * NBLK;
                unsigned v;
                do {
                    asm volatile("ld.global.acquire.gpu.b32 %0, [%1];"
                                 : "=r"(v) : "l"(&g_bar) : "memory");
                } while (v < target);
            }
            __syncthreads();
        }
    }
}

// ---------------- 128x128 tile compute (shared by logits/xproj) ----------------
template<bool FOURTH>
__device__ __forceinline__ void compute_chunk128(
    unsigned st, const unsigned* aoffA, const unsigned* aoffB,
    unsigned kbA, unsigned kbB, unsigned xm, float acc[4][4][4])
{
    #pragma unroll
    for (int ks = 0; ks < 4; ks++) {
        unsigned kA = ((unsigned)(ks * 32) + kbA) ^ xm;
        unsigned kB = ((unsigned)(ks * 32) + kbB) ^ xm;
        unsigned ah[4][4], al[4][4], bh[2][4], bl[2][4];
        #pragma unroll
        for (int mt = 0; mt < 4; mt++) {
            ldsm4(ah[mt], st + 0 * OP_BYTES + aoffA[mt] + kA);
            ldsm4(al[mt], st + 1 * OP_BYTES + aoffA[mt] + kA);
        }
        #pragma unroll
        for (int nt = 0; nt < 2; nt++) {
            ldsm4(bh[nt], st + 2 * OP_BYTES + aoffB[nt] + kB);
            ldsm4(bl[nt], st + 3 * OP_BYTES + aoffB[nt] + kB);
        }
        #pragma unroll
        for (int mt = 0; mt < 4; mt++) {
            #pragma unroll
            for (int n2 = 0; n2 < 2; n2++) {
                mma16816(acc[mt][n2 * 2],     ah[mt], bh[n2][0], bh[n2][1]);
                mma16816(acc[mt][n2 * 2],     al[mt], bh[n2][0], bh[n2][1]);
                mma16816(acc[mt][n2 * 2],     ah[mt], bl[n2][0], bl[n2][1]);
                if (FOURTH)
                    mma16816(acc[mt][n2 * 2], al[mt], bl[n2][0], bl[n2][1]);
                mma16816(acc[mt][n2 * 2 + 1], ah[mt], bh[n2][2], bh[n2][3]);
                mma16816(acc[mt][n2 * 2 + 1], al[mt], bh[n2][2], bh[n2][3]);
                mma16816(acc[mt][n2 * 2 + 1], ah[mt], bl[n2][2], bl[n2][3]);
                if (FOURTH)
                    mma16816(acc[mt][n2 * 2 + 1], al[mt], bl[n2][2], bl[n2][3]);
            }
        }
    }
}

__device__ __forceinline__ void tile_geometry(int lane, int wid,
                                              unsigned* aoffA, unsigned* aoffB,
                                              unsigned& kbA, unsigned& kbB,
                                              unsigned& xm)
{
    const int warp_m = (wid >> 2) * 64;
    const int warp_n = (wid & 3) * 32;
    xm  = (unsigned)((lane & 7) << 4);
    const int rowA = (lane & 7) + ((lane >> 3) & 1) * 8;
    kbA = (unsigned)((lane >> 4) * 16);
    const int rowB = (lane & 7) + ((lane >> 4) << 3);
    kbB = (unsigned)(((lane >> 3) & 1) * 16);
    #pragma unroll
    for (int mt = 0; mt < 4; mt++)
        aoffA[mt] = (unsigned)((warp_m + mt * 16 + rowA) * 128);
    #pragma unroll
    for (int nt = 0; nt < 2; nt++)
        aoffB[nt] = (unsigned)((warp_n + nt * 16 + rowB) * 128);
}

__device__ __forceinline__ void acc_to_smem(float* sm, int lane, int wid,
                                            const float acc[4][4][4])
{
    const int warp_m = (wid >> 2) * 64;
    const int warp_n = (wid & 3) * 32;
    const int r0l = lane >> 2;
    const int c0l = 2 * (lane & 3);
    #pragma unroll
    for (int mt = 0; mt < 4; mt++) {
        #pragma unroll
        for (int nt = 0; nt < 4; nt++) {
            int row = warp_m + mt * 16 + r0l;
            int col = warp_n + nt * 8 + c0l;
            sm[row * 129 + col]           = acc[mt][nt][0];
            sm[row * 129 + col + 1]       = acc[mt][nt][1];
            sm[(row + 8) * 129 + col]     = acc[mt][nt][2];
            sm[(row + 8) * 129 + col + 1] = acc[mt][nt][3];
        }
    }
}

// ---------------- logits kernel (288 threads, producer warp 8) ------------------
__global__ __launch_bounds__(288, 1) void logits_mma_kernel(
    const float* __restrict__ vb, float* __restrict__ out)
{
    extern __shared__ char dsm[];
    __shared__ ull s_full[2], s_empty[2];
    const int tid  = threadIdx.x;
    const int lane = tid & 31, wid = tid >> 5;
    const int mbase = blockIdx.y * 128;
    const int nbase = blockIdx.x * 128;
    const unsigned sb = (smem_u32(dsm) + 1023u) & ~1023u;
    const unsigned mbf = smem_u32(&s_full[0]);
    const unsigned mbe = smem_u32(&s_empty[0]);

    if (tid == 0) {
        MBAR_INIT(mbf, 1);     MBAR_INIT(mbf + 8, 1);
        MBAR_INIT(mbe, 8);     MBAR_INIT(mbe + 8, 8);
    }
    __syncthreads();

    const int s0 = mbase / 64 + 1;      // h1 slots
    const char* ahb = (const char*)g_h1h;
    const char* alb = (const char*)g_h1l;
    const char* bhb = (const char*)g_Bh + (size_t)(nbase >> 7) * T_TILE_BYTES;
    const char* blb = (const char*)g_Bl + (size_t)(nbase >> 7) * T_TILE_BYTES;

    if (tid == 256) {
        #pragma unroll 1
        for (int c = 0; c < NKT; c++) {
            int s = c & 1, q = c >> 1;
            if (q > 0) MBARRIER_WAIT_PARITY(mbe + s * 8, (q - 1) & 1);
            unsigned dst = sb + (unsigned)(s * STAGE_BYTES);
            MBAR_EXPECT_TX(mbf + s * 8, 65536u);
            bulk_g2s(dst,                   ahb + (size_t)s0 * H_SLOT_BYTES + c * H_CHUNK_BYTES, 8192, mbf + s * 8);
            bulk_g2s(dst + 8192,            ahb + (size_t)(s0 + 1) * H_SLOT_BYTES + c * H_CHUNK_BYTES, 8192, mbf + s * 8);
            bulk_g2s(dst + OP_BYTES,        alb + (size_t)s0 * H_SLOT_BYTES + c * H_CHUNK_BYTES, 8192, mbf + s * 8);
            bulk_g2s(dst + OP_BYTES + 8192, alb + (size_t)(s0 + 1) * H_SLOT_BYTES + c * H_CHUNK_BYTES, 8192, mbf + s * 8);
            bulk_g2s(dst + 2 * OP_BYTES,    bhb + c * T_CHUNK_BYTES, 16384, mbf + s * 8);
            bulk_g2s(dst + 3 * OP_BYTES,    blb + c * T_CHUNK_BYTES, 16384, mbf + s * 8);
        }
    } else if (wid < 8) {
        unsigned aoffA[4], aoffB[2], kbA, kbB, xm;
        tile_geometry(lane, wid, aoffA, aoffB, kbA, kbB, xm);
        float acc[4][4][4] = {};

        #pragma unroll 1
        for (int c = 0; c < NKT; c++) {
            int s = c & 1, q = c >> 1;
            MBARRIER_WAIT_PARITY(mbf + s * 8, q & 1);
            unsigned st = sb + (unsigned)(s * STAGE_BYTES);
            compute_chunk128<false>(st, aoffA, aoffB, kbA, kbB, xm, acc);
            if (lane == 0) MBAR_ARRIVE(mbe + s * 8);
        }

        BAR_SYNC(1, 256);
        float* sm = (float*)dsm;
        acc_to_smem(sm, lane, wid, acc);
        BAR_SYNC(1, 256);

        const int c4 = tid & 31;
        const int rg = tid >> 5;
        const int n0 = nbase + c4 * 4;
        float b0 = (n0 + 0 < VOCAB) ? vb[n0 + 0] : 0.f;
        float b1 = (n0 + 1 < VOCAB) ? vb[n0 + 1] : 0.f;
        float b2 = (n0 + 2 < VOCAB) ? vb[n0 + 2] : 0.f;
        float b3 = (n0 + 3 < VOCAB) ? vb[n0 + 3] : 0.f;
        const bool full = (nbase + 128 <= VOCAB);

        #pragma unroll 4
        for (int it = 0; it < 16; it++) {
            int row = it * 8 + rg;
            const float* sr = sm + row * 129 + c4 * 4;
            float4 v = make_float4(sr[0] + b0, sr[1] + b1, sr[2] + b2, sr[3] + b3);
            float* orow = out + (size_t)(mbase + row) * VOCAB;
            if (full) {
                *(float4*)(orow + n0) = v;
            } else {
                if (n0 + 0 < VOCAB) orow[n0 + 0] = v.x;
                if (n0 + 1 < VOCAB) orow[n0 + 1] = v.y;
                if (n0 + 2 < VOCAB) orow[n0 + 2] = v.z;
                if (n0 + 3 < VOCAB) orow[n0 + 3] = v.w;
            }
        }
    }
}

// ---------------- xproj kernel (288 threads, producer warp 8) -------------------
__global__ __launch_bounds__(288, 1) void xproj_mma_kernel(
    const float* __restrict__ bh0)
{
    extern __shared__ char dsm[];
    __shared__ ull s_full[2], s_empty[2];
    const int tid  = threadIdx.x;
    const int lane = tid & 31, wid = tid >> 5;
    const int mbase = blockIdx.y * 128;
    const int nbase = blockIdx.x * 128;
    const unsigned sb = (smem_u32(dsm) + 1023u) & ~1023u;
    const unsigned mbf = smem_u32(&s_full[0]);
    const unsigned mbe = smem_u32(&s_empty[0]);

    if (tid == 0) {
        MBAR_INIT(mbf, 1);     MBAR_INIT(mbf + 8, 1);
        MBAR_INIT(mbe, 8);     MBAR_INIT(mbe + 8, 8);
    }
    __syncthreads();

    const char* ahb = (const char*)g_Xh + (size_t)(mbase >> 7) * T_TILE_BYTES;
    const char* alb = (const char*)g_Xl + (size_t)(mbase >> 7) * T_TILE_BYTES;
    const char* bhb = (const char*)g_Wh + (size_t)(nbase >> 7) * T_TILE_BYTES;
    const char* blb = (const char*)g_Wl + (size_t)(nbase >> 7) * T_TILE_BYTES;

    if (tid == 256) {
        #pragma unroll 1
        for (int c = 0; c < NKT; c++) {
            int s = c & 1, q = c >> 1;
            if (q > 0) MBARRIER_WAIT_PARITY(mbe + s * 8, (q - 1) & 1);
            unsigned dst = sb + (unsigned)(s * STAGE_BYTES);
            MBAR_EXPECT_TX(mbf + s * 8, 65536u);
            bulk_g2s(dst,                ahb + c * T_CHUNK_BYTES, 16384, mbf + s * 8);
            bulk_g2s(dst + OP_BYTES,     alb + c * T_CHUNK_BYTES, 16384, mbf + s * 8);
            bulk_g2s(dst + 2 * OP_BYTES, bhb + c * T_CHUNK_BYTES, 16384, mbf + s * 8);
            bulk_g2s(dst + 3 * OP_BYTES, blb + c * T_CHUNK_BYTES, 16384, mbf + s * 8);
        }
    } else if (wid < 8) {
        unsigned aoffA[4], aoffB[2], kbA, kbB, xm;
        tile_geometry(lane, wid, aoffA, aoffB, kbA, kbB, xm);
        float acc[4][4][4] = {};

        #pragma unroll 1
        for (int c = 0; c < NKT; c++) {
            int s = c & 1, q = c >> 1;
            MBARRIER_WAIT_PARITY(mbf + s * 8, q & 1);
            unsigned st = sb + (unsigned)(s * STAGE_BYTES);
            compute_chunk128<true>(st, aoffA, aoffB, kbA, kbB, xm, acc);
            if (lane == 0) MBAR_ARRIVE(mbe + s * 8);
        }

        BAR_SYNC(1, 256);
        float* sm = (float*)dsm;
        acc_to_smem(sm, lane, wid, acc);
        BAR_SYNC(1, 256);

        const int c4 = tid & 31;
        const int rg = tid >> 5;
        const int n0 = nbase + c4 * 4;
        float4 bb = *(const float4*)(bh0 + n0);

        #pragma unroll 4
        for (int it = 0; it < 16; it++) {
            int row = it * 8 + rg;
            const float* sr = sm + row * 129 + c4 * 4;
            float4 v = make_float4(sr[0] + bb.x, sr[1] + bb.y,
                                   sr[2] + bb.z, sr[3] + bb.w);
            *(float4*)(g_xproj0 + (size_t)(mbase + row) * HID + n0) = v;
        }
    }
}

// ---------------- finalize: hidden_final = hi + lo at slot SEQ ------------------
__global__ void finalize_kernel(float* __restrict__ out) {
    int i = blockIdx.x * blockDim.x + threadIdx.x;
    if (i < 2 * BH) {
        int l = i >> 16;                 // BH = 65536
        int r = i & (BH - 1);
        int b = r >> 10, n = r & 1023;
        unsigned off = hoff_bytes(SEQ, b, n);
        const char* hs = l ? (const char*)g_h1h : (const char*)g_h0h;
        const char* ls = l ? (const char*)g_h1l : (const char*)g_h0l;
        out[(size_t)ROWS * VOCAB + i] =
            __bfloat162float(*(const __nv_bfloat16*)(hs + off)) +
            __bfloat162float(*(const __nv_bfloat16*)(ls + off));
    }
}

// ---------------- launcher --------------------------------------------------------
extern "C" void kernel_launch(void* const* d_in, const int* in_sizes, int n_in,
                              void* d_out, int out_size)
{
    const int*   inputs    = (const int*)  d_in[0];
    const float* hidden    = (const float*)d_in[1];
    const float* embedding = (const float*)d_in[2];
    const float* wx0       = (const float*)d_in[3];
    const float* wh0       = (const float*)d_in[4];
    const float* bh0       = (const float*)d_in[5];
    const float* wx1       = (const float*)d_in[6];
    const float* wh1       = (const float*)d_in[7];
    const float* bh1       = (const float*)d_in[8];
    const float* v_w       = (const float*)d_in[9];
    const float* v_b       = (const float*)d_in[10];
    float* out = (float*)d_out;

    static bool attr_set = false;
    if (!attr_set) {
        cudaFuncSetAttribute(recur_kernel,
                             cudaFuncAttributeMaxDynamicSharedMemorySize,
                             RECUR_SMEM);
        cudaFuncSetAttribute(logits_mma_kernel,
                             cudaFuncAttributeMaxDynamicSharedMemorySize,
                             GEMM_SMEM);
        cudaFuncSetAttribute(xproj_mma_kernel,
                             cudaFuncAttributeMaxDynamicSharedMemorySize,
                             GEMM_SMEM);
        attr_set = true;
    }

    __nv_bfloat16 *dBh, *dBl, *dWh, *dWl, *dXh, *dXl;
    cudaGetSymbolAddress((void**)&dBh, g_Bh);
    cudaGetSymbolAddress((void**)&dBl, g_Bl);
    cudaGetSymbolAddress((void**)&dWh, g_Wh);
    cudaGetSymbolAddress((void**)&dWl, g_Wl);
    cudaGetSymbolAddress((void**)&dXh, g_Xh);
    cudaGetSymbolAddress((void**)&dXl, g_Xl);

    init_kernel<<<(BH + 255) / 256, 256>>>(hidden);
    conv_tiles_kernel<<<(VOCAB * HID / 4 + 255) / 256, 256>>>(
        v_w, 0, dBh, dBl, VOCAB * HID / 4);
    conv_tiles_kernel<<<(HID * HID / 4 + 255) / 256, 256>>>(
        wx0, 0, dWh, dWl, HID * HID / 4);
    conv_tiles_kernel<<<(ROWS * HID / 4 + 255) / 256, 256>>>(
        embedding, inputs, dXh, dXl, ROWS * HID / 4);
    xproj_mma_kernel<<<dim3(HID / 128, ROWS / 128), 288, GEMM_SMEM>>>(bh0);
    recur_kernel<<<NBLK, 288, RECUR_SMEM>>>(wh0, wx1, wh1, bh1);
    logits_mma_kernel<<<dim3(VPAD / 128, ROWS / 128), 288, GEMM_SMEM>>>(v_b, out);

    long long need = (long long)ROWS * VOCAB + 2LL * BH;
    if ((long long)out_size >= need) {
        finalize_kernel<<<(2 * BH + 255) / 256, 256>>>(out);
    }
}

// round 10
// speedup vs baseline: 6.9833x; 1.2127x over previous
#include <cuda_runtime.h>
#include <cuda_bf16.h>
#include <math.h>

// Problem constants
#define EMB   1024
#define HID   1024
#define SEQ   128
#define BATCH 64
#define VOCAB 10000
#define VPAD  10112              // 79 * 128
#define BH    (BATCH * HID)      // 65536
#define ROWS  (SEQ * BATCH)      // 8192

// h layout: [slot][16 chunks][8KB swizzled (64 rows x 128B)]
#define H_SLOT_BYTES  131072
#define H_CHUNK_BYTES 8192
// tile layout (B/X/W): [128-row tile][16 chunks][16KB swizzled]
#define T_TILE_BYTES  262144
#define T_CHUNK_BYTES 16384

// Fused persistent kernel config
#define NB_L0 32
#define NB_L1 64
#define NBLK  (NB_L0 + NB_L1)    // 96 recurrence blocks
#define NGRID 148                // + 52 logits worker blocks
#define NT_N  79
#define NTILES (64 * NT_N)       // 5056 logits tiles
#define A_BASE 131072            // recur: A stages after weights
#define L0_STAGE 16384
#define L1_STAGE 32768
#define RECUR_SMEM (131072 + 3 * 32768)   // 229376

// 128x128 GEMM config
#define NKT  16
#define OP_BYTES 16384
#define STAGE_BYTES (4 * OP_BYTES)
#define GEMM_SMEM (2 * STAGE_BYTES + 1024)

typedef unsigned long long ull;

// ---------------- scratch (device globals) ----------------------------------
__device__ float g_xproj0[ROWS * HID];
__device__ unsigned g_bar;
__device__ unsigned g_tileq;
// hidden states, bf16 hi/lo, chunk-swizzled; slot s = state after step s-1
__device__ __nv_bfloat16 g_h0h[(SEQ + 1) * BH];
__device__ __nv_bfloat16 g_h0l[(SEQ + 1) * BH];
__device__ __nv_bfloat16 g_h1h[(SEQ + 1) * BH];
__device__ __nv_bfloat16 g_h1l[(SEQ + 1) * BH];
// tiled split weights / gathered embedding
__device__ __nv_bfloat16 g_Bh[VPAD * HID];   // v_w tiles; pad rows stay zero
__device__ __nv_bfloat16 g_Bl[VPAD * HID];
__device__ __nv_bfloat16 g_Wh[HID * HID];    // wx0 tiles
__device__ __nv_bfloat16 g_Wl[HID * HID];
__device__ __nv_bfloat16 g_Xh[ROWS * HID];   // gathered emb tiles
__device__ __nv_bfloat16 g_Xl[ROWS * HID];

// ---------------- helpers -----------------------------------------------------
__device__ __forceinline__ unsigned smem_u32(const void* p) {
    unsigned a;
    asm("{ .reg .u64 t; cvta.to.shared.u64 t, %1; cvt.u32.u64 %0, t; }"
        : "=r"(a) : "l"(p));
    return a;
}

#define SWZ(o) ((o) ^ (((o) >> 3) & 0x70))

__device__ __forceinline__ unsigned hoff_bytes(int slot, int m, int k) {
    unsigned o = (unsigned)(m * 128 + (k & 63) * 2);
    return (unsigned)(slot * H_SLOT_BYTES + ((k >> 6) * H_CHUNK_BYTES)) + SWZ(o);
}

#define MBAR_INIT(addr, cnt) \
    asm volatile("mbarrier.init.shared.b64 [%0], %1;" \
                 :: "r"((unsigned)(addr)), "r"((unsigned)(cnt)) : "memory")
#define MBAR_EXPECT_TX(addr, tx) \
    asm volatile("mbarrier.arrive.expect_tx.shared.b64 _, [%0], %1;" \
                 :: "r"((unsigned)(addr)), "r"((unsigned)(tx)) : "memory")
#define MBAR_ARRIVE(addr) \
    asm volatile("mbarrier.arrive.shared.b64 _, [%0];" \
                 :: "r"((unsigned)(addr)) : "memory")

#define MBARRIER_WAIT_PARITY(addr, par) do {                                  \
    unsigned _m = (unsigned)(addr), _p = (unsigned)(par), _d;                 \
    asm volatile("{\n\t.reg .pred p;\n\t"                                     \
        "mbarrier.try_wait.parity.acquire.cta.shared::cta.b64 p, [%1], %2;\n\t" \
        "selp.b32 %0, 1, 0, p;\n\t}"                                          \
        : "=r"(_d) : "r"(_m), "r"(_p) : "memory");                            \
    if (!_d) {                                                                \
        asm volatile("{\n\t.reg .pred P1;\n\t"                                \
            "WL_%=:\n\t"                                                      \
            "mbarrier.try_wait.parity.acquire.cta.shared::cta.b64 P1, [%0], %1, 0x989680;\n\t" \
            "@P1 bra.uni WD_%=;\n\t"                                          \
            "bra.uni WL_%=;\n\t"                                              \
            "WD_%=:\n\t}" :: "r"(_m), "r"(_p) : "memory");                    \
    }                                                                         \
} while (0)

__device__ __forceinline__ void bulk_g2s(unsigned dst, const void* src,
                                         unsigned bytes, unsigned mbar) {
    asm volatile(
        "cp.async.bulk.shared::cluster.global.mbarrier::complete_tx::bytes "
        "[%0], [%1], %2, [%3];"
        :: "r"(dst), "l"(src), "r"(bytes), "r"(mbar) : "memory");
}

__device__ __forceinline__ void ldsm4(unsigned* r, unsigned addr) {
    asm volatile("ldmatrix.sync.aligned.m8n8.x4.shared.b16 {%0,%1,%2,%3}, [%4];"
                 : "=r"(r[0]), "=r"(r[1]), "=r"(r[2]), "=r"(r[3]) : "r"(addr));
}
__device__ __forceinline__ void mma16816(float* c, const unsigned* a,
                                         unsigned b0, unsigned b1) {
    asm volatile(
        "mma.sync.aligned.m16n8k16.row.col.f32.bf16.bf16.f32 "
        "{%0,%1,%2,%3}, {%4,%5,%6,%7}, {%8,%9}, {%0,%1,%2,%3};"
        : "+f"(c[0]), "+f"(c[1]), "+f"(c[2]), "+f"(c[3])
        : "r"(a[0]), "r"(a[1]), "r"(a[2]), "r"(a[3]), "r"(b0), "r"(b1));
}

__device__ __forceinline__ void split_bf16(float v, __nv_bfloat16& h,
                                           __nv_bfloat16& l) {
    h = __float2bfloat16(v);
    l = __float2bfloat16(v - __bfloat162float(h));
}

// ---------------- init: initial hidden -> slot 0 (swizzled) -------------------
__global__ void init_kernel(const float* __restrict__ hidden) {
    int i = blockIdx.x * blockDim.x + threadIdx.x;
    if (i == 0) { g_bar = 0; g_tileq = 0; }
    if (i < BH) {
        int b = i >> 10, n = i & 1023;
        unsigned off = hoff_bytes(0, b, n);
        __nv_bfloat16 h, l;
        split_bf16(hidden[i], h, l);
        *(__nv_bfloat16*)((char*)g_h0h + off) = h;
        *(__nv_bfloat16*)((char*)g_h0l + off) = l;
        split_bf16(hidden[BH + i], h, l);
        *(__nv_bfloat16*)((char*)g_h1h + off) = h;
        *(__nv_bfloat16*)((char*)g_h1l + off) = l;
    }
}

// ---------------- convert fp32 rows -> split bf16 tiles (swizzled) ------------
__global__ __launch_bounds__(256) void conv_tiles_kernel(
    const float* __restrict__ src, const int* __restrict__ idx,
    __nv_bfloat16* __restrict__ dh, __nv_bfloat16* __restrict__ dl, int total4)
{
    int i = blockIdx.x * 256 + threadIdx.x;
    if (i >= total4) return;
    int e = i * 4;
    int r = e >> 10, k = e & 1023;
    int srow = idx ? idx[r] : r;
    float4 a = *(const float4*)(src + (size_t)srow * 1024 + k);
    __nv_bfloat16 h0, l0, h1, l1, h2, l2, h3, l3;
    split_bf16(a.x, h0, l0); split_bf16(a.y, h1, l1);
    split_bf16(a.z, h2, l2); split_bf16(a.w, h3, l3);
    unsigned o = (unsigned)((r & 127) * 128 + (k & 63) * 2);
    unsigned off = (unsigned)((r >> 7) * T_TILE_BYTES + (k >> 6) * T_CHUNK_BYTES)
                 + SWZ(o);
    *(__nv_bfloat162*)((char*)dh + off)     = __nv_bfloat162(h0, h1);
    *(__nv_bfloat162*)((char*)dh + off + 4) = __nv_bfloat162(h2, h3);
    *(__nv_bfloat162*)((char*)dl + off)     = __nv_bfloat162(l0, l1);
    *(__nv_bfloat162*)((char*)dl + off + 4) = __nv_bfloat162(l2, l3);
}

// ---------------- recur: layer-0 step (3-product split bf16) ------------------
__device__ __forceinline__ void step_l0(unsigned sb, unsigned mbf, unsigned mbe,
                                        int bid, int k, int u0, int tid,
                                        int lane, int wid)
{
    const char* a0h = (const char*)g_h0h + (size_t)k * H_SLOT_BYTES;
    const char* a0l = (const char*)g_h0l + (size_t)k * H_SLOT_BYTES;

    if (tid == 256) {
        #pragma unroll 1
        for (int c = 0; c < 16; c++) {
            int uu = u0 + c, s = uu & 3, q = uu >> 2;
            if (q > 0) MBARRIER_WAIT_PARITY(mbe + s * 8, (q - 1) & 1);
            unsigned dst = sb + A_BASE + s * L0_STAGE;
            MBAR_EXPECT_TX(mbf + s * 8, 16384u);
            bulk_g2s(dst,        a0h + c * H_CHUNK_BYTES, 8192, mbf + s * 8);
            bulk_g2s(dst + 8192, a0l + c * H_CHUNK_BYTES, 8192, mbf + s * 8);
        }
    } else if (wid < 8) {
        const int wm = wid >> 1, wn = wid & 1;
        const unsigned xm    = (unsigned)((lane & 7) << 4);
        const unsigned aoffA = (unsigned)((wm * 16 + (lane & 7) + ((lane >> 3) & 1) * 8) * 128);
        const unsigned kbA   = (unsigned)((lane >> 4) * 16);
        const unsigned boffB = (unsigned)((wn * 16 + (lane & 7) + ((lane >> 4) << 3)) * 128);
        const unsigned kbB   = (unsigned)(((lane >> 3) & 1) * 16);

        float acc[2][4] = {};

        #pragma unroll 1
        for (int c = 0; c < 16; c++) {
            int uu = u0 + c, s = uu & 3, q = uu >> 2;
            MBARRIER_WAIT_PARITY(mbf + s * 8, q & 1);
            unsigned stg = sb + A_BASE + s * L0_STAGE;
            unsigned wbh = sb + (unsigned)(c * 4096);
            unsigned wbl = wbh + 65536;
            #pragma unroll
            for (int ks = 0; ks < 4; ks++) {
                unsigned kA = ((unsigned)(ks * 32) + kbA) ^ xm;
                unsigned kB = ((unsigned)(ks * 32) + kbB) ^ xm;
                unsigned ah[4], al[4], bh[4], bl[4];
                ldsm4(ah, stg + aoffA + kA);
                ldsm4(al, stg + 8192 + aoffA + kA);
                ldsm4(bh, wbh + boffB + kB);
                ldsm4(bl, wbl + boffB + kB);
                mma16816(acc[0], ah, bh[0], bh[1]);
                mma16816(acc[0], al, bh[0], bh[1]);
                mma16816(acc[0], ah, bl[0], bl[1]);
                mma16816(acc[1], ah, bh[2], bh[3]);
                mma16816(acc[1], al, bh[2], bh[3]);
                mma16816(acc[1], ah, bl[2], bl[3]);
            }
            if (lane == 0) MBAR_ARRIVE(mbe + s * 8);
        }

        int r = lane >> 2, c0 = 2 * (lane & 3);
        int mrow = wm * 16 + r;
        #pragma unroll
        for (int n2 = 0; n2 < 2; n2++) {
            int gn = bid * 32 + wn * 16 + n2 * 8 + c0;
            const float* xp0 = g_xproj0 + ((size_t)k * BATCH + mrow) * HID + gn;
            const float* xp1 = g_xproj0 + ((size_t)k * BATCH + mrow + 8) * HID + gn;
            float2 x0 = *(const float2*)xp0;
            float2 x1 = *(const float2*)xp1;
            float t0 = tanhf(acc[n2][0] + x0.x);
            float t1 = tanhf(acc[n2][1] + x0.y);
            float t2 = tanhf(acc[n2][2] + x1.x);
            float t3 = tanhf(acc[n2][3] + x1.y);
            __nv_bfloat16 h0, l0, h1, l1, h2, l2, h3, l3;
            split_bf16(t0, h0, l0); split_bf16(t1, h1, l1);
            split_bf16(t2, h2, l2); split_bf16(t3, h3, l3);
            unsigned o0 = hoff_bytes(k + 1, mrow, gn);
            unsigned o1 = hoff_bytes(k + 1, mrow + 8, gn);
            *(__nv_bfloat162*)((char*)g_h0h + o0) = __nv_bfloat162(h0, h1);
            *(__nv_bfloat162*)((char*)g_h0l + o0) = __nv_bfloat162(l0, l1);
            *(__nv_bfloat162*)((char*)g_h0h + o1) = __nv_bfloat162(h2, h3);
            *(__nv_bfloat162*)((char*)g_h0l + o1) = __nv_bfloat162(l2, l3);
        }
    }
}

// ---------------- recur: layer-1 step (3-product split bf16) ------------------
#define BAR_SYNC(id, n) \
    asm volatile("bar.sync %0, %1;" :: "r"(id), "r"(n) : "memory")

__device__ __forceinline__ void step_l1(char* smc, unsigned sb, unsigned mbf,
                                        unsigned mbe, int bid, int k, int u0,
                                        int tid, int lane, int wid,
                                        const float* __restrict__ bh1)
{
    const char* a0h = (const char*)g_h0h + (size_t)k * H_SLOT_BYTES;
    const char* a0l = (const char*)g_h0l + (size_t)k * H_SLOT_BYTES;
    const char* a1h = (const char*)g_h1h + (size_t)(k - 1) * H_SLOT_BYTES;
    const char* a1l = (const char*)g_h1l + (size_t)(k - 1) * H_SLOT_BYTES;

    if (tid == 256) {
        #pragma unroll 1
        for (int c = 0; c < 16; c++) {
            int uu = u0 + c, s = uu % 3, q = uu / 3;
            if (q > 0) MBARRIER_WAIT_PARITY(mbe + s * 8, (q - 1) & 1);
            unsigned dst = sb + A_BASE + s * L1_STAGE;
            MBAR_EXPECT_TX(mbf + s * 8, 32768u);
            bulk_g2s(dst,         a0h + c * H_CHUNK_BYTES, 8192, mbf + s * 8);
            bulk_g2s(dst + 8192,  a0l + c * H_CHUNK_BYTES, 8192, mbf + s * 8);
            bulk_g2s(dst + 16384, a1h + c * H_CHUNK_BYTES, 8192, mbf + s * 8);
            bulk_g2s(dst + 24576, a1l + c * H_CHUNK_BYTES, 8192, mbf + s * 8);
        }
    } else if (wid < 8) {
        const int wm = wid >> 1, kq = wid & 1;
        const unsigned xm    = (unsigned)((lane & 7) << 4);
        const unsigned aoffA = (unsigned)((wm * 16 + (lane & 7) + ((lane >> 3) & 1) * 8) * 128);
        const unsigned kbA   = (unsigned)((lane >> 4) * 16);
        const unsigned boffB = (unsigned)(((lane & 7) + ((lane >> 4) << 3)) * 128);
        const unsigned kbB   = (unsigned)(((lane >> 3) & 1) * 16);
        const unsigned aq    = (unsigned)(kq * 16384);

        float acc[2][4] = {};

        #pragma unroll 1
        for (int c = 0; c < 16; c++) {
            int uu = u0 + c, s = uu % 3, q = uu / 3;
            MBARRIER_WAIT_PARITY(mbf + s * 8, q & 1);
            unsigned stg = sb + A_BASE + s * L1_STAGE + aq;
            unsigned wbh = sb + (unsigned)(kq * 65536 + c * 2048);
            unsigned wbl = wbh + 32768;
            #pragma unroll
            for (int ks = 0; ks < 4; ks++) {
                unsigned kA = ((unsigned)(ks * 32) + kbA) ^ xm;
                unsigned kB = ((unsigned)(ks * 32) + kbB) ^ xm;
                unsigned ah[4], al[4], bh[4], bl[4];
                ldsm4(ah, stg + aoffA + kA);
                ldsm4(al, stg + 8192 + aoffA + kA);
                ldsm4(bh, wbh + boffB + kB);
                ldsm4(bl, wbl + boffB + kB);
                mma16816(acc[0], ah, bh[0], bh[1]);
                mma16816(acc[0], al, bh[0], bh[1]);
                mma16816(acc[0], ah, bl[0], bl[1]);
                mma16816(acc[1], ah, bh[2], bh[3]);
                mma16816(acc[1], al, bh[2], bh[3]);
                mma16816(acc[1], ah, bl[2], bl[3]);
            }
            if (lane == 0) MBAR_ARRIVE(mbe + s * 8);
        }

        float* red = (float*)(smc + A_BASE + ((u0 + 15) % 3) * L1_STAGE);
        int r = lane >> 2, c0 = 2 * (lane & 3);
        int mrow = wm * 16 + r;
        BAR_SYNC(1, 256);
        if (kq == 1) {
            #pragma unroll
            for (int n2 = 0; n2 < 2; n2++) {
                int col = n2 * 8 + c0;
                *(float2*)&red[mrow * 16 + col]       = make_float2(acc[n2][0], acc[n2][1]);
                *(float2*)&red[(mrow + 8) * 16 + col] = make_float2(acc[n2][2], acc[n2][3]);
            }
        }
        BAR_SYNC(1, 256);
        if (kq == 0) {
            int gnb = (bid - NB_L0) * 16;
            #pragma unroll
            for (int n2 = 0; n2 < 2; n2++) {
                int col = n2 * 8 + c0;
                int gn = gnb + col;
                float2 r0 = *(const float2*)&red[mrow * 16 + col];
                float2 r1 = *(const float2*)&red[(mrow + 8) * 16 + col];
                float2 bv = *(const float2*)(bh1 + gn);
                float t0 = tanhf(acc[n2][0] + r0.x + bv.x);
                float t1 = tanhf(acc[n2][1] + r0.y + bv.y);
                float t2 = tanhf(acc[n2][2] + r1.x + bv.x);
                float t3 = tanhf(acc[n2][3] + r1.y + bv.y);
                __nv_bfloat16 h0, l0, h1, l1, h2, l2, h3, l3;
                split_bf16(t0, h0, l0); split_bf16(t1, h1, l1);
                split_bf16(t2, h2, l2); split_bf16(t3, h3, l3);
                unsigned o0 = hoff_bytes(k, mrow, gn);
                unsigned o1 = hoff_bytes(k, mrow + 8, gn);
                *(__nv_bfloat162*)((char*)g_h1h + o0) = __nv_bfloat162(h0, h1);
                *(__nv_bfloat162*)((char*)g_h1l + o0) = __nv_bfloat162(l0, l1);
                *(__nv_bfloat162*)((char*)g_h1h + o1) = __nv_bfloat162(h2, h3);
                *(__nv_bfloat162*)((char*)g_h1l + o1) = __nv_bfloat162(l2, l3);
            }
        }
    }
}

// ---------------- shared 128x128 GEMM machinery --------------------------------
template<bool FOURTH>
__device__ __forceinline__ void compute_chunk128(
    unsigned st, const unsigned* aoffA, const unsigned* aoffB,
    unsigned kbA, unsigned kbB, unsigned xm, float acc[4][4][4])
{
    #pragma unroll
    for (int ks = 0; ks < 4; ks++) {
        unsigned kA = ((unsigned)(ks * 32) + kbA) ^ xm;
        unsigned kB = ((unsigned)(ks * 32) + kbB) ^ xm;
        unsigned ah[4][4], al[4][4], bh[2][4], bl[2][4];
        #pragma unroll
        for (int mt = 0; mt < 4; mt++) {
            ldsm4(ah[mt], st + 0 * OP_BYTES + aoffA[mt] + kA);
            ldsm4(al[mt], st + 1 * OP_BYTES + aoffA[mt] + kA);
        }
        #pragma unroll
        for (int nt = 0; nt < 2; nt++) {
            ldsm4(bh[nt], st + 2 * OP_BYTES + aoffB[nt] + kB);
            ldsm4(bl[nt], st + 3 * OP_BYTES + aoffB[nt] + kB);
        }
        #pragma unroll
        for (int mt = 0; mt < 4; mt++) {
            #pragma unroll
            for (int n2 = 0; n2 < 2; n2++) {
                mma16816(acc[mt][n2 * 2],     ah[mt], bh[n2][0], bh[n2][1]);
                mma16816(acc[mt][n2 * 2],     al[mt], bh[n2][0], bh[n2][1]);
                mma16816(acc[mt][n2 * 2],     ah[mt], bl[n2][0], bl[n2][1]);
                if (FOURTH)
                    mma16816(acc[mt][n2 * 2], al[mt], bl[n2][0], bl[n2][1]);
                mma16816(acc[mt][n2 * 2 + 1], ah[mt], bh[n2][2], bh[n2][3]);
                mma16816(acc[mt][n2 * 2 + 1], al[mt], bh[n2][2], bh[n2][3]);
                mma16816(acc[mt][n2 * 2 + 1], ah[mt], bl[n2][2], bl[n2][3]);
                if (FOURTH)
                    mma16816(acc[mt][n2 * 2 + 1], al[mt], bl[n2][2], bl[n2][3]);
            }
        }
    }
}

__device__ __forceinline__ void tile_geometry(int lane, int wid,
                                              unsigned* aoffA, unsigned* aoffB,
                                              unsigned& kbA, unsigned& kbB,
                                              unsigned& xm)
{
    const int warp_m = (wid >> 2) * 64;
    const int warp_n = (wid & 3) * 32;
    xm  = (unsigned)((lane & 7) << 4);
    const int rowA = (lane & 7) + ((lane >> 3) & 1) * 8;
    kbA = (unsigned)((lane >> 4) * 16);
    const int rowB = (lane & 7) + ((lane >> 4) << 3);
    kbB = (unsigned)(((lane >> 3) & 1) * 16);
    #pragma unroll
    for (int mt = 0; mt < 4; mt++)
        aoffA[mt] = (unsigned)((warp_m + mt * 16 + rowA) * 128);
    #pragma unroll
    for (int nt = 0; nt < 2; nt++)
        aoffB[nt] = (unsigned)((warp_n + nt * 16 + rowB) * 128);
}

// ---------------- fused persistent kernel: recurrence + logits workers ---------
__global__ __launch_bounds__(288, 1) void fused_kernel(
    const float* __restrict__ wh0, const float* __restrict__ wx1,
    const float* __restrict__ wh1, const float* __restrict__ bh1,
    const float* __restrict__ vb, float* __restrict__ out)
{
    extern __shared__ char sm[];
    __shared__ ull s_full[4], s_empty[4];   // recur rings
    __shared__ ull s_lf[2], s_le[2];        // logits rings
    __shared__ int s_tile;
    const int tid = threadIdx.x;
    const int lane = tid & 31, wid = tid >> 5;
    const int bid = blockIdx.x;
    const unsigned sb = smem_u32(sm);
    const unsigned mbf = smem_u32(&s_full[0]);
    const unsigned mbe = smem_u32(&s_empty[0]);
    const unsigned mlf = smem_u32(&s_lf[0]);
    const unsigned mle = smem_u32(&s_le[0]);

    if (tid == 0) {
        #pragma unroll
        for (int s = 0; s < 4; s++) {
            MBAR_INIT(mbf + s * 8, 1);
            MBAR_INIT(mbe + s * 8, 8);
        }
        #pragma unroll
        for (int s = 0; s < 2; s++) {
            MBAR_INIT(mlf + s * 8, 1);
            MBAR_INIT(mle + s * 8, 8);
        }
    }
    __syncthreads();

    // ================= recurrence phase (blocks 0..95) =================
    if (bid < NBLK) {
        const bool is_l1 = (bid >= NB_L0);
        if (!is_l1) {
            int nb = bid * 32;
            for (int idx = tid; idx < 32 * 1024; idx += 288) {
                int n = idx >> 10, kk = idx & 1023;
                float w = wh0[(size_t)(nb + n) * HID + kk];
                __nv_bfloat16 h, l; split_bf16(w, h, l);
                int c = kk >> 6;
                unsigned off = SWZ((unsigned)(n * 128 + (kk & 63) * 2));
                *(__nv_bfloat16*)(sm + c * 4096 + off) = h;
                *(__nv_bfloat16*)(sm + 65536 + c * 4096 + off) = l;
            }
        } else {
            int nb = (bid - NB_L0) * 16;
            for (int idx = tid; idx < 2 * 16 * 1024; idx += 288) {
                int mat = idx >> 14;
                int rr = idx & 16383;
                int n = rr >> 10, kk = rr & 1023;
                const float* W = mat ? wh1 : wx1;
                float w = W[(size_t)(nb + n) * HID + kk];
                __nv_bfloat16 h, l; split_bf16(w, h, l);
                int c = kk >> 6;
                unsigned off = SWZ((unsigned)(n * 128 + (kk & 63) * 2));
                char* base = sm + mat * 65536;
                *(__nv_bfloat16*)(base + c * 2048 + off) = h;
                *(__nv_bfloat16*)(base + 32768 + c * 2048 + off) = l;
            }
        }
        __syncthreads();

        int u = 0;
        for (int k = 0; k <= SEQ; k++) {
            bool active = is_l1 ? (k >= 1) : (k < SEQ);
            if (active) {
                if (!is_l1) step_l0(sb, mbf, mbe, bid, k, u, tid, lane, wid);
                else        step_l1(sm, sb, mbf, mbe, bid, k, u, tid, lane, wid, bh1);
                u += 16;
            }
            if (k < SEQ) {
                __syncthreads();
                if (tid == 0) {
                    asm volatile("red.release.gpu.global.add.u32 [%0], %1;"
                                 :: "l"(&g_bar), "r"(1u) : "memory");
                    unsigned target = (unsigned)(k + 1) * NBLK;
                    unsigned v;
                    do {
                        asm volatile("ld.global.acquire.gpu.b32 %0, [%1];"
                                     : "=r"(v) : "l"(&g_bar) : "memory");
                    } while (v < target);
                }
                __syncthreads();
            }
        }
        // final release: publishes h1[SEQ]; raises g_bar to 129*NBLK
        __syncthreads();
        if (tid == 0) {
            asm volatile("red.release.gpu.global.add.u32 [%0], %1;"
                         :: "l"(&g_bar), "r"(1u) : "memory");
        }
    }

    // ================= logits tile phase (all blocks) =================
    // stages at sm+0 (2 x STAGE_BYTES); weights region reused by ex-recur blocks
    const char* ahb = (const char*)g_h1h;
    const char* alb = (const char*)g_h1l;
    int lu = 0;

    while (true) {
        __syncthreads();
        if (tid == 0) {
            unsigned t = atomicAdd(&g_tileq, 1u);
            s_tile = (int)t;
            if (t < NTILES) {
                unsigned need = (unsigned)((t / NT_N) * 2 + 3) * NBLK;
                unsigned v;
                do {
                    asm volatile("ld.global.acquire.gpu.b32 %0, [%1];"
                                 : "=r"(v) : "l"(&g_bar) : "memory");
                } while (v < need);
            }
        }
        __syncthreads();
        int t = s_tile;
        if (t >= NTILES) break;
        int mt = t / NT_N, nt = t - mt * NT_N;
        int mbase = mt * 128, nbase = nt * 128;
        int s0 = mt * 2 + 1;
        const char* bhb = (const char*)g_Bh + (size_t)nt * T_TILE_BYTES;
        const char* blb = (const char*)g_Bl + (size_t)nt * T_TILE_BYTES;

        if (tid == 256) {
            #pragma unroll 1
            for (int c = 0; c < NKT; c++) {
                int uu = lu + c, s = uu & 1, q = uu >> 1;
                if (uu >= 2) MBARRIER_WAIT_PARITY(mle + s * 8, (q - 1) & 1);
                unsigned dst = sb + (unsigned)(s * STAGE_BYTES);
                MBAR_EXPECT_TX(mlf + s * 8, 65536u);
                bulk_g2s(dst,                   ahb + (size_t)s0 * H_SLOT_BYTES + c * H_CHUNK_BYTES, 8192, mlf + s * 8);
                bulk_g2s(dst + 8192,            ahb + (size_t)(s0 + 1) * H_SLOT_BYTES + c * H_CHUNK_BYTES, 8192, mlf + s * 8);
                bulk_g2s(dst + OP_BYTES,        alb + (size_t)s0 * H_SLOT_BYTES + c * H_CHUNK_BYTES, 8192, mlf + s * 8);
                bulk_g2s(dst + OP_BYTES + 8192, alb + (size_t)(s0 + 1) * H_SLOT_BYTES + c * H_CHUNK_BYTES, 8192, mlf + s * 8);
                bulk_g2s(dst + 2 * OP_BYTES,    bhb + c * T_CHUNK_BYTES, 16384, mlf + s * 8);
                bulk_g2s(dst + 3 * OP_BYTES,    blb + c * T_CHUNK_BYTES, 16384, mlf + s * 8);
            }
        } else if (wid < 8) {
            unsigned aoffA[4], aoffB[2], kbA, kbB, xm;
            tile_geometry(lane, wid, aoffA, aoffB, kbA, kbB, xm);
            float acc[4][4][4] = {};

            #pragma unroll 1
            for (int c = 0; c < NKT; c++) {
                int uu = lu + c, s = uu & 1, q = uu >> 1;
                MBARRIER_WAIT_PARITY(mlf + s * 8, q & 1);
                unsigned st = sb + (unsigned)(s * STAGE_BYTES);
                compute_chunk128<false>(st, aoffA, aoffB, kbA, kbB, xm, acc);
                if (lane == 0) MBAR_ARRIVE(mle + s * 8);
            }

            // direct-store epilogue (32B sector-aligned float2 stores)
            const int warp_m = (wid >> 2) * 64;
            const int warp_n = (wid & 3) * 32;
            const int r0l = lane >> 2;
            const int c0l = 2 * (lane & 3);
            #pragma unroll
            for (int nt4 = 0; nt4 < 4; nt4++) {
                int col = nbase + warp_n + nt4 * 8 + c0l;
                if (col >= VOCAB) continue;
                float bv0 = vb[col], bv1 = vb[col + 1];
                #pragma unroll
                for (int mt4 = 0; mt4 < 4; mt4++) {
                    int row = mbase + warp_m + mt4 * 16 + r0l;
                    float* o0 = out + (size_t)row * VOCAB + col;
                    float* o1 = out + (size_t)(row + 8) * VOCAB + col;
                    *(float2*)o0 = make_float2(acc[mt4][nt4][0] + bv0,
                                               acc[mt4][nt4][1] + bv1);
                    *(float2*)o1 = make_float2(acc[mt4][nt4][2] + bv0,
                                               acc[mt4][nt4][3] + bv1);
                }
            }
        }
        lu += 16;
    }
}

// ---------------- xproj kernel (288 threads, producer warp 8) -------------------
__global__ __launch_bounds__(288, 1) void xproj_mma_kernel(
    const float* __restrict__ bh0)
{
    extern __shared__ char dsm[];
    __shared__ ull s_full[2], s_empty[2];
    const int tid  = threadIdx.x;
    const int lane = tid & 31, wid = tid >> 5;
    const int mbase = blockIdx.y * 128;
    const int nbase = blockIdx.x * 128;
    const unsigned sb = (smem_u32(dsm) + 1023u) & ~1023u;
    const unsigned mbf = smem_u32(&s_full[0]);
    const unsigned mbe = smem_u32(&s_empty[0]);

    if (tid == 0) {
        MBAR_INIT(mbf, 1);     MBAR_INIT(mbf + 8, 1);
        MBAR_INIT(mbe, 8);     MBAR_INIT(mbe + 8, 8);
    }
    __syncthreads();

    const char* ahb = (const char*)g_Xh + (size_t)(mbase >> 7) * T_TILE_BYTES;
    const char* alb = (const char*)g_Xl + (size_t)(mbase >> 7) * T_TILE_BYTES;
    const char* bhb = (const char*)g_Wh + (size_t)(nbase >> 7) * T_TILE_BYTES;
    const char* blb = (const char*)g_Wl + (size_t)(nbase >> 7) * T_TILE_BYTES;

    if (tid == 256) {
        #pragma unroll 1
        for (int c = 0; c < NKT; c++) {
            int s = c & 1, q = c >> 1;
            if (q > 0) MBARRIER_WAIT_PARITY(mbe + s * 8, (q - 1) & 1);
            unsigned dst = sb + (unsigned)(s * STAGE_BYTES);
            MBAR_EXPECT_TX(mbf + s * 8, 65536u);
            bulk_g2s(dst,                ahb + c * T_CHUNK_BYTES, 16384, mbf + s * 8);
            bulk_g2s(dst + OP_BYTES,     alb + c * T_CHUNK_BYTES, 16384, mbf + s * 8);
            bulk_g2s(dst + 2 * OP_BYTES, bhb + c * T_CHUNK_BYTES, 16384, mbf + s * 8);
            bulk_g2s(dst + 3 * OP_BYTES, blb + c * T_CHUNK_BYTES, 16384, mbf + s * 8);
        }
    } else if (wid < 8) {
        unsigned aoffA[4], aoffB[2], kbA, kbB, xm;
        tile_geometry(lane, wid, aoffA, aoffB, kbA, kbB, xm);
        float acc[4][4][4] = {};

        #pragma unroll 1
        for (int c = 0; c < NKT; c++) {
            int s = c & 1, q = c >> 1;
            MBARRIER_WAIT_PARITY(mbf + s * 8, q & 1);
            unsigned st = sb + (unsigned)(s * STAGE_BYTES);
            compute_chunk128<true>(st, aoffA, aoffB, kbA, kbB, xm, acc);
            if (lane == 0) MBAR_ARRIVE(mbe + s * 8);
        }

        // direct-store epilogue into g_xproj0
        const int warp_m = (wid >> 2) * 64;
        const int warp_n = (wid & 3) * 32;
        const int r0l = lane >> 2;
        const int c0l = 2 * (lane & 3);
        #pragma unroll
        for (int nt4 = 0; nt4 < 4; nt4++) {
            int col = nbase + warp_n + nt4 * 8 + c0l;
            float2 bv = *(const float2*)(bh0 + col);
            #pragma unroll
            for (int mt4 = 0; mt4 < 4; mt4++) {
                int row = mbase + warp_m + mt4 * 16 + r0l;
                float* o0 = g_xproj0 + (size_t)row * HID + col;
                float* o1 = g_xproj0 + (size_t)(row + 8) * HID + col;
                *(float2*)o0 = make_float2(acc[mt4][nt4][0] + bv.x,
                                           acc[mt4][nt4][1] + bv.y);
                *(float2*)o1 = make_float2(acc[mt4][nt4][2] + bv.x,
                                           acc[mt4][nt4][3] + bv.y);
            }
        }
    }
}

// ---------------- finalize: hidden_final = hi + lo at slot SEQ ------------------
__global__ void finalize_kernel(float* __restrict__ out) {
    int i = blockIdx.x * blockDim.x + threadIdx.x;
    if (i < 2 * BH) {
        int l = i >> 16;                 // BH = 65536
        int r = i & (BH - 1);
        int b = r >> 10, n = r & 1023;
        unsigned off = hoff_bytes(SEQ, b, n);
        const char* hs = l ? (const char*)g_h1h : (const char*)g_h0h;
        const char* ls = l ? (const char*)g_h1l : (const char*)g_h0l;
        out[(size_t)ROWS * VOCAB + i] =
            __bfloat162float(*(const __nv_bfloat16*)(hs + off)) +
            __bfloat162float(*(const __nv_bfloat16*)(ls + off));
    }
}

// ---------------- launcher --------------------------------------------------------
extern "C" void kernel_launch(void* const* d_in, const int* in_sizes, int n_in,
                              void* d_out, int out_size)
{
    const int*   inputs    = (const int*)  d_in[0];
    const float* hidden    = (const float*)d_in[1];
    const float* embedding = (const float*)d_in[2];
    const float* wx0       = (const float*)d_in[3];
    const float* wh0       = (const float*)d_in[4];
    const float* bh0       = (const float*)d_in[5];
    const float* wx1       = (const float*)d_in[6];
    const float* wh1       = (const float*)d_in[7];
    const float* bh1       = (const float*)d_in[8];
    const float* v_w       = (const float*)d_in[9];
    const float* v_b       = (const float*)d_in[10];
    float* out = (float*)d_out;

    static bool attr_set = false;
    if (!attr_set) {
        cudaFuncSetAttribute(fused_kernel,
                             cudaFuncAttributeMaxDynamicSharedMemorySize,
                             RECUR_SMEM);
        cudaFuncSetAttribute(xproj_mma_kernel,
                             cudaFuncAttributeMaxDynamicSharedMemorySize,
                             GEMM_SMEM);
        attr_set = true;
    }

    __nv_bfloat16 *dBh, *dBl, *dWh, *dWl, *dXh, *dXl;
    cudaGetSymbolAddress((void**)&dBh, g_Bh);
    cudaGetSymbolAddress((void**)&dBl, g_Bl);
    cudaGetSymbolAddress((void**)&dWh, g_Wh);
    cudaGetSymbolAddress((void**)&dWl, g_Wl);
    cudaGetSymbolAddress((void**)&dXh, g_Xh);
    cudaGetSymbolAddress((void**)&dXl, g_Xl);

    init_kernel<<<(BH + 255) / 256, 256>>>(hidden);
    conv_tiles_kernel<<<(VOCAB * HID / 4 + 255) / 256, 256>>>(
        v_w, 0, dBh, dBl, VOCAB * HID / 4);
    conv_tiles_kernel<<<(HID * HID / 4 + 255) / 256, 256>>>(
        wx0, 0, dWh, dWl, HID * HID / 4);
    conv_tiles_kernel<<<(ROWS * HID / 4 + 255) / 256, 256>>>(
        embedding, inputs, dXh, dXl, ROWS * HID / 4);
    xproj_mma_kernel<<<dim3(HID / 128, ROWS / 128), 288, GEMM_SMEM>>>(bh0);
    fused_kernel<<<NGRID, 288, RECUR_SMEM>>>(wh0, wx1, wh1, bh1, v_b, out);

    long long need = (long long)ROWS * VOCAB + 2LL * BH;
    if ((long long)out_size >= need) {
        finalize_kernel<<<(2 * BH + 255) / 256, 256>>>(out);
    }
}